// round 4
// baseline (speedup 1.0000x reference)
#include <cuda_runtime.h>
#include <math.h>

#define BB 4
#define HH 8
#define TT 2048
#define DD 64
#define EE 512
#define TOPKK 96
#define QT 64
#define KROWS 192
#define KPAD 68
#define PPAD 132

typedef unsigned long long ull;

// Scratch (device globals; no allocation allowed)
__device__ float g_q[(size_t)BB * HH * TT * DD];
__device__ float g_k[(size_t)BB * HH * TT * DD];
__device__ float g_v[(size_t)BB * HH * TT * DD];
__device__ float g_attn[(size_t)BB * TT * EE];

__device__ __forceinline__ ull fma2(ull a, ull b, ull c) {
    ull d;
    asm("fma.rn.f32x2 %0, %1, %2, %3;" : "=l"(d) : "l"(a), "l"(b), "l"(c));
    return d;
}
__device__ __forceinline__ ull pack2(float x) {
    ull d;
    asm("mov.b64 %0, {%1, %1};" : "=l"(d) : "f"(x));
    return d;
}
__device__ __forceinline__ float sum2(ull v) {
    float lo, hi;
    asm("mov.b64 {%0, %1}, %2;" : "=f"(lo), "=f"(hi) : "l"(v));
    return lo + hi;
}
__device__ __forceinline__ unsigned f2ord(float f) {
    unsigned u = __float_as_uint(f);
    return (u & 0x80000000u) ? ~u : (u | 0x80000000u);
}

// ---------------------------------------------------------------------------
// GEMM: Y = X @ W^T + bias.  X:[M,512], W:[512,512] both row-major.
// 128x64 tile, 256 threads, 8x4 per-thread microtile, BK=16, double-buffered,
// K-pair-packed FFMA2 accumulation (both operands packed along K -> no packs).
// NOUT=3: fused QKV, head-split output layout. NOUT=1: plain row-major out.
// ---------------------------------------------------------------------------
#define BM 128
#define BN 64
#define BK 16
#define BROW 132  // Bs row stride in floats (64 cols * 2 + 4 pad)

template <int NOUT>
__global__ __launch_bounds__(256) void gemmk(
    const float* __restrict__ X,
    const float* __restrict__ W0, const float* __restrict__ bias0, float* __restrict__ Y0,
    const float* __restrict__ W1, const float* __restrict__ bias1, float* __restrict__ Y1,
    const float* __restrict__ W2, const float* __restrict__ bias2, float* __restrict__ Y2) {
    __shared__ float As[2][BM][BK];
    __shared__ float Bs[2][BK / 2][BROW];

    const float* W;
    const float* bias;
    float* Y;
    if (NOUT == 3) {
        int z = blockIdx.z;
        W = (z == 0) ? W0 : (z == 1) ? W1 : W2;
        bias = (z == 0) ? bias0 : (z == 1) ? bias1 : bias2;
        Y = (z == 0) ? Y0 : (z == 1) ? Y1 : Y2;
    } else {
        W = W0; bias = bias0; Y = Y0;
    }

    const int m0 = blockIdx.x * BM;
    const int n0 = blockIdx.y * BN;
    const int tid = threadIdx.x;
    const int tc = tid & 15;   // col group 0..15 -> cols tc*4..+3
    const int tr = tid >> 4;   // row group 0..15 -> rows tr*8..+7

    // global load mapping
    const int ar = tid >> 1, ak = (tid & 1) * 8;
    const int bc = tid >> 2, bk = (tid & 3) * 4;
    const float* Ag = X + (size_t)(m0 + ar) * EE + ak;
    const float* Bg = W + (size_t)(n0 + bc) * EE + bk;
    const int bkp = bk >> 1;

    float4 pa0 = *(const float4*)(Ag);
    float4 pa1 = *(const float4*)(Ag + 4);
    float4 pb = *(const float4*)(Bg);

    // store tile 0
    *(float4*)&As[0][ar][ak] = pa0;
    *(float4*)&As[0][ar][ak + 4] = pa1;
    *(float2*)&Bs[0][bkp][bc * 2] = make_float2(pb.x, pb.y);
    *(float2*)&Bs[0][bkp + 1][bc * 2] = make_float2(pb.z, pb.w);
    __syncthreads();

    ull c2[8][4];
#pragma unroll
    for (int i = 0; i < 8; i++)
#pragma unroll
        for (int j = 0; j < 4; j++) c2[i][j] = 0ull;

    int buf = 0;
    for (int k0 = BK; k0 <= EE; k0 += BK) {
        if (k0 < EE) {
            pa0 = *(const float4*)(Ag + k0);
            pa1 = *(const float4*)(Ag + k0 + 4);
            pb = *(const float4*)(Bg + k0);
        }
#pragma unroll
        for (int kc = 0; kc < 4; kc++) {
            ull a0[8], a1[8];
#pragma unroll
            for (int i = 0; i < 8; i++) {
                ulonglong2 av = *(const ulonglong2*)&As[buf][tr * 8 + i][kc * 4];
                a0[i] = av.x;
                a1[i] = av.y;
            }
            {
                ulonglong2 bv0 = *(const ulonglong2*)&Bs[buf][2 * kc][tc * 8];
                ulonglong2 bv1 = *(const ulonglong2*)&Bs[buf][2 * kc][tc * 8 + 4];
                ull b0 = bv0.x, b1 = bv0.y, b2 = bv1.x, b3 = bv1.y;
#pragma unroll
                for (int i = 0; i < 8; i++) {
                    c2[i][0] = fma2(a0[i], b0, c2[i][0]);
                    c2[i][1] = fma2(a0[i], b1, c2[i][1]);
                    c2[i][2] = fma2(a0[i], b2, c2[i][2]);
                    c2[i][3] = fma2(a0[i], b3, c2[i][3]);
                }
            }
            {
                ulonglong2 bv0 = *(const ulonglong2*)&Bs[buf][2 * kc + 1][tc * 8];
                ulonglong2 bv1 = *(const ulonglong2*)&Bs[buf][2 * kc + 1][tc * 8 + 4];
                ull b0 = bv0.x, b1 = bv0.y, b2 = bv1.x, b3 = bv1.y;
#pragma unroll
                for (int i = 0; i < 8; i++) {
                    c2[i][0] = fma2(a1[i], b0, c2[i][0]);
                    c2[i][1] = fma2(a1[i], b1, c2[i][1]);
                    c2[i][2] = fma2(a1[i], b2, c2[i][2]);
                    c2[i][3] = fma2(a1[i], b3, c2[i][3]);
                }
            }
        }
        if (k0 < EE) {
            int nb = buf ^ 1;
            *(float4*)&As[nb][ar][ak] = pa0;
            *(float4*)&As[nb][ar][ak + 4] = pa1;
            *(float2*)&Bs[nb][bkp][bc * 2] = make_float2(pb.x, pb.y);
            *(float2*)&Bs[nb][bkp + 1][bc * 2] = make_float2(pb.z, pb.w);
            __syncthreads();
        }
        buf ^= 1;
    }

    float4 bbv = *(const float4*)&bias[n0 + tc * 4];
#pragma unroll
    for (int i = 0; i < 8; i++) {
        float4 r;
        r.x = sum2(c2[i][0]) + bbv.x;
        r.y = sum2(c2[i][1]) + bbv.y;
        r.z = sum2(c2[i][2]) + bbv.z;
        r.w = sum2(c2[i][3]) + bbv.w;
        int m = m0 + tr * 8 + i;
        if (NOUT == 3) {
            int bi = m >> 11;         // m / 2048
            int t = m & 2047;
            int h = n0 >> 6;
            *(float4*)&Y[(((size_t)bi * HH + h) * TT + t) * DD + tc * 4] = r;
        } else {
            *(float4*)&Y[(size_t)m * EE + n0 + tc * 4] = r;
        }
    }
}

// ---------------------------------------------------------------------------
// Attention: block per (q-tile of 64, h, b). 512 threads = 16 warps.
// Dot-product scores with precomputed norms, radix-4 exact top-96 threshold,
// softmax, FFMA2 PV.
// ---------------------------------------------------------------------------
__global__ __launch_bounds__(512) void attn_kernel(const float* __restrict__ log_sigma) {
    extern __shared__ float sm[];
    float* sQ = sm;                          // 64  x 68
    float* sK = sQ + 64 * KPAD;              // 192 x 68
    float* sV = sK + KROWS * KPAD;           // 192 x 68
    float* sP = sV + KROWS * KPAD;           // 64  x 132
    float* sKsq = sP + 64 * PPAD;            // 192
    float* sQsq = sKsq + KROWS;              // 64

    const int q0 = blockIdx.x * QT;
    const int h = blockIdx.y;
    const int b = blockIdx.z;
    const int tid = threadIdx.x;

    const float* Qg = g_q + ((size_t)(b * HH + h) * TT) * DD;
    const float* Kg = g_k + ((size_t)(b * HH + h) * TT) * DD;
    const float* Vg = g_v + ((size_t)(b * HH + h) * TT) * DD;
    const float scale = -0.5f * expf(-2.f * log_sigma[h]);

    // ---- load tiles ----
    for (int i = tid; i < 64 * 16; i += 512) {
        int r = i >> 4, c = i & 15;
        *(float4*)&sQ[r * KPAD + c * 4] =
            *(const float4*)&Qg[(size_t)(q0 + r) * DD + c * 4];
    }
    const float4 z4 = make_float4(0.f, 0.f, 0.f, 0.f);
    for (int i = tid; i < KROWS * 16; i += 512) {
        int r = i >> 4, c = i & 15;
        int gk = q0 - 128 + r;
        float4 kv = z4, vv = z4;
        if (gk >= 0) {
            kv = *(const float4*)&Kg[(size_t)gk * DD + c * 4];
            vv = *(const float4*)&Vg[(size_t)gk * DD + c * 4];
        }
        *(float4*)&sK[r * KPAD + c * 4] = kv;
        *(float4*)&sV[r * KPAD + c * 4] = vv;
    }
    __syncthreads();

    // ---- row norms ----
    if (tid < KROWS + 64) {
        const float* row = (tid < KROWS) ? &sK[tid * KPAD] : &sQ[(tid - KROWS) * KPAD];
        ull acc = 0ull;
#pragma unroll
        for (int c = 0; c < 16; c++) {
            ulonglong2 v = *(const ulonglong2*)&row[c * 4];
            acc = fma2(v.x, v.x, acc);
            acc = fma2(v.y, v.y, acc);
        }
        float s = sum2(acc);
        if (tid < KROWS) sKsq[tid] = s;
        else sQsq[tid - KROWS] = s;
    }
    __syncthreads();

    // ---- scores + top-k + softmax (warp per 4 queries; lane owns 4 keys) ----
    const int w = tid >> 5, l = tid & 31;
    const float NEGINF = __int_as_float(0xff800000);

    for (int qq = 0; qq < 4; qq++) {
        const int qi = w * 4 + qq;
        const int gq = q0 + qi;
        ull acc2[4] = {0ull, 0ull, 0ull, 0ull};
        const float* qrow = &sQ[qi * KPAD];
        const float* kbase = &sK[(qi + 1 + l) * KPAD];
#pragma unroll 8
        for (int c = 0; c < 16; c++) {
            ulonglong2 qv = *(const ulonglong2*)&qrow[c * 4];
#pragma unroll
            for (int t = 0; t < 4; t++) {
                ulonglong2 kv = *(const ulonglong2*)&kbase[32 * t * KPAD + c * 4];
                acc2[t] = fma2(qv.x, kv.x, acc2[t]);
                acc2[t] = fma2(qv.y, kv.y, acc2[t]);
            }
        }
        float s[4];
        unsigned key[4];
        bool valid[4];
        float qs = sQsq[qi];
#pragma unroll
        for (int t = 0; t < 4; t++) {
            int j = l + 32 * t;
            float dot = sum2(acc2[t]);
            float dist = qs + sKsq[qi + 1 + j] - 2.f * dot;
            s[t] = dist * scale;
            valid[t] = (gq - 127 + j) >= 0;
            key[t] = valid[t] ? f2ord(s[t]) : 0u;
        }

        unsigned thr = 0u;
        if (gq >= TOPKK) {  // >96 valid keys -> top-k filter active
#pragma unroll 1
            for (int bp = 30; bp >= 0; bp -= 2) {
                unsigned c1 = thr | (1u << bp);
                unsigned cc2 = thr | (2u << bp);
                unsigned c3 = thr | (3u << bp);
                unsigned pk = 0;
#pragma unroll
                for (int t = 0; t < 4; t++) {
                    pk += (key[t] >= c1 ? 1u : 0u);
                    pk += (key[t] >= cc2 ? 0x100u : 0u);
                    pk += (key[t] >= c3 ? 0x10000u : 0u);
                }
                pk = __reduce_add_sync(0xffffffffu, pk);
                if ((pk >> 16) >= TOPKK) thr = c3;
                else if (((pk >> 8) & 0xffu) >= TOPKK) thr = cc2;
                else if ((pk & 0xffu) >= TOPKK) thr = c1;
            }
        }

        bool kept[4];
        float mv = NEGINF;
#pragma unroll
        for (int t = 0; t < 4; t++) {
            kept[t] = valid[t] && (key[t] >= thr);
            if (kept[t]) mv = fmaxf(mv, s[t]);
        }
#pragma unroll
        for (int o = 16; o > 0; o >>= 1)
            mv = fmaxf(mv, __shfl_xor_sync(0xffffffffu, mv, o));

        float e[4];
        float esum = 0.f;
#pragma unroll
        for (int t = 0; t < 4; t++) {
            e[t] = kept[t] ? __expf(s[t] - mv) : 0.f;
            esum += e[t];
        }
#pragma unroll
        for (int o = 16; o > 0; o >>= 1)
            esum += __shfl_xor_sync(0xffffffffu, esum, o);
        float inv = 1.f / esum;
#pragma unroll
        for (int t = 0; t < 4; t++) sP[qi * PPAD + l + 32 * t] = e[t] * inv;
    }
    __syncthreads();

    // ---- PV: thread (qi = tid&63, dg = tid>>6) covers dims dg*8..dg*8+7 ----
    {
        const int qi = tid & 63;
        const int dg = tid >> 6;
        ull o2[4] = {0ull, 0ull, 0ull, 0ull};
        const float* prow = &sP[qi * PPAD];
        const float* vbase = &sV[(qi + 1) * KPAD + dg * 8];
#pragma unroll 4
        for (int j = 0; j < 128; j++) {
            ull p2 = pack2(prow[j]);
            const float* vr = vbase + j * KPAD;
            ulonglong2 v0 = *(const ulonglong2*)vr;
            ulonglong2 v1 = *(const ulonglong2*)(vr + 4);
            o2[0] = fma2(p2, v0.x, o2[0]);
            o2[1] = fma2(p2, v0.y, o2[1]);
            o2[2] = fma2(p2, v1.x, o2[2]);
            o2[3] = fma2(p2, v1.y, o2[3]);
        }
        size_t obase = ((size_t)b * TT + q0 + qi) * EE + h * DD + dg * 8;
        ulonglong2 w0, w1;
        w0.x = o2[0]; w0.y = o2[1];
        w1.x = o2[2]; w1.y = o2[3];
        *(ulonglong2*)&g_attn[obase] = w0;
        *(ulonglong2*)&g_attn[obase + 4] = w1;
    }
}

// ---------------------------------------------------------------------------
extern "C" void kernel_launch(void* const* d_in, const int* in_sizes, int n_in,
                              void* d_out, int out_size) {
    const float* x  = (const float*)d_in[0];
    const float* Wq = (const float*)d_in[1];
    const float* bq = (const float*)d_in[2];
    const float* Wk = (const float*)d_in[3];
    const float* bk = (const float*)d_in[4];
    const float* Wv = (const float*)d_in[5];
    const float* bv = (const float*)d_in[6];
    const float* Wo = (const float*)d_in[7];
    const float* bo = (const float*)d_in[8];
    const float* ls = (const float*)d_in[9];

    float *qp, *kp, *vp, *ap;
    cudaGetSymbolAddress((void**)&qp, g_q);
    cudaGetSymbolAddress((void**)&kp, g_k);
    cudaGetSymbolAddress((void**)&vp, g_v);
    cudaGetSymbolAddress((void**)&ap, g_attn);

    dim3 gqkv(BB * TT / BM, EE / BN, 3);  // 64 x 8 x 3
    gemmk<3><<<gqkv, 256>>>(x, Wq, bq, qp, Wk, bk, kp, Wv, bv, vp);

    const size_t smem =
        (size_t)(64 * KPAD + 2 * KROWS * KPAD + 64 * PPAD + KROWS + 64) * sizeof(float);
    cudaFuncSetAttribute(attn_kernel, cudaFuncAttributeMaxDynamicSharedMemorySize,
                         (int)smem);
    attn_kernel<<<dim3(TT / QT, HH, BB), 512, smem>>>(ls);

    dim3 go(BB * TT / BM, EE / BN);  // 64 x 8
    gemmk<1><<<go, 256>>>(ap, Wo, bo, (float*)d_out,
                          nullptr, nullptr, nullptr, nullptr, nullptr, nullptr);
}

// round 5
// speedup vs baseline: 1.2070x; 1.2070x over previous
#include <cuda_runtime.h>
#include <math.h>

#define BB 4
#define HH 8
#define TT 2048
#define DD 64
#define EE 512
#define TOPKK 96
#define QT 64
#define KROWS 192
#define PPAD 132

typedef unsigned long long ull;

// Scratch (device globals; no allocation allowed)
__device__ float g_q[(size_t)BB * HH * TT * DD];
__device__ float g_k[(size_t)BB * HH * TT * DD];
__device__ float g_v[(size_t)BB * HH * TT * DD];
__device__ float g_attn[(size_t)BB * TT * EE];

__device__ __forceinline__ ull fma2(ull a, ull b, ull c) {
    ull d;
    asm("fma.rn.f32x2 %0, %1, %2, %3;" : "=l"(d) : "l"(a), "l"(b), "l"(c));
    return d;
}
__device__ __forceinline__ ull pack2(float x) {
    ull d;
    asm("mov.b64 %0, {%1, %1};" : "=l"(d) : "f"(x));
    return d;
}
__device__ __forceinline__ float sum2(ull v) {
    float lo, hi;
    asm("mov.b64 {%0, %1}, %2;" : "=f"(lo), "=f"(hi) : "l"(v));
    return lo + hi;
}
__device__ __forceinline__ unsigned f2ord(float f) {
    unsigned u = __float_as_uint(f);
    return (u & 0x80000000u) ? ~u : (u | 0x80000000u);
}

// ---------------------------------------------------------------------------
// GEMM: Y = X @ W^T + bias.  X:[M,512], W:[512,512] row-major.
// 64x64 tile, BK=32, 256 threads, 4x4 microtile, k-pair-packed FFMA2.
// Smem tiles stored [row][32] with XOR chunk swizzle  pos = c ^ ((r>>2)&7)
// so B compute loads (lanes at 4-row stride) hit 8 distinct bank-groups
// per LDS.128 phase -> conflict-free. A compute loads are broadcast.
// ---------------------------------------------------------------------------
#define GBK 32

__device__ __forceinline__ int gswz(int r, int c) {  // float offset in tile
    return r * GBK + ((c ^ ((r >> 2) & 7)) << 2);
}

template <int NOUT>
__global__ __launch_bounds__(256) void gemmk(
    const float* __restrict__ X,
    const float* __restrict__ W0, const float* __restrict__ bias0, float* __restrict__ Y0,
    const float* __restrict__ W1, const float* __restrict__ bias1, float* __restrict__ Y1,
    const float* __restrict__ W2, const float* __restrict__ bias2, float* __restrict__ Y2) {
    __shared__ float As[2][64 * GBK];
    __shared__ float Bs[2][64 * GBK];

    const float* W;
    const float* bias;
    float* Y;
    if (NOUT == 3) {
        int z = blockIdx.z;
        W = (z == 0) ? W0 : (z == 1) ? W1 : W2;
        bias = (z == 0) ? bias0 : (z == 1) ? bias1 : bias2;
        Y = (z == 0) ? Y0 : (z == 1) ? Y1 : Y2;
    } else {
        W = W0; bias = bias0; Y = Y0;
    }

    const int m0 = blockIdx.x * 64;
    const int n0 = blockIdx.y * 64;
    const int tid = threadIdx.x;
    const int tn = tid & 15;
    const int tm = tid >> 4;

    // global load mapping: thread owns row lr, k-offset lc (8 floats)
    const int lr = tid >> 2;
    const int lc = (tid & 3) * 8;
    const float* Ag = X + (size_t)(m0 + lr) * EE + lc;
    const float* Bg = W + (size_t)(n0 + lr) * EE + lc;
    const int s0 = gswz(lr, lc >> 2);
    const int s1 = gswz(lr, (lc >> 2) + 1);

    float4 pa0 = *(const float4*)(Ag);
    float4 pa1 = *(const float4*)(Ag + 4);
    float4 pb0 = *(const float4*)(Bg);
    float4 pb1 = *(const float4*)(Bg + 4);

    *(float4*)&As[0][s0] = pa0;
    *(float4*)&As[0][s1] = pa1;
    *(float4*)&Bs[0][s0] = pb0;
    *(float4*)&Bs[0][s1] = pb1;
    __syncthreads();

    ull c2[4][4];
#pragma unroll
    for (int i = 0; i < 4; i++)
#pragma unroll
        for (int j = 0; j < 4; j++) c2[i][j] = 0ull;

    const int akey = tm & 7;
    const int bkey = tn & 7;
    int buf = 0;
    for (int k0 = GBK; k0 <= EE; k0 += GBK) {
        if (k0 < EE) {
            pa0 = *(const float4*)(Ag + k0);
            pa1 = *(const float4*)(Ag + k0 + 4);
            pb0 = *(const float4*)(Bg + k0);
            pb1 = *(const float4*)(Bg + k0 + 4);
        }
#pragma unroll
        for (int kq = 0; kq < 8; kq++) {
            ulonglong2 a[4], b[4];
#pragma unroll
            for (int i = 0; i < 4; i++)
                a[i] = *(const ulonglong2*)&As[buf][(tm * 4 + i) * GBK + ((kq ^ akey) << 2)];
#pragma unroll
            for (int j = 0; j < 4; j++)
                b[j] = *(const ulonglong2*)&Bs[buf][(tn * 4 + j) * GBK + ((kq ^ bkey) << 2)];
#pragma unroll
            for (int i = 0; i < 4; i++)
#pragma unroll
                for (int j = 0; j < 4; j++) {
                    c2[i][j] = fma2(a[i].x, b[j].x, c2[i][j]);
                    c2[i][j] = fma2(a[i].y, b[j].y, c2[i][j]);
                }
        }
        if (k0 < EE) {
            int nb = buf ^ 1;
            *(float4*)&As[nb][s0] = pa0;
            *(float4*)&As[nb][s1] = pa1;
            *(float4*)&Bs[nb][s0] = pb0;
            *(float4*)&Bs[nb][s1] = pb1;
            __syncthreads();
        }
        buf ^= 1;
    }

    float4 bbv = *(const float4*)&bias[n0 + tn * 4];
#pragma unroll
    for (int i = 0; i < 4; i++) {
        float4 r;
        r.x = sum2(c2[i][0]) + bbv.x;
        r.y = sum2(c2[i][1]) + bbv.y;
        r.z = sum2(c2[i][2]) + bbv.z;
        r.w = sum2(c2[i][3]) + bbv.w;
        int m = m0 + tm * 4 + i;
        if (NOUT == 3) {
            int bi = m >> 11;
            int t = m & 2047;
            int h = n0 >> 6;
            *(float4*)&Y[(((size_t)bi * HH + h) * TT + t) * DD + tn * 4] = r;
        } else {
            *(float4*)&Y[(size_t)m * EE + n0 + tn * 4] = r;
        }
    }
}

// ---------------------------------------------------------------------------
// Attention: block per (q-tile of 64, h, b). 512 threads = 16 warps.
// K/V/Q smem tiles stored [row][64] with XOR chunk swizzle pos = c ^ (r&7):
// lanes access consecutive rows -> conflict-free LDS.128.
// Dot-product scores w/ precomputed norms, radix-4 exact top-96, softmax,
// FFMA2 PV.
// ---------------------------------------------------------------------------
__device__ __forceinline__ int aswz(int r, int c) {  // float offset, 64-f rows
    return (r << 6) + ((c ^ (r & 7)) << 2);
}

__global__ __launch_bounds__(512) void attn_kernel(const float* __restrict__ log_sigma) {
    extern __shared__ float sm[];
    float* sQ = sm;                       // 64  x 64 (swizzled)
    float* sK = sQ + 64 * 64;             // 192 x 64 (swizzled)
    float* sV = sK + KROWS * 64;          // 192 x 64 (swizzled)
    float* sP = sV + KROWS * 64;          // 64  x 132
    float* sKsq = sP + 64 * PPAD;         // 192
    float* sQsq = sKsq + KROWS;           // 64

    const int q0 = blockIdx.x * QT;
    const int h = blockIdx.y;
    const int b = blockIdx.z;
    const int tid = threadIdx.x;

    const float* Qg = g_q + ((size_t)(b * HH + h) * TT) * DD;
    const float* Kg = g_k + ((size_t)(b * HH + h) * TT) * DD;
    const float* Vg = g_v + ((size_t)(b * HH + h) * TT) * DD;
    const float scale = -0.5f * expf(-2.f * log_sigma[h]);

    // ---- load tiles (swizzled stores) ----
    for (int i = tid; i < 64 * 16; i += 512) {
        int r = i >> 4, c = i & 15;
        *(float4*)&sQ[aswz(r, c)] =
            *(const float4*)&Qg[(size_t)(q0 + r) * DD + c * 4];
    }
    const float4 z4 = make_float4(0.f, 0.f, 0.f, 0.f);
    for (int i = tid; i < KROWS * 16; i += 512) {
        int r = i >> 4, c = i & 15;
        int gk = q0 - 128 + r;
        float4 kv = z4, vv = z4;
        if (gk >= 0) {
            kv = *(const float4*)&Kg[(size_t)gk * DD + c * 4];
            vv = *(const float4*)&Vg[(size_t)gk * DD + c * 4];
        }
        *(float4*)&sK[aswz(r, c)] = kv;
        *(float4*)&sV[aswz(r, c)] = vv;
    }
    __syncthreads();

    // ---- row norms ----
    if (tid < KROWS + 64) {
        int rr = (tid < KROWS) ? tid : (tid - KROWS);
        const float* base = (tid < KROWS) ? sK : sQ;
        ull acc = 0ull;
#pragma unroll
        for (int c = 0; c < 16; c++) {
            ulonglong2 v = *(const ulonglong2*)&base[aswz(rr, c)];
            acc = fma2(v.x, v.x, acc);
            acc = fma2(v.y, v.y, acc);
        }
        float s = sum2(acc);
        if (tid < KROWS) sKsq[tid] = s;
        else sQsq[tid - KROWS] = s;
    }
    __syncthreads();

    // ---- scores + top-k + softmax (warp per 4 queries; lane owns 4 keys) ----
    const int w = tid >> 5, l = tid & 31;
    const float NEGINF = __int_as_float(0xff800000);

    for (int qq = 0; qq < 4; qq++) {
        const int qi = w * 4 + qq;
        const int gq = q0 + qi;
        const int qkey = qi & 7;
        const int r0 = qi + 1 + l;           // + 32t for t-th key
        const int rkey = r0 & 7;             // (r0+32t)&7 == r0&7
        ull acc2[4] = {0ull, 0ull, 0ull, 0ull};
#pragma unroll 8
        for (int c = 0; c < 16; c++) {
            ulonglong2 qv = *(const ulonglong2*)&sQ[(qi << 6) + ((c ^ qkey) << 2)];
            const int coff = (c ^ rkey) << 2;
#pragma unroll
            for (int t = 0; t < 4; t++) {
                ulonglong2 kv = *(const ulonglong2*)&sK[((r0 + 32 * t) << 6) + coff];
                acc2[t] = fma2(qv.x, kv.x, acc2[t]);
                acc2[t] = fma2(qv.y, kv.y, acc2[t]);
            }
        }
        float s[4];
        unsigned key[4];
        bool valid[4];
        float qs = sQsq[qi];
#pragma unroll
        for (int t = 0; t < 4; t++) {
            int j = l + 32 * t;
            float dot = sum2(acc2[t]);
            float dist = qs + sKsq[qi + 1 + j] - 2.f * dot;
            s[t] = dist * scale;
            valid[t] = (gq - 127 + j) >= 0;
            key[t] = valid[t] ? f2ord(s[t]) : 0u;
        }

        unsigned thr = 0u;
        if (gq >= TOPKK) {
#pragma unroll 1
            for (int bp = 30; bp >= 0; bp -= 2) {
                unsigned c1 = thr | (1u << bp);
                unsigned cc2 = thr | (2u << bp);
                unsigned c3 = thr | (3u << bp);
                unsigned pk = 0;
#pragma unroll
                for (int t = 0; t < 4; t++) {
                    pk += (key[t] >= c1 ? 1u : 0u);
                    pk += (key[t] >= cc2 ? 0x100u : 0u);
                    pk += (key[t] >= c3 ? 0x10000u : 0u);
                }
                pk = __reduce_add_sync(0xffffffffu, pk);
                if ((pk >> 16) >= TOPKK) thr = c3;
                else if (((pk >> 8) & 0xffu) >= TOPKK) thr = cc2;
                else if ((pk & 0xffu) >= TOPKK) thr = c1;
            }
        }

        bool kept[4];
        float mv = NEGINF;
#pragma unroll
        for (int t = 0; t < 4; t++) {
            kept[t] = valid[t] && (key[t] >= thr);
            if (kept[t]) mv = fmaxf(mv, s[t]);
        }
#pragma unroll
        for (int o = 16; o > 0; o >>= 1)
            mv = fmaxf(mv, __shfl_xor_sync(0xffffffffu, mv, o));

        float e[4];
        float esum = 0.f;
#pragma unroll
        for (int t = 0; t < 4; t++) {
            e[t] = kept[t] ? __expf(s[t] - mv) : 0.f;
            esum += e[t];
        }
#pragma unroll
        for (int o = 16; o > 0; o >>= 1)
            esum += __shfl_xor_sync(0xffffffffu, esum, o);
        float inv = 1.f / esum;
#pragma unroll
        for (int t = 0; t < 4; t++) sP[qi * PPAD + l + 32 * t] = e[t] * inv;
    }
    __syncthreads();

    // ---- PV: thread (qi = tid&63, dg = tid>>6) covers dims dg*8..dg*8+7 ----
    {
        const int qi = tid & 63;
        const int dg = tid >> 6;
        ull o2[4] = {0ull, 0ull, 0ull, 0ull};
        const float* prow = &sP[qi * PPAD];
#pragma unroll 2
        for (int j4 = 0; j4 < 128; j4 += 4) {
            float4 p4 = *(const float4*)&prow[j4];
#pragma unroll
            for (int jj = 0; jj < 4; jj++) {
                int r = qi + 1 + j4 + jj;
                float pj = (jj == 0) ? p4.x : (jj == 1) ? p4.y : (jj == 2) ? p4.z : p4.w;
                ull p2 = pack2(pj);
                int rk = r & 7;
                ulonglong2 v0 = *(const ulonglong2*)&sV[(r << 6) + (((2 * dg) ^ rk) << 2)];
                ulonglong2 v1 = *(const ulonglong2*)&sV[(r << 6) + (((2 * dg + 1) ^ rk) << 2)];
                o2[0] = fma2(p2, v0.x, o2[0]);
                o2[1] = fma2(p2, v0.y, o2[1]);
                o2[2] = fma2(p2, v1.x, o2[2]);
                o2[3] = fma2(p2, v1.y, o2[3]);
            }
        }
        size_t obase = ((size_t)b * TT + q0 + qi) * EE + h * DD + dg * 8;
        ulonglong2 w0, w1;
        w0.x = o2[0]; w0.y = o2[1];
        w1.x = o2[2]; w1.y = o2[3];
        *(ulonglong2*)&g_attn[obase] = w0;
        *(ulonglong2*)&g_attn[obase + 4] = w1;
    }
}

// ---------------------------------------------------------------------------
extern "C" void kernel_launch(void* const* d_in, const int* in_sizes, int n_in,
                              void* d_out, int out_size) {
    const float* x  = (const float*)d_in[0];
    const float* Wq = (const float*)d_in[1];
    const float* bq = (const float*)d_in[2];
    const float* Wk = (const float*)d_in[3];
    const float* bk = (const float*)d_in[4];
    const float* Wv = (const float*)d_in[5];
    const float* bv = (const float*)d_in[6];
    const float* Wo = (const float*)d_in[7];
    const float* bo = (const float*)d_in[8];
    const float* ls = (const float*)d_in[9];

    float *qp, *kp, *vp, *ap;
    cudaGetSymbolAddress((void**)&qp, g_q);
    cudaGetSymbolAddress((void**)&kp, g_k);
    cudaGetSymbolAddress((void**)&vp, g_v);
    cudaGetSymbolAddress((void**)&ap, g_attn);

    dim3 gqkv(BB * TT / 64, EE / 64, 3);  // 128 x 8 x 3
    gemmk<3><<<gqkv, 256>>>(x, Wq, bq, qp, Wk, bk, kp, Wv, bv, vp);

    const size_t smem =
        (size_t)(64 * 64 + 2 * KROWS * 64 + 64 * PPAD + KROWS + 64) * sizeof(float);
    cudaFuncSetAttribute(attn_kernel, cudaFuncAttributeMaxDynamicSharedMemorySize,
                         (int)smem);
    attn_kernel<<<dim3(TT / QT, HH, BB), 512, smem>>>(ls);

    dim3 go(BB * TT / 64, EE / 64);  // 128 x 8
    gemmk<1><<<go, 256>>>(ap, Wo, bo, (float*)d_out,
                          nullptr, nullptr, nullptr, nullptr, nullptr, nullptr);
}

// round 6
// speedup vs baseline: 1.2549x; 1.0397x over previous
#include <cuda_runtime.h>
#include <math.h>

#define BB 4
#define HH 8
#define TT 2048
#define DD 64
#define EE 512
#define TOPKK 96
#define QT 64
#define KROWS 192
#define PTS 68   // sPT row stride (64 queries + 4 pad), float4-aligned

typedef unsigned long long ull;

// Scratch (device globals; no allocation allowed)
__device__ float g_q[(size_t)BB * HH * TT * DD];
__device__ float g_k[(size_t)BB * HH * TT * DD];
__device__ float g_v[(size_t)BB * HH * TT * DD];
__device__ float g_attn[(size_t)BB * TT * EE];

__device__ __forceinline__ ull fma2(ull a, ull b, ull c) {
    ull d;
    asm("fma.rn.f32x2 %0, %1, %2, %3;" : "=l"(d) : "l"(a), "l"(b), "l"(c));
    return d;
}
__device__ __forceinline__ ull pack2(float x) {
    ull d;
    asm("mov.b64 %0, {%1, %1};" : "=l"(d) : "f"(x));
    return d;
}
__device__ __forceinline__ float sum2(ull v) {
    float lo, hi;
    asm("mov.b64 {%0, %1}, %2;" : "=f"(lo), "=f"(hi) : "l"(v));
    return lo + hi;
}
__device__ __forceinline__ void unpack2(ull v, float& lo, float& hi) {
    asm("mov.b64 {%0, %1}, %2;" : "=f"(lo), "=f"(hi) : "l"(v));
}
__device__ __forceinline__ unsigned f2ord(float f) {
    unsigned u = __float_as_uint(f);
    return (u & 0x80000000u) ? ~u : (u | 0x80000000u);
}
__device__ __forceinline__ unsigned s2u(const void* p) {
    return (unsigned)__cvta_generic_to_shared(p);
}
__device__ __forceinline__ void cpa16(unsigned saddr, const void* g) {
    asm volatile("cp.async.cg.shared.global [%0], [%1], 16;" :: "r"(saddr), "l"(g));
}

// ---------------------------------------------------------------------------
// GEMM: Y = X @ W^T + bias.  X:[M,512], W:[512,512] row-major.
// 128x64 tile, BK=32, 256 threads, 8x4 microtile, k-pair-packed FFMA2,
// cp.async double-buffered.  Smem tiles [row][32] XOR-chunk-swizzled:
// pos = c ^ ((r>>2)&7)  -> B compute loads conflict-free, A loads broadcast.
// ---------------------------------------------------------------------------
#define GBK 32
#define ABUF (128 * GBK)
#define BBUF (64 * GBK)

__device__ __forceinline__ int gswz(int r, int c) {  // float offset in tile
    return r * GBK + ((c ^ ((r >> 2) & 7)) << 2);
}

template <int NOUT>
__global__ __launch_bounds__(256, 2) void gemmk(
    const float* __restrict__ X,
    const float* __restrict__ W0, const float* __restrict__ bias0, float* __restrict__ Y0,
    const float* __restrict__ W1, const float* __restrict__ bias1, float* __restrict__ Y1,
    const float* __restrict__ W2, const float* __restrict__ bias2, float* __restrict__ Y2) {
    extern __shared__ float smg[];
    float* As = smg;               // [2][128*32]
    float* Bs = smg + 2 * ABUF;    // [2][64*32]

    const float* W;
    const float* bias;
    float* Y;
    if (NOUT == 3) {
        int z = blockIdx.z;
        W = (z == 0) ? W0 : (z == 1) ? W1 : W2;
        bias = (z == 0) ? bias0 : (z == 1) ? bias1 : bias2;
        Y = (z == 0) ? Y0 : (z == 1) ? Y1 : Y2;
    } else {
        W = W0; bias = bias0; Y = Y0;
    }

    const int m0 = blockIdx.x * 128;
    const int n0 = blockIdx.y * 64;
    const int tid = threadIdx.x;
    const int tm = tid >> 4;   // 0..15 -> rows tm*8..+7
    const int tn = tid & 15;   // 0..15 -> cols tn*4..+3

    // global->smem mapping
    const int ar = tid >> 1, ac = (tid & 1) * 4;   // A: row, chunk base (4 chunks)
    const int br = tid >> 2, bc = (tid & 3) * 2;   // B: row, chunk base (2 chunks)
    const float* Agp = X + (size_t)(m0 + ar) * EE;
    const float* Bgp = W + (size_t)(n0 + br) * EE;
    unsigned sA[4], sB[2];
#pragma unroll
    for (int u = 0; u < 4; u++) sA[u] = s2u(&As[gswz(ar, ac + u)]);
#pragma unroll
    for (int u = 0; u < 2; u++) sB[u] = s2u(&Bs[gswz(br, bc + u)]);

    auto issue = [&](int t, int buf) {
        const float* ag = Agp + t * GBK;
        const float* bg = Bgp + t * GBK;
        unsigned ao = buf * (ABUF * 4);
        unsigned bo = buf * (BBUF * 4);
#pragma unroll
        for (int u = 0; u < 4; u++) cpa16(sA[u] + ao, ag + (ac + u) * 4);
#pragma unroll
        for (int u = 0; u < 2; u++) cpa16(sB[u] + bo, bg + (bc + u) * 4);
        asm volatile("cp.async.commit_group;");
    };

    ull c2[2][4][4];
#pragma unroll
    for (int ih = 0; ih < 2; ih++)
#pragma unroll
        for (int i = 0; i < 4; i++)
#pragma unroll
            for (int j = 0; j < 4; j++) c2[ih][i][j] = 0ull;

    issue(0, 0);
    const int NT = EE / GBK;  // 16
    for (int t = 0; t < NT; t++) {
        if (t + 1 < NT) {
            issue(t + 1, (t + 1) & 1);
            asm volatile("cp.async.wait_group 1;");
        } else {
            asm volatile("cp.async.wait_group 0;");
        }
        __syncthreads();
        const float* Ab = As + (t & 1) * ABUF;
        const float* Bb = Bs + (t & 1) * BBUF;
#pragma unroll
        for (int kq = 0; kq < 8; kq++) {
            ulonglong2 b[4];
            const int bco = ((kq ^ (tn & 7)) << 2);
#pragma unroll
            for (int j = 0; j < 4; j++)
                b[j] = *(const ulonglong2*)&Bb[(tn * 4 + j) * GBK + bco];
#pragma unroll
            for (int ih = 0; ih < 2; ih++) {
                const int aco = ((kq ^ ((2 * tm + ih) & 7)) << 2);
                ulonglong2 a[4];
#pragma unroll
                for (int i = 0; i < 4; i++)
                    a[i] = *(const ulonglong2*)&Ab[(tm * 8 + ih * 4 + i) * GBK + aco];
#pragma unroll
                for (int i = 0; i < 4; i++)
#pragma unroll
                    for (int j = 0; j < 4; j++) {
                        c2[ih][i][j] = fma2(a[i].x, b[j].x, c2[ih][i][j]);
                        c2[ih][i][j] = fma2(a[i].y, b[j].y, c2[ih][i][j]);
                    }
            }
        }
        __syncthreads();
    }

    float4 bbv = *(const float4*)&bias[n0 + tn * 4];
#pragma unroll
    for (int ih = 0; ih < 2; ih++)
#pragma unroll
        for (int i = 0; i < 4; i++) {
            float4 r;
            r.x = sum2(c2[ih][i][0]) + bbv.x;
            r.y = sum2(c2[ih][i][1]) + bbv.y;
            r.z = sum2(c2[ih][i][2]) + bbv.z;
            r.w = sum2(c2[ih][i][3]) + bbv.w;
            int m = m0 + tm * 8 + ih * 4 + i;
            if (NOUT == 3) {
                int bi = m >> 11;
                int tt = m & 2047;
                int h = n0 >> 6;
                *(float4*)&Y[(((size_t)bi * HH + h) * TT + tt) * DD + tn * 4] = r;
            } else {
                *(float4*)&Y[(size_t)m * EE + n0 + tn * 4] = r;
            }
        }
}

// ---------------------------------------------------------------------------
// Attention: block per (q-tile of 64, h, b). 512 threads = 16 warps.
// K/V/Q smem [row][64] XOR-chunk-swizzled: pos = c ^ (r&7).
// Score phase: warp per 4 queries, lane owns absolute rows {l+32t, t=0..5}
// -> K loads shared across the 4 queries. Radix-4 exact top-96, softmax.
// P stored TRANSPOSED sPT[row][query] so PV runs as an outer product:
// thread = (4-query group, dim pair); per row: broadcast float4 P + 8B V.
// ---------------------------------------------------------------------------
__device__ __forceinline__ int aswz(int r, int c) {  // float offset, 64-f rows
    return (r << 6) + ((c ^ (r & 7)) << 2);
}

__global__ __launch_bounds__(512) void attn_kernel(const float* __restrict__ log_sigma) {
    extern __shared__ float sm[];
    float* sQ = sm;                       // 64  x 64 (swizzled)
    float* sK = sQ + 64 * 64;             // 192 x 64 (swizzled)
    float* sV = sK + KROWS * 64;          // 192 x 64 (swizzled)
    float* sPT = sV + KROWS * 64;         // 192 x 68 (row-major, [row][query])
    float* sKsq = sPT + KROWS * PTS;      // 192
    float* sQsq = sKsq + KROWS;           // 64

    const int q0 = blockIdx.x * QT;
    const int h = blockIdx.y;
    const int b = blockIdx.z;
    const int tid = threadIdx.x;

    const float* Qg = g_q + ((size_t)(b * HH + h) * TT) * DD;
    const float* Kg = g_k + ((size_t)(b * HH + h) * TT) * DD;
    const float* Vg = g_v + ((size_t)(b * HH + h) * TT) * DD;
    const float scale = -0.5f * expf(-2.f * log_sigma[h]);

    // ---- load tiles (swizzled stores) ----
    for (int i = tid; i < 64 * 16; i += 512) {
        int r = i >> 4, c = i & 15;
        *(float4*)&sQ[aswz(r, c)] =
            *(const float4*)&Qg[(size_t)(q0 + r) * DD + c * 4];
    }
    const float4 z4 = make_float4(0.f, 0.f, 0.f, 0.f);
    for (int i = tid; i < KROWS * 16; i += 512) {
        int r = i >> 4, c = i & 15;
        int gk = q0 - 128 + r;
        float4 kv = z4, vv = z4;
        if (gk >= 0) {
            kv = *(const float4*)&Kg[(size_t)gk * DD + c * 4];
            vv = *(const float4*)&Vg[(size_t)gk * DD + c * 4];
        }
        *(float4*)&sK[aswz(r, c)] = kv;
        *(float4*)&sV[aswz(r, c)] = vv;
    }
    __syncthreads();

    // ---- row norms ----
    if (tid < KROWS + 64) {
        int rr = (tid < KROWS) ? tid : (tid - KROWS);
        const float* base = (tid < KROWS) ? sK : sQ;
        ull acc = 0ull;
#pragma unroll
        for (int c = 0; c < 16; c++) {
            ulonglong2 v = *(const ulonglong2*)&base[aswz(rr, c)];
            acc = fma2(v.x, v.x, acc);
            acc = fma2(v.y, v.y, acc);
        }
        float s = sum2(acc);
        if (tid < KROWS) sKsq[tid] = s;
        else sQsq[tid - KROWS] = s;
    }
    __syncthreads();

    // ---- scores: warp per 4 queries; lane owns rows {l+32t, t=0..5} ----
    const int w = tid >> 5, l = tid & 31;
    const float NEGINF = __int_as_float(0xff800000);
    const int qb = w * 4;

    ull acc2[4][6];
#pragma unroll
    for (int qq = 0; qq < 4; qq++)
#pragma unroll
        for (int t = 0; t < 6; t++) acc2[qq][t] = 0ull;

    {
        const int rk = l & 7;  // (l+32t)&7 == l&7
#pragma unroll 4
        for (int c = 0; c < 16; c++) {
            const int coff = (c ^ rk) << 2;
            ulonglong2 kv[6];
#pragma unroll
            for (int t = 0; t < 6; t++)
                kv[t] = *(const ulonglong2*)&sK[((l + 32 * t) << 6) + coff];
#pragma unroll
            for (int qq = 0; qq < 4; qq++) {
                const int qi = qb + qq;
                ulonglong2 qv = *(const ulonglong2*)&sQ[(qi << 6) + ((c ^ (qi & 7)) << 2)];
#pragma unroll
                for (int t = 0; t < 6; t++) {
                    acc2[qq][t] = fma2(qv.x, kv[t].x, acc2[qq][t]);
                    acc2[qq][t] = fma2(qv.y, kv[t].y, acc2[qq][t]);
                }
            }
        }
    }

    // ---- per query: top-k threshold + softmax, store P transposed ----
#pragma unroll 1
    for (int qq = 0; qq < 4; qq++) {
        const int qi = qb + qq;
        const int gq = q0 + qi;
        const float qs = sQsq[qi];
        float s[6];
        unsigned key[6];
#pragma unroll
        for (int t = 0; t < 6; t++) {
            int r = l + 32 * t;
            float dot = sum2(acc2[qq][t]);
            float dist = qs + sKsq[r] - 2.f * dot;
            s[t] = dist * scale;
            bool valid = (r > qi) && (r <= qi + 128) && (q0 - 128 + r >= 0);
            key[t] = valid ? f2ord(s[t]) : 0u;
        }

        unsigned thr = 0u;
        if (gq >= TOPKK) {
#pragma unroll 1
            for (int bp = 30; bp >= 0; bp -= 2) {
                unsigned c1 = thr | (1u << bp);
                unsigned cA = thr | (2u << bp);
                unsigned cB = thr | (3u << bp);
                unsigned pk = 0;
#pragma unroll
                for (int t = 0; t < 6; t++) {
                    pk += (key[t] >= c1 ? 1u : 0u);
                    pk += (key[t] >= cA ? 0x100u : 0u);
                    pk += (key[t] >= cB ? 0x10000u : 0u);
                }
                pk = __reduce_add_sync(0xffffffffu, pk);
                if ((pk >> 16) >= TOPKK) thr = cB;
                else if (((pk >> 8) & 0xffu) >= TOPKK) thr = cA;
                else if ((pk & 0xffu) >= TOPKK) thr = c1;
            }
        }

        float mv = NEGINF;
        bool kept[6];
#pragma unroll
        for (int t = 0; t < 6; t++) {
            kept[t] = (key[t] != 0u) && (key[t] >= thr);
            if (kept[t]) mv = fmaxf(mv, s[t]);
        }
#pragma unroll
        for (int o = 16; o > 0; o >>= 1)
            mv = fmaxf(mv, __shfl_xor_sync(0xffffffffu, mv, o));

        float e[6];
        float esum = 0.f;
#pragma unroll
        for (int t = 0; t < 6; t++) {
            e[t] = kept[t] ? __expf(s[t] - mv) : 0.f;
            esum += e[t];
        }
#pragma unroll
        for (int o = 16; o > 0; o >>= 1)
            esum += __shfl_xor_sync(0xffffffffu, esum, o);
        float inv = 1.f / esum;
#pragma unroll
        for (int t = 0; t < 6; t++)
            sPT[(l + 32 * t) * PTS + qi] = e[t] * inv;
    }
    __syncthreads();

    // ---- PV outer product: thread = (4-query group qg, dim pair dp) ----
    {
        const int qg = tid >> 5;   // 0..15, queries 4qg..4qg+3
        const int dp = tid & 31;   // dims 2dp, 2dp+1
        ull acc[2][2] = {{0ull, 0ull}, {0ull, 0ull}};  // [dim_sub][query_pair]
        const int rbeg = 4 * qg + 1;
        const int g = dp >> 1;
        const int sub = (dp & 1) * 2;
#pragma unroll 4
        for (int jj = 0; jj < 131; jj++) {
            int r = rbeg + jj;
            ulonglong2 p4 = *(const ulonglong2*)&sPT[r * PTS + 4 * qg];
            const float* vp = &sV[(r << 6) + (((g ^ (r & 7)) << 2)) + sub];
            float2 vv = *(const float2*)vp;
            ull vd0 = pack2(vv.x);
            ull vd1 = pack2(vv.y);
            acc[0][0] = fma2(p4.x, vd0, acc[0][0]);
            acc[0][1] = fma2(p4.y, vd0, acc[0][1]);
            acc[1][0] = fma2(p4.x, vd1, acc[1][0]);
            acc[1][1] = fma2(p4.y, vd1, acc[1][1]);
        }
        size_t obase = ((size_t)b * TT + q0 + 4 * qg) * EE + h * DD + 2 * dp;
#pragma unroll
        for (int qp = 0; qp < 2; qp++)
#pragma unroll
            for (int dd = 0; dd < 2; dd++) {
                float lo, hi;
                unpack2(acc[dd][qp], lo, hi);
                g_attn[obase + (size_t)(2 * qp) * EE + dd] = lo;
                g_attn[obase + (size_t)(2 * qp + 1) * EE + dd] = hi;
            }
    }
}

// ---------------------------------------------------------------------------
extern "C" void kernel_launch(void* const* d_in, const int* in_sizes, int n_in,
                              void* d_out, int out_size) {
    const float* x  = (const float*)d_in[0];
    const float* Wq = (const float*)d_in[1];
    const float* bq = (const float*)d_in[2];
    const float* Wk = (const float*)d_in[3];
    const float* bk = (const float*)d_in[4];
    const float* Wv = (const float*)d_in[5];
    const float* bv = (const float*)d_in[6];
    const float* Wo = (const float*)d_in[7];
    const float* bo = (const float*)d_in[8];
    const float* ls = (const float*)d_in[9];

    float *qp, *kp, *vp, *ap;
    cudaGetSymbolAddress((void**)&qp, g_q);
    cudaGetSymbolAddress((void**)&kp, g_k);
    cudaGetSymbolAddress((void**)&vp, g_v);
    cudaGetSymbolAddress((void**)&ap, g_attn);

    const int gsmem = (2 * ABUF + 2 * BBUF) * sizeof(float);  // 49152
    cudaFuncSetAttribute(gemmk<3>, cudaFuncAttributeMaxDynamicSharedMemorySize, gsmem);
    cudaFuncSetAttribute(gemmk<1>, cudaFuncAttributeMaxDynamicSharedMemorySize, gsmem);

    dim3 gqkv(BB * TT / 128, EE / 64, 3);  // 64 x 8 x 3
    gemmk<3><<<gqkv, 256, gsmem>>>(x, Wq, bq, qp, Wk, bk, kp, Wv, bv, vp);

    const size_t asmem =
        (size_t)(64 * 64 + 2 * KROWS * 64 + KROWS * PTS + KROWS + 64) * sizeof(float);
    cudaFuncSetAttribute(attn_kernel, cudaFuncAttributeMaxDynamicSharedMemorySize,
                         (int)asmem);
    attn_kernel<<<dim3(TT / QT, HH, BB), 512, asmem>>>(ls);

    dim3 go(BB * TT / 128, EE / 64);  // 64 x 8
    gemmk<1><<<go, 256, gsmem>>>(ap, Wo, bo, (float*)d_out,
                                 nullptr, nullptr, nullptr, nullptr, nullptr, nullptr);
}

// round 8
// speedup vs baseline: 1.5161x; 1.2082x over previous
#include <cuda_runtime.h>
#include <math.h>

#define BB 4
#define HH 8
#define TT 2048
#define DD 64
#define EE 512
#define TOPKK 96
#define QT 64
#define KROWS 192
#define PTS 68   // sPT row stride (64 queries + 4 pad), float4-aligned

typedef unsigned long long ull;

// Scratch (device globals; no allocation allowed)
__device__ float g_q[(size_t)BB * HH * TT * DD];
__device__ float g_k[(size_t)BB * HH * TT * DD];
__device__ float g_v[(size_t)BB * HH * TT * DD];
__device__ float g_attn[(size_t)BB * TT * EE];

__device__ __forceinline__ ull fma2(ull a, ull b, ull c) {
    ull d;
    asm("fma.rn.f32x2 %0, %1, %2, %3;" : "=l"(d) : "l"(a), "l"(b), "l"(c));
    return d;
}
__device__ __forceinline__ ull pack2(float x) {
    ull d;
    asm("mov.b64 %0, {%1, %1};" : "=l"(d) : "f"(x));
    return d;
}
__device__ __forceinline__ float sum2(ull v) {
    float lo, hi;
    asm("mov.b64 {%0, %1}, %2;" : "=f"(lo), "=f"(hi) : "l"(v));
    return lo + hi;
}
__device__ __forceinline__ void unpack2(ull v, float& lo, float& hi) {
    asm("mov.b64 {%0, %1}, %2;" : "=f"(lo), "=f"(hi) : "l"(v));
}
__device__ __forceinline__ unsigned f2ord(float f) {
    unsigned u = __float_as_uint(f);
    return (u & 0x80000000u) ? ~u : (u | 0x80000000u);
}
__device__ __forceinline__ unsigned s2u(const void* p) {
    return (unsigned)__cvta_generic_to_shared(p);
}
__device__ __forceinline__ unsigned tf32rna(float f) {
    unsigned u;
    asm("cvt.rna.tf32.f32 %0, %1;" : "=r"(u) : "f"(f));
    return u;
}
__device__ __forceinline__ void ldsm4(unsigned& r0, unsigned& r1, unsigned& r2,
                                      unsigned& r3, unsigned addr) {
    asm volatile("ldmatrix.sync.aligned.m8n8.x4.shared.b16 {%0,%1,%2,%3}, [%4];"
                 : "=r"(r0), "=r"(r1), "=r"(r2), "=r"(r3) : "r"(addr));
}
__device__ __forceinline__ void mma_tf32(float& c0, float& c1, float& c2, float& c3,
                                         unsigned a0, unsigned a1, unsigned a2,
                                         unsigned a3, unsigned b0, unsigned b1) {
    asm volatile(
        "mma.sync.aligned.m16n8k8.row.col.f32.tf32.tf32.f32 "
        "{%0,%1,%2,%3}, {%4,%5,%6,%7}, {%8,%9}, {%0,%1,%2,%3};"
        : "+f"(c0), "+f"(c1), "+f"(c2), "+f"(c3)
        : "r"(a0), "r"(a1), "r"(a2), "r"(a3), "r"(b0), "r"(b1));
}

// ---------------------------------------------------------------------------
// 3xTF32 split-precision tensor-core GEMM: Y = X @ W^T + bias.
// x = hi + lo (hi = rna_tf32(x), lo = rna_tf32(x - hi));
// D = A_hi B_hi + A_hi B_lo + A_lo B_hi  (error ~2^-22, ~fp32).
// CTA tile 64(m) x 128(n) x 32(k), 256 threads = 8 warps (2m x 4n),
// warp tile 32x32 -> 2 m x 4 n m16n8k8 tiles. Fragments via ldmatrix.x4 on
// XOR-swizzled smem (chunk pos = c ^ (row&7)). Reg-staged double buffer;
// hi and lo tiles stored contiguously per buffer.
// ---------------------------------------------------------------------------
#define GBM 64
#define GBN 128
#define GBK 32
#define ABUF (GBM * GBK)     // hi tile floats
#define ASEG (2 * ABUF)      // hi + lo per buffer
#define BBUF (GBN * GBK)
#define BSEG (2 * BBUF)

template <int NOUT>
__global__ __launch_bounds__(256, 2) void gemmk(
    const float* __restrict__ X,
    const float* __restrict__ W0, const float* __restrict__ bias0, float* __restrict__ Y0,
    const float* __restrict__ W1, const float* __restrict__ bias1, float* __restrict__ Y1,
    const float* __restrict__ W2, const float* __restrict__ bias2, float* __restrict__ Y2) {
    extern __shared__ float smg[];
    float* sA = smg;                  // [2][hi 64*32 | lo 64*32]
    float* sB = smg + 2 * ASEG;       // [2][hi 128*32 | lo 128*32]

    const float* W;
    const float* bias;
    float* Y;
    if (NOUT == 3) {
        int z = blockIdx.z;
        W = (z == 0) ? W0 : (z == 1) ? W1 : W2;
        bias = (z == 0) ? bias0 : (z == 1) ? bias1 : bias2;
        Y = (z == 0) ? Y0 : (z == 1) ? Y1 : Y2;
    } else {
        W = W0; bias = bias0; Y = Y0;
    }

    const int m0 = blockIdx.x * GBM;
    const int n0 = blockIdx.y * GBN;
    const int tid = threadIdx.x;
    const int wid = tid >> 5;
    const int lane = tid & 31;
    const int wm = (wid & 1) * 32;
    const int wn = (wid >> 1) * 32;

    // ---- staging load mapping ----
    const int arow = tid >> 2, acb = (tid & 3) * 2;   // A: 2 chunks
    const int brow = tid >> 1, bcb = (tid & 1) * 4;   // B: 4 chunks
    const float* Agp = X + (size_t)(m0 + arow) * EE + acb * 4;
    const float* Bgp = W + (size_t)(n0 + brow) * EE + bcb * 4;
    int aoffs[2], boffs[4];
#pragma unroll
    for (int u = 0; u < 2; u++) aoffs[u] = arow * GBK + (((acb + u) ^ (arow & 7)) << 2);
#pragma unroll
    for (int u = 0; u < 4; u++) boffs[u] = brow * GBK + (((bcb + u) ^ (brow & 7)) << 2);

    // ---- fragment ldmatrix lane addressing ----
    const int a_m = (lane & 7) + ((lane >> 3) & 1) * 8;
    const int a_kh = lane >> 4;
    const int aoff = a_kh ^ (lane & 7);
    const int b_n = (lane & 7) + (lane >> 4) * 8;
    const int b_kh = (lane >> 3) & 1;
    const int boff = b_kh ^ (lane & 7);
    unsigned aBase[2], bBase[2];
#pragma unroll
    for (int mt = 0; mt < 2; mt++)
        aBase[mt] = s2u(sA) + (unsigned)(wm + mt * 16 + a_m) * (GBK * 4);
#pragma unroll
    for (int p = 0; p < 2; p++)
        bBase[p] = s2u(sB) + (unsigned)(wn + p * 16 + b_n) * (GBK * 4);

    float4 ra[2], rb[4];
    auto ldg = [&](int t) {
#pragma unroll
        for (int u = 0; u < 2; u++) ra[u] = *(const float4*)(Agp + t * GBK + u * 4);
#pragma unroll
        for (int u = 0; u < 4; u++) rb[u] = *(const float4*)(Bgp + t * GBK + u * 4);
    };
    auto split4 = [](float4 x, uint4& hi, uint4& lo) {
        hi.x = tf32rna(x.x); hi.y = tf32rna(x.y);
        hi.z = tf32rna(x.z); hi.w = tf32rna(x.w);
        lo.x = tf32rna(x.x - __uint_as_float(hi.x));
        lo.y = tf32rna(x.y - __uint_as_float(hi.y));
        lo.z = tf32rna(x.z - __uint_as_float(hi.z));
        lo.w = tf32rna(x.w - __uint_as_float(hi.w));
    };
    auto sts = [&](int buf) {
        float* Ab = sA + buf * ASEG;
        float* Bb = sB + buf * BSEG;
#pragma unroll
        for (int u = 0; u < 2; u++) {
            uint4 hi, lo;
            split4(ra[u], hi, lo);
            *(uint4*)&Ab[aoffs[u]] = hi;
            *(uint4*)&Ab[aoffs[u] + ABUF] = lo;
        }
#pragma unroll
        for (int u = 0; u < 4; u++) {
            uint4 hi, lo;
            split4(rb[u], hi, lo);
            *(uint4*)&Bb[boffs[u]] = hi;
            *(uint4*)&Bb[boffs[u] + BBUF] = lo;
        }
    };

    float c[2][4][4];
#pragma unroll
    for (int mt = 0; mt < 2; mt++)
#pragma unroll
        for (int nt = 0; nt < 4; nt++)
#pragma unroll
            for (int r = 0; r < 4; r++) c[mt][nt][r] = 0.f;

    ldg(0);
    sts(0);
    __syncthreads();

    const int NT = EE / GBK;  // 16
    for (int t = 0; t < NT; t++) {
        if (t + 1 < NT) ldg(t + 1);
        const unsigned abuf = (unsigned)(t & 1) * (ASEG * 4);
        const unsigned bbuf = (unsigned)(t & 1) * (BSEG * 4);
#pragma unroll
        for (int ks = 0; ks < 4; ks++) {
            unsigned ah[2][4], al[2][4], bh[4][2], bl[4][2];
#pragma unroll
            for (int mt = 0; mt < 2; mt++) {
                unsigned base = aBase[mt] + abuf + (unsigned)(((2 * ks) ^ aoff) << 4);
                ldsm4(ah[mt][0], ah[mt][1], ah[mt][2], ah[mt][3], base);
                ldsm4(al[mt][0], al[mt][1], al[mt][2], al[mt][3], base + ABUF * 4);
            }
#pragma unroll
            for (int p = 0; p < 2; p++) {
                unsigned base = bBase[p] + bbuf + (unsigned)(((2 * ks) ^ boff) << 4);
                ldsm4(bh[2 * p][0], bh[2 * p][1], bh[2 * p + 1][0], bh[2 * p + 1][1], base);
                ldsm4(bl[2 * p][0], bl[2 * p][1], bl[2 * p + 1][0], bl[2 * p + 1][1],
                      base + BBUF * 4);
            }
            // term 1: hi*hi
#pragma unroll
            for (int mt = 0; mt < 2; mt++)
#pragma unroll
                for (int nt = 0; nt < 4; nt++)
                    mma_tf32(c[mt][nt][0], c[mt][nt][1], c[mt][nt][2], c[mt][nt][3],
                             ah[mt][0], ah[mt][1], ah[mt][2], ah[mt][3],
                             bh[nt][0], bh[nt][1]);
            // term 2: hi*lo
#pragma unroll
            for (int mt = 0; mt < 2; mt++)
#pragma unroll
                for (int nt = 0; nt < 4; nt++)
                    mma_tf32(c[mt][nt][0], c[mt][nt][1], c[mt][nt][2], c[mt][nt][3],
                             ah[mt][0], ah[mt][1], ah[mt][2], ah[mt][3],
                             bl[nt][0], bl[nt][1]);
            // term 3: lo*hi
#pragma unroll
            for (int mt = 0; mt < 2; mt++)
#pragma unroll
                for (int nt = 0; nt < 4; nt++)
                    mma_tf32(c[mt][nt][0], c[mt][nt][1], c[mt][nt][2], c[mt][nt][3],
                             al[mt][0], al[mt][1], al[mt][2], al[mt][3],
                             bh[nt][0], bh[nt][1]);
        }
        __syncthreads();
        if (t + 1 < NT) {
            sts((t + 1) & 1);
            __syncthreads();
        }
    }

    // ---- epilogue ----
    const int g = lane >> 2;
    const int tc = lane & 3;
#pragma unroll
    for (int mt = 0; mt < 2; mt++)
#pragma unroll
        for (int nt = 0; nt < 4; nt++) {
            int col = n0 + wn + nt * 8 + tc * 2;
            float2 bb = *(const float2*)&bias[col];
            float2 v0 = make_float2(c[mt][nt][0] + bb.x, c[mt][nt][1] + bb.y);
            float2 v1 = make_float2(c[mt][nt][2] + bb.x, c[mt][nt][3] + bb.y);
            int row = m0 + wm + mt * 16 + g;
            if (NOUT == 3) {
                int h = col >> 6, d = col & 63;
                int bi = row >> 11, tt0 = row & 2047;
                float* base = Y + (((size_t)bi * HH + h) * TT) * DD + d;
                *(float2*)&base[(size_t)tt0 * DD] = v0;
                *(float2*)&base[(size_t)(tt0 + 8) * DD] = v1;
            } else {
                *(float2*)&Y[(size_t)row * EE + col] = v0;
                *(float2*)&Y[(size_t)(row + 8) * EE + col] = v1;
            }
        }
}

// ---------------------------------------------------------------------------
// Attention: block per (q-tile of 64, h, b). 512 threads = 16 warps.
// (unchanged from R6 — known passing)
// ---------------------------------------------------------------------------
__device__ __forceinline__ int aswz(int r, int c) {  // float offset, 64-f rows
    return (r << 6) + ((c ^ (r & 7)) << 2);
}

__global__ __launch_bounds__(512) void attn_kernel(const float* __restrict__ log_sigma) {
    extern __shared__ float sm[];
    float* sQ = sm;                       // 64  x 64 (swizzled)
    float* sK = sQ + 64 * 64;             // 192 x 64 (swizzled)
    float* sV = sK + KROWS * 64;          // 192 x 64 (swizzled)
    float* sPT = sV + KROWS * 64;         // 192 x 68 ([row][query])
    float* sKsq = sPT + KROWS * PTS;      // 192
    float* sQsq = sKsq + KROWS;           // 64

    const int q0 = blockIdx.x * QT;
    const int h = blockIdx.y;
    const int b = blockIdx.z;
    const int tid = threadIdx.x;

    const float* Qg = g_q + ((size_t)(b * HH + h) * TT) * DD;
    const float* Kg = g_k + ((size_t)(b * HH + h) * TT) * DD;
    const float* Vg = g_v + ((size_t)(b * HH + h) * TT) * DD;
    const float scale = -0.5f * expf(-2.f * log_sigma[h]);

    for (int i = tid; i < 64 * 16; i += 512) {
        int r = i >> 4, c = i & 15;
        *(float4*)&sQ[aswz(r, c)] =
            *(const float4*)&Qg[(size_t)(q0 + r) * DD + c * 4];
    }
    const float4 z4 = make_float4(0.f, 0.f, 0.f, 0.f);
    for (int i = tid; i < KROWS * 16; i += 512) {
        int r = i >> 4, c = i & 15;
        int gk = q0 - 128 + r;
        float4 kv = z4, vv = z4;
        if (gk >= 0) {
            kv = *(const float4*)&Kg[(size_t)gk * DD + c * 4];
            vv = *(const float4*)&Vg[(size_t)gk * DD + c * 4];
        }
        *(float4*)&sK[aswz(r, c)] = kv;
        *(float4*)&sV[aswz(r, c)] = vv;
    }
    __syncthreads();

    if (tid < KROWS + 64) {
        int rr = (tid < KROWS) ? tid : (tid - KROWS);
        const float* base = (tid < KROWS) ? sK : sQ;
        ull acc = 0ull;
#pragma unroll
        for (int c = 0; c < 16; c++) {
            ulonglong2 v = *(const ulonglong2*)&base[aswz(rr, c)];
            acc = fma2(v.x, v.x, acc);
            acc = fma2(v.y, v.y, acc);
        }
        float s = sum2(acc);
        if (tid < KROWS) sKsq[tid] = s;
        else sQsq[tid - KROWS] = s;
    }
    __syncthreads();

    const int w = tid >> 5, l = tid & 31;
    const float NEGINF = __int_as_float(0xff800000);
    const int qb = w * 4;

    ull acc2[4][6];
#pragma unroll
    for (int qq = 0; qq < 4; qq++)
#pragma unroll
        for (int t = 0; t < 6; t++) acc2[qq][t] = 0ull;

    {
        const int rk = l & 7;
#pragma unroll 4
        for (int c = 0; c < 16; c++) {
            const int coff = (c ^ rk) << 2;
            ulonglong2 kv[6];
#pragma unroll
            for (int t = 0; t < 6; t++)
                kv[t] = *(const ulonglong2*)&sK[((l + 32 * t) << 6) + coff];
#pragma unroll
            for (int qq = 0; qq < 4; qq++) {
                const int qi = qb + qq;
                ulonglong2 qv = *(const ulonglong2*)&sQ[(qi << 6) + ((c ^ (qi & 7)) << 2)];
#pragma unroll
                for (int t = 0; t < 6; t++) {
                    acc2[qq][t] = fma2(qv.x, kv[t].x, acc2[qq][t]);
                    acc2[qq][t] = fma2(qv.y, kv[t].y, acc2[qq][t]);
                }
            }
        }
    }

#pragma unroll 1
    for (int qq = 0; qq < 4; qq++) {
        const int qi = qb + qq;
        const int gq = q0 + qi;
        const float qs = sQsq[qi];
        float s[6];
        unsigned key[6];
#pragma unroll
        for (int t = 0; t < 6; t++) {
            int r = l + 32 * t;
            float dot = sum2(acc2[qq][t]);
            float dist = qs + sKsq[r] - 2.f * dot;
            s[t] = dist * scale;
            bool valid = (r > qi) && (r <= qi + 128) && (q0 - 128 + r >= 0);
            key[t] = valid ? f2ord(s[t]) : 0u;
        }

        unsigned thr = 0u;
        if (gq >= TOPKK) {
#pragma unroll 1
            for (int bp = 30; bp >= 0; bp -= 2) {
                unsigned c1 = thr | (1u << bp);
                unsigned cA = thr | (2u << bp);
                unsigned cB = thr | (3u << bp);
                unsigned pk = 0;
#pragma unroll
                for (int t = 0; t < 6; t++) {
                    pk += (key[t] >= c1 ? 1u : 0u);
                    pk += (key[t] >= cA ? 0x100u : 0u);
                    pk += (key[t] >= cB ? 0x10000u : 0u);
                }
                pk = __reduce_add_sync(0xffffffffu, pk);
                if ((pk >> 16) >= TOPKK) thr = cB;
                else if (((pk >> 8) & 0xffu) >= TOPKK) thr = cA;
                else if ((pk & 0xffu) >= TOPKK) thr = c1;
            }
        }

        float mv = NEGINF;
        bool kept[6];
#pragma unroll
        for (int t = 0; t < 6; t++) {
            kept[t] = (key[t] != 0u) && (key[t] >= thr);
            if (kept[t]) mv = fmaxf(mv, s[t]);
        }
#pragma unroll
        for (int o = 16; o > 0; o >>= 1)
            mv = fmaxf(mv, __shfl_xor_sync(0xffffffffu, mv, o));

        float e[6];
        float esum = 0.f;
#pragma unroll
        for (int t = 0; t < 6; t++) {
            e[t] = kept[t] ? __expf(s[t] - mv) : 0.f;
            esum += e[t];
        }
#pragma unroll
        for (int o = 16; o > 0; o >>= 1)
            esum += __shfl_xor_sync(0xffffffffu, esum, o);
        float inv = 1.f / esum;
#pragma unroll
        for (int t = 0; t < 6; t++)
            sPT[(l + 32 * t) * PTS + qi] = e[t] * inv;
    }
    __syncthreads();

    {
        const int qg = tid >> 5;
        const int dp = tid & 31;
        ull acc[2][2] = {{0ull, 0ull}, {0ull, 0ull}};
        const int rbeg = 4 * qg + 1;
        const int g = dp >> 1;
        const int sub = (dp & 1) * 2;
#pragma unroll 4
        for (int jj = 0; jj < 131; jj++) {
            int r = rbeg + jj;
            ulonglong2 p4 = *(const ulonglong2*)&sPT[r * PTS + 4 * qg];
            const float* vp = &sV[(r << 6) + (((g ^ (r & 7)) << 2)) + sub];
            float2 vv = *(const float2*)vp;
            ull vd0 = pack2(vv.x);
            ull vd1 = pack2(vv.y);
            acc[0][0] = fma2(p4.x, vd0, acc[0][0]);
            acc[0][1] = fma2(p4.y, vd0, acc[0][1]);
            acc[1][0] = fma2(p4.x, vd1, acc[1][0]);
            acc[1][1] = fma2(p4.y, vd1, acc[1][1]);
        }
        size_t obase = ((size_t)b * TT + q0 + 4 * qg) * EE + h * DD + 2 * dp;
#pragma unroll
        for (int qp = 0; qp < 2; qp++)
#pragma unroll
            for (int dd = 0; dd < 2; dd++) {
                float lo, hi;
                unpack2(acc[dd][qp], lo, hi);
                g_attn[obase + (size_t)(2 * qp) * EE + dd] = lo;
                g_attn[obase + (size_t)(2 * qp + 1) * EE + dd] = hi;
            }
    }
}

// ---------------------------------------------------------------------------
extern "C" void kernel_launch(void* const* d_in, const int* in_sizes, int n_in,
                              void* d_out, int out_size) {
    const float* x  = (const float*)d_in[0];
    const float* Wq = (const float*)d_in[1];
    const float* bq = (const float*)d_in[2];
    const float* Wk = (const float*)d_in[3];
    const float* bk = (const float*)d_in[4];
    const float* Wv = (const float*)d_in[5];
    const float* bv = (const float*)d_in[6];
    const float* Wo = (const float*)d_in[7];
    const float* bo = (const float*)d_in[8];
    const float* ls = (const float*)d_in[9];

    float *qp, *kp, *vp, *ap;
    cudaGetSymbolAddress((void**)&qp, g_q);
    cudaGetSymbolAddress((void**)&kp, g_k);
    cudaGetSymbolAddress((void**)&vp, g_v);
    cudaGetSymbolAddress((void**)&ap, g_attn);

    const int gsmem = (2 * ASEG + 2 * BSEG) * sizeof(float);  // 98304
    cudaFuncSetAttribute(gemmk<3>, cudaFuncAttributeMaxDynamicSharedMemorySize, gsmem);
    cudaFuncSetAttribute(gemmk<1>, cudaFuncAttributeMaxDynamicSharedMemorySize, gsmem);

    dim3 gqkv(BB * TT / GBM, EE / GBN, 3);  // 128 x 4 x 3
    gemmk<3><<<gqkv, 256, gsmem>>>(x, Wq, bq, qp, Wk, bk, kp, Wv, bv, vp);

    const size_t asmem =
        (size_t)(64 * 64 + 2 * KROWS * 64 + KROWS * PTS + KROWS + 64) * sizeof(float);
    cudaFuncSetAttribute(attn_kernel, cudaFuncAttributeMaxDynamicSharedMemorySize,
                         (int)asmem);
    attn_kernel<<<dim3(TT / QT, HH, BB), 512, asmem>>>(ls);

    dim3 go(BB * TT / GBM, EE / GBN);  // 128 x 4
    gemmk<1><<<go, 256, gsmem>>>(ap, Wo, bo, (float*)d_out,
                                 nullptr, nullptr, nullptr, nullptr, nullptr, nullptr);
}

// round 9
// speedup vs baseline: 1.6395x; 1.0814x over previous
#include <cuda_runtime.h>
#include <math.h>

#define BB 4
#define HH 8
#define TT 2048
#define DD 64
#define EE 512
#define TOPKK 96
#define KR 160   // key rows per 32-query tile (window 128 + 32)

typedef unsigned long long ull;

// Scratch (device globals; no allocation allowed)
__device__ float g_q[(size_t)BB * HH * TT * DD];
__device__ float g_k[(size_t)BB * HH * TT * DD];
__device__ float g_v[(size_t)BB * HH * TT * DD];
__device__ float g_attn[(size_t)BB * TT * EE];

__device__ __forceinline__ ull fma2(ull a, ull b, ull c) {
    ull d;
    asm("fma.rn.f32x2 %0, %1, %2, %3;" : "=l"(d) : "l"(a), "l"(b), "l"(c));
    return d;
}
__device__ __forceinline__ ull pack2(float x) {
    ull d;
    asm("mov.b64 %0, {%1, %1};" : "=l"(d) : "f"(x));
    return d;
}
__device__ __forceinline__ float sum2(ull v) {
    float lo, hi;
    asm("mov.b64 {%0, %1}, %2;" : "=f"(lo), "=f"(hi) : "l"(v));
    return lo + hi;
}
__device__ __forceinline__ unsigned f2ord(float f) {
    unsigned u = __float_as_uint(f);
    return (u & 0x80000000u) ? ~u : (u | 0x80000000u);
}
__device__ __forceinline__ float ord2f(unsigned k) {
    unsigned u = (k & 0x80000000u) ? (k & 0x7fffffffu) : ~k;
    return __uint_as_float(u);
}
__device__ __forceinline__ unsigned s2u(const void* p) {
    return (unsigned)__cvta_generic_to_shared(p);
}
__device__ __forceinline__ unsigned tf32rna(float f) {
    unsigned u;
    asm("cvt.rna.tf32.f32 %0, %1;" : "=r"(u) : "f"(f));
    return u;
}
__device__ __forceinline__ void ldsm4(unsigned& r0, unsigned& r1, unsigned& r2,
                                      unsigned& r3, unsigned addr) {
    asm volatile("ldmatrix.sync.aligned.m8n8.x4.shared.b16 {%0,%1,%2,%3}, [%4];"
                 : "=r"(r0), "=r"(r1), "=r"(r2), "=r"(r3) : "r"(addr));
}
__device__ __forceinline__ void mma_tf32(float& c0, float& c1, float& c2, float& c3,
                                         unsigned a0, unsigned a1, unsigned a2,
                                         unsigned a3, unsigned b0, unsigned b1) {
    asm volatile(
        "mma.sync.aligned.m16n8k8.row.col.f32.tf32.tf32.f32 "
        "{%0,%1,%2,%3}, {%4,%5,%6,%7}, {%8,%9}, {%0,%1,%2,%3};"
        : "+f"(c0), "+f"(c1), "+f"(c2), "+f"(c3)
        : "r"(a0), "r"(a1), "r"(a2), "r"(a3), "r"(b0), "r"(b1));
}
__device__ __forceinline__ void split1(unsigned raw, unsigned& h, unsigned& l) {
    float v = __uint_as_float(raw);
    h = tf32rna(v);
    l = tf32rna(v - __uint_as_float(h));
}

// ---------------------------------------------------------------------------
// 3xTF32 tensor-core GEMM, hi/lo split IN REGISTERS (halves LDSM + smem).
// Raw fp32 tiles in smem; ldmatrix once per fragment; split post-load.
// CTA tile 64(m) x 128(n) x 32(k), 256 threads = 8 warps (2m x 4n),
// warp tile 32x32. XOR-swizzled smem (chunk pos = c ^ (row&7)).
// ---------------------------------------------------------------------------
#define GBM 64
#define GBN 128
#define GBK 32
#define ABUF (GBM * GBK)
#define BBUF (GBN * GBK)

template <int NOUT>
__global__ __launch_bounds__(256, 2) void gemmk(
    const float* __restrict__ X,
    const float* __restrict__ W0, const float* __restrict__ bias0, float* __restrict__ Y0,
    const float* __restrict__ W1, const float* __restrict__ bias1, float* __restrict__ Y1,
    const float* __restrict__ W2, const float* __restrict__ bias2, float* __restrict__ Y2) {
    extern __shared__ float smg[];
    float* sA = smg;                  // [2][64*32]
    float* sB = smg + 2 * ABUF;       // [2][128*32]

    const float* W;
    const float* bias;
    float* Y;
    if (NOUT == 3) {
        int z = blockIdx.z;
        W = (z == 0) ? W0 : (z == 1) ? W1 : W2;
        bias = (z == 0) ? bias0 : (z == 1) ? bias1 : bias2;
        Y = (z == 0) ? Y0 : (z == 1) ? Y1 : Y2;
    } else {
        W = W0; bias = bias0; Y = Y0;
    }

    const int m0 = blockIdx.x * GBM;
    const int n0 = blockIdx.y * GBN;
    const int tid = threadIdx.x;
    const int wid = tid >> 5;
    const int lane = tid & 31;
    const int wm = (wid & 1) * 32;
    const int wn = (wid >> 1) * 32;

    // staging load mapping
    const int arow = tid >> 2, acb = (tid & 3) * 2;
    const int brow = tid >> 1, bcb = (tid & 1) * 4;
    const float* Agp = X + (size_t)(m0 + arow) * EE + acb * 4;
    const float* Bgp = W + (size_t)(n0 + brow) * EE + bcb * 4;
    int aoffs[2], boffs[4];
#pragma unroll
    for (int u = 0; u < 2; u++) aoffs[u] = arow * GBK + (((acb + u) ^ (arow & 7)) << 2);
#pragma unroll
    for (int u = 0; u < 4; u++) boffs[u] = brow * GBK + (((bcb + u) ^ (brow & 7)) << 2);

    // fragment ldmatrix lane addressing
    const int a_m = (lane & 7) + ((lane >> 3) & 1) * 8;
    const int a_kh = lane >> 4;
    const int aoff = a_kh ^ (lane & 7);
    const int b_n = (lane & 7) + (lane >> 4) * 8;
    const int b_kh = (lane >> 3) & 1;
    const int boff = b_kh ^ (lane & 7);
    unsigned aBase[2], bBase[2];
#pragma unroll
    for (int mt = 0; mt < 2; mt++)
        aBase[mt] = s2u(sA) + (unsigned)(wm + mt * 16 + a_m) * (GBK * 4);
#pragma unroll
    for (int p = 0; p < 2; p++)
        bBase[p] = s2u(sB) + (unsigned)(wn + p * 16 + b_n) * (GBK * 4);

    float4 ra[2], rb[4];
    auto ldg = [&](int t) {
#pragma unroll
        for (int u = 0; u < 2; u++) ra[u] = *(const float4*)(Agp + t * GBK + u * 4);
#pragma unroll
        for (int u = 0; u < 4; u++) rb[u] = *(const float4*)(Bgp + t * GBK + u * 4);
    };
    auto sts = [&](int buf) {
        float* Ab = sA + buf * ABUF;
        float* Bb = sB + buf * BBUF;
#pragma unroll
        for (int u = 0; u < 2; u++) *(float4*)&Ab[aoffs[u]] = ra[u];
#pragma unroll
        for (int u = 0; u < 4; u++) *(float4*)&Bb[boffs[u]] = rb[u];
    };

    float c[2][4][4];
#pragma unroll
    for (int mt = 0; mt < 2; mt++)
#pragma unroll
        for (int nt = 0; nt < 4; nt++)
#pragma unroll
            for (int r = 0; r < 4; r++) c[mt][nt][r] = 0.f;

    ldg(0);
    sts(0);
    __syncthreads();

    const int NT = EE / GBK;  // 16
    for (int t = 0; t < NT; t++) {
        if (t + 1 < NT) ldg(t + 1);
        const unsigned abuf = (unsigned)(t & 1) * (ABUF * 4);
        const unsigned bbuf = (unsigned)(t & 1) * (BBUF * 4);
#pragma unroll
        for (int ks = 0; ks < 4; ks++) {
            unsigned ah[2][4], al[2][4], bh[4][2], bl[4][2];
#pragma unroll
            for (int mt = 0; mt < 2; mt++) {
                unsigned r0, r1, r2, r3;
                ldsm4(r0, r1, r2, r3,
                      aBase[mt] + abuf + (unsigned)(((2 * ks) ^ aoff) << 4));
                split1(r0, ah[mt][0], al[mt][0]);
                split1(r1, ah[mt][1], al[mt][1]);
                split1(r2, ah[mt][2], al[mt][2]);
                split1(r3, ah[mt][3], al[mt][3]);
            }
#pragma unroll
            for (int p = 0; p < 2; p++) {
                unsigned r0, r1, r2, r3;
                ldsm4(r0, r1, r2, r3,
                      bBase[p] + bbuf + (unsigned)(((2 * ks) ^ boff) << 4));
                split1(r0, bh[2 * p][0], bl[2 * p][0]);
                split1(r1, bh[2 * p][1], bl[2 * p][1]);
                split1(r2, bh[2 * p + 1][0], bl[2 * p + 1][0]);
                split1(r3, bh[2 * p + 1][1], bl[2 * p + 1][1]);
            }
#pragma unroll
            for (int mt = 0; mt < 2; mt++)
#pragma unroll
                for (int nt = 0; nt < 4; nt++)
                    mma_tf32(c[mt][nt][0], c[mt][nt][1], c[mt][nt][2], c[mt][nt][3],
                             ah[mt][0], ah[mt][1], ah[mt][2], ah[mt][3],
                             bh[nt][0], bh[nt][1]);
#pragma unroll
            for (int mt = 0; mt < 2; mt++)
#pragma unroll
                for (int nt = 0; nt < 4; nt++)
                    mma_tf32(c[mt][nt][0], c[mt][nt][1], c[mt][nt][2], c[mt][nt][3],
                             ah[mt][0], ah[mt][1], ah[mt][2], ah[mt][3],
                             bl[nt][0], bl[nt][1]);
#pragma unroll
            for (int mt = 0; mt < 2; mt++)
#pragma unroll
                for (int nt = 0; nt < 4; nt++)
                    mma_tf32(c[mt][nt][0], c[mt][nt][1], c[mt][nt][2], c[mt][nt][3],
                             al[mt][0], al[mt][1], al[mt][2], al[mt][3],
                             bh[nt][0], bh[nt][1]);
        }
        __syncthreads();
        if (t + 1 < NT) {
            sts((t + 1) & 1);
            __syncthreads();
        }
    }

    // epilogue
    const int g = lane >> 2;
    const int tc = lane & 3;
#pragma unroll
    for (int mt = 0; mt < 2; mt++)
#pragma unroll
        for (int nt = 0; nt < 4; nt++) {
            int col = n0 + wn + nt * 8 + tc * 2;
            float2 bbv = *(const float2*)&bias[col];
            float2 v0 = make_float2(c[mt][nt][0] + bbv.x, c[mt][nt][1] + bbv.y);
            float2 v1 = make_float2(c[mt][nt][2] + bbv.x, c[mt][nt][3] + bbv.y);
            int row = m0 + wm + mt * 16 + g;
            if (NOUT == 3) {
                int h = col >> 6, d = col & 63;
                int bi = row >> 11, tt0 = row & 2047;
                float* base = Y + (((size_t)bi * HH + h) * TT) * DD + d;
                *(float2*)&base[(size_t)tt0 * DD] = v0;
                *(float2*)&base[(size_t)(tt0 + 8) * DD] = v1;
            } else {
                *(float2*)&Y[(size_t)row * EE + col] = v0;
                *(float2*)&Y[(size_t)(row + 8) * EE + col] = v1;
            }
        }
}

// ---------------------------------------------------------------------------
// Attention v2: block per (q-tile of 32, h, b). 512 threads = 16 warps,
// 2 CTAs/SM (smem ~111KB). Warp handles 2 queries; lane owns relative key
// slots r = qi+1+l+32t (t=0..3) == the exact 128-key causal window.
// Top-k + softmax interleaved across the 2 queries (independent REDUX/shfl
// chains). Scores kept as order-preserving uints; recovered via ord2f.
// P stored sP[query][row] (stores consecutive -> conflict-free, PV loads
// broadcast). PV: thread = (query, 4-dim group), V via natural LDS.128.
// ---------------------------------------------------------------------------
__device__ __forceinline__ int aswz(int r, int c) {  // float offset, 64-f rows
    return (r << 6) + ((c ^ (r & 7)) << 2);
}

__global__ __launch_bounds__(512, 2) void attn_kernel(const float* __restrict__ log_sigma) {
    extern __shared__ float sm[];
    float* sQ = sm;                 // 32  x 64 (swizzled)
    float* sK = sQ + 32 * 64;       // 160 x 64 (swizzled)
    float* sV = sK + KR * 64;       // 160 x 64 (swizzled)
    float* sP = sV + KR * 64;       // 32 x 160 ([query][row])
    float* sKsq = sP + 32 * KR;     // 160
    float* sQsq = sKsq + KR;        // 32

    const int q0 = blockIdx.x * 32;
    const int h = blockIdx.y;
    const int b = blockIdx.z;
    const int tid = threadIdx.x;

    const float* Qg = g_q + ((size_t)(b * HH + h) * TT) * DD;
    const float* Kg = g_k + ((size_t)(b * HH + h) * TT) * DD;
    const float* Vg = g_v + ((size_t)(b * HH + h) * TT) * DD;
    const float scale = -0.5f * expf(-2.f * log_sigma[h]);

    // ---- load tiles + zero sP ----
    {
        int r = tid >> 4, c = tid & 15;
        *(float4*)&sQ[aswz(r, c)] =
            *(const float4*)&Qg[(size_t)(q0 + r) * DD + c * 4];
    }
    const float4 z4 = make_float4(0.f, 0.f, 0.f, 0.f);
    for (int i = tid; i < KR * 16; i += 512) {
        int r = i >> 4, c = i & 15;
        int gk = q0 - 128 + r;
        float4 kv = z4, vv = z4;
        if (gk >= 0) {
            kv = *(const float4*)&Kg[(size_t)gk * DD + c * 4];
            vv = *(const float4*)&Vg[(size_t)gk * DD + c * 4];
        }
        *(float4*)&sK[aswz(r, c)] = kv;
        *(float4*)&sV[aswz(r, c)] = vv;
    }
#pragma unroll
    for (int i = 0; i < 10; i++) sP[tid + i * 512] = 0.f;
    __syncthreads();

    // ---- row norms ----
    if (tid < KR + 32) {
        int rr = (tid < KR) ? tid : (tid - KR);
        const float* base = (tid < KR) ? sK : sQ;
        ull acc = 0ull;
#pragma unroll
        for (int c = 0; c < 16; c++) {
            ulonglong2 v = *(const ulonglong2*)&base[aswz(rr, c)];
            acc = fma2(v.x, v.x, acc);
            acc = fma2(v.y, v.y, acc);
        }
        float s = sum2(acc);
        if (tid < KR) sKsq[tid] = s;
        else sQsq[tid - KR] = s;
    }
    __syncthreads();

    // ---- scores: warp per 2 queries; lane owns r = qi+1+l+32t ----
    const int w = tid >> 5, l = tid & 31;
    const int qA = 2 * w, qB = 2 * w + 1;
    const int r0A = qA + 1 + l, r0B = qB + 1 + l;

    ull acc2[2][4];
#pragma unroll
    for (int q = 0; q < 2; q++)
#pragma unroll
        for (int t = 0; t < 4; t++) acc2[q][t] = 0ull;

    {
        const int rkA = r0A & 7, rkB = r0B & 7;
        const int qkA = qA & 7, qkB = qB & 7;
#pragma unroll 4
        for (int c = 0; c < 16; c++) {
            ulonglong2 qvA = *(const ulonglong2*)&sQ[(qA << 6) + ((c ^ qkA) << 2)];
            ulonglong2 qvB = *(const ulonglong2*)&sQ[(qB << 6) + ((c ^ qkB) << 2)];
            const int cA = (c ^ rkA) << 2, cB = (c ^ rkB) << 2;
#pragma unroll
            for (int t = 0; t < 4; t++) {
                ulonglong2 kvA = *(const ulonglong2*)&sK[((r0A + 32 * t) << 6) + cA];
                acc2[0][t] = fma2(qvA.x, kvA.x, acc2[0][t]);
                acc2[0][t] = fma2(qvA.y, kvA.y, acc2[0][t]);
                ulonglong2 kvB = *(const ulonglong2*)&sK[((r0B + 32 * t) << 6) + cB];
                acc2[1][t] = fma2(qvB.x, kvB.x, acc2[1][t]);
                acc2[1][t] = fma2(qvB.y, kvB.y, acc2[1][t]);
            }
        }
    }

    // ---- keys (order-preserving uints; 0 = invalid) ----
    unsigned key[2][4];
#pragma unroll
    for (int q = 0; q < 2; q++) {
        const int qi = (q == 0) ? qA : qB;
        const int r0 = (q == 0) ? r0A : r0B;
        const float qs = sQsq[qi];
#pragma unroll
        for (int t = 0; t < 4; t++) {
            int r = r0 + 32 * t;
            float dot = sum2(acc2[q][t]);
            float dist = qs + sKsq[r] - 2.f * dot;
            float s = dist * scale;
            bool valid = (q0 - 128 + r) >= 0;
            key[q][t] = valid ? f2ord(s) : 0u;
        }
    }

    // ---- exact top-96 thresholds, 2 queries interleaved ----
    unsigned thr[2] = {0u, 0u};
#pragma unroll 1
    for (int bp = 30; bp >= 0; bp -= 2) {
        unsigned pk[2];
#pragma unroll
        for (int q = 0; q < 2; q++) {
            unsigned c1 = thr[q] | (1u << bp);
            unsigned c2 = thr[q] | (2u << bp);
            unsigned c3 = thr[q] | (3u << bp);
            unsigned p = 0;
#pragma unroll
            for (int t = 0; t < 4; t++) {
                p += (key[q][t] >= c1 ? 1u : 0u);
                p += (key[q][t] >= c2 ? 0x100u : 0u);
                p += (key[q][t] >= c3 ? 0x10000u : 0u);
            }
            pk[q] = p;
        }
        pk[0] = __reduce_add_sync(0xffffffffu, pk[0]);
        pk[1] = __reduce_add_sync(0xffffffffu, pk[1]);
#pragma unroll
        for (int q = 0; q < 2; q++) {
            if ((pk[q] >> 16) >= TOPKK) thr[q] |= (3u << bp);
            else if (((pk[q] >> 8) & 0xffu) >= TOPKK) thr[q] |= (2u << bp);
            else if ((pk[q] & 0xffu) >= TOPKK) thr[q] |= (1u << bp);
        }
    }

    // ---- softmax (max via reduce_max on ordered keys), interleaved ----
    unsigned km[2][4];
    unsigned mx[2] = {0u, 0u};
#pragma unroll
    for (int q = 0; q < 2; q++)
#pragma unroll
        for (int t = 0; t < 4; t++) {
            unsigned k = key[q][t];
            unsigned kk = (k >= thr[q]) ? k : 0u;
            km[q][t] = kk;
            mx[q] = max(mx[q], kk);
        }
    mx[0] = __reduce_max_sync(0xffffffffu, mx[0]);
    mx[1] = __reduce_max_sync(0xffffffffu, mx[1]);
    float mv[2] = {ord2f(mx[0]), ord2f(mx[1])};

    float e[2][4];
    float esum[2] = {0.f, 0.f};
#pragma unroll
    for (int q = 0; q < 2; q++)
#pragma unroll
        for (int t = 0; t < 4; t++) {
            float v = (km[q][t] != 0u) ? __expf(ord2f(km[q][t]) - mv[q]) : 0.f;
            e[q][t] = v;
            esum[q] += v;
        }
#pragma unroll
    for (int o = 16; o > 0; o >>= 1) {
        esum[0] += __shfl_xor_sync(0xffffffffu, esum[0], o);
        esum[1] += __shfl_xor_sync(0xffffffffu, esum[1], o);
    }
    float inv0 = 1.f / esum[0];
    float inv1 = 1.f / esum[1];
#pragma unroll
    for (int t = 0; t < 4; t++) {
        sP[qA * KR + r0A + 32 * t] = e[0][t] * inv0;
        sP[qB * KR + r0B + 32 * t] = e[1][t] * inv1;
    }
    __syncthreads();

    // ---- PV: thread = (query qi, 4-dim group dp) ----
    {
        const int qi = tid >> 4;
        const int dp = tid & 15;
        ull a0 = 0ull, a1 = 0ull;
        const float* prow = &sP[qi * KR];
#pragma unroll 4
        for (int jj = 0; jj < 128; jj++) {
            int r = qi + 1 + jj;
            ull p2 = pack2(prow[r]);
            ulonglong2 v2 = *(const ulonglong2*)&sV[(r << 6) + ((dp ^ (r & 7)) << 2)];
            a0 = fma2(p2, v2.x, a0);
            a1 = fma2(p2, v2.y, a1);
        }
        ulonglong2 outv;
        outv.x = a0;
        outv.y = a1;
        *(ulonglong2*)&g_attn[((size_t)b * TT + q0 + qi) * EE + h * DD + 4 * dp] = outv;
    }
}

// ---------------------------------------------------------------------------
extern "C" void kernel_launch(void* const* d_in, const int* in_sizes, int n_in,
                              void* d_out, int out_size) {
    const float* x  = (const float*)d_in[0];
    const float* Wq = (const float*)d_in[1];
    const float* bq = (const float*)d_in[2];
    const float* Wk = (const float*)d_in[3];
    const float* bk = (const float*)d_in[4];
    const float* Wv = (const float*)d_in[5];
    const float* bv = (const float*)d_in[6];
    const float* Wo = (const float*)d_in[7];
    const float* bo = (const float*)d_in[8];
    const float* ls = (const float*)d_in[9];

    float *qp, *kp, *vp, *ap;
    cudaGetSymbolAddress((void**)&qp, g_q);
    cudaGetSymbolAddress((void**)&kp, g_k);
    cudaGetSymbolAddress((void**)&vp, g_v);
    cudaGetSymbolAddress((void**)&ap, g_attn);

    const int gsmem = 2 * (ABUF + BBUF) * sizeof(float);  // 49152
    cudaFuncSetAttribute(gemmk<3>, cudaFuncAttributeMaxDynamicSharedMemorySize, gsmem);
    cudaFuncSetAttribute(gemmk<1>, cudaFuncAttributeMaxDynamicSharedMemorySize, gsmem);

    dim3 gqkv(BB * TT / GBM, EE / GBN, 3);  // 128 x 4 x 3
    gemmk<3><<<gqkv, 256, gsmem>>>(x, Wq, bq, qp, Wk, bk, kp, Wv, bv, vp);

    const size_t asmem =
        (size_t)(32 * 64 + 2 * KR * 64 + 32 * KR + KR + 32) * sizeof(float);  // ~111KB
    cudaFuncSetAttribute(attn_kernel, cudaFuncAttributeMaxDynamicSharedMemorySize,
                         (int)asmem);
    attn_kernel<<<dim3(TT / 32, HH, BB), 512, asmem>>>(ls);

    dim3 go(BB * TT / GBM, EE / GBN);  // 128 x 4
    gemmk<1><<<go, 256, gsmem>>>(ap, Wo, bo, (float*)d_out,
                                 nullptr, nullptr, nullptr, nullptr, nullptr, nullptr);
}

// round 10
// speedup vs baseline: 2.0541x; 1.2529x over previous
#include <cuda_runtime.h>
#include <cuda_fp16.h>
#include <math.h>

#define BB 4
#define HH 8
#define TT 2048
#define DD 64
#define EE 512
#define TOPKK 96
#define KR 160   // key rows per 32-query tile (window 128 + 32)

typedef unsigned long long ull;

// Scratch (device globals; no allocation allowed)
__device__ float g_q[(size_t)BB * HH * TT * DD];
__device__ float g_k[(size_t)BB * HH * TT * DD];
__device__ float g_v[(size_t)BB * HH * TT * DD];
__device__ float g_attn[(size_t)BB * TT * EE];

__device__ __forceinline__ ull fma2(ull a, ull b, ull c) {
    ull d;
    asm("fma.rn.f32x2 %0, %1, %2, %3;" : "=l"(d) : "l"(a), "l"(b), "l"(c));
    return d;
}
__device__ __forceinline__ ull pack2(float x) {
    ull d;
    asm("mov.b64 %0, {%1, %1};" : "=l"(d) : "f"(x));
    return d;
}
__device__ __forceinline__ float sum2(ull v) {
    float lo, hi;
    asm("mov.b64 {%0, %1}, %2;" : "=f"(lo), "=f"(hi) : "l"(v));
    return lo + hi;
}
__device__ __forceinline__ unsigned f2ord(float f) {
    unsigned u = __float_as_uint(f);
    return (u & 0x80000000u) ? ~u : (u | 0x80000000u);
}
__device__ __forceinline__ float ord2f(unsigned k) {
    unsigned u = (k & 0x80000000u) ? (k & 0x7fffffffu) : ~k;
    return __uint_as_float(u);
}
__device__ __forceinline__ unsigned s2u(const void* p) {
    return (unsigned)__cvta_generic_to_shared(p);
}
__device__ __forceinline__ void ldsm4(unsigned& r0, unsigned& r1, unsigned& r2,
                                      unsigned& r3, unsigned addr) {
    asm volatile("ldmatrix.sync.aligned.m8n8.x4.shared.b16 {%0,%1,%2,%3}, [%4];"
                 : "=r"(r0), "=r"(r1), "=r"(r2), "=r"(r3) : "r"(addr));
}
__device__ __forceinline__ void mma_f16(float& c0, float& c1, float& c2, float& c3,
                                        unsigned a0, unsigned a1, unsigned a2,
                                        unsigned a3, unsigned b0, unsigned b1) {
    asm volatile(
        "mma.sync.aligned.m16n8k16.row.col.f32.f16.f16.f32 "
        "{%0,%1,%2,%3}, {%4,%5,%6,%7}, {%8,%9}, {%0,%1,%2,%3};"
        : "+f"(c0), "+f"(c1), "+f"(c2), "+f"(c3)
        : "r"(a0), "r"(a1), "r"(a2), "r"(a3), "r"(b0), "r"(b1));
}
// split 2 floats -> hi half2 + lo half2 (x = hi + lo, 22-bit effective mantissa)
__device__ __forceinline__ void split2(float x, float y, unsigned& h, unsigned& l) {
    __half2 h2 = __float22half2_rn(make_float2(x, y));
    float2 hf = __half22float2(h2);
    __half2 l2 = __float22half2_rn(make_float2(x - hf.x, y - hf.y));
    h = *(unsigned*)&h2;
    l = *(unsigned*)&l2;
}

// ---------------------------------------------------------------------------
// 3xFP16 tensor-core GEMM: Y = X @ W^T + bias.
// x = hi + lo (fp16 each; 22-bit pair);  D = Ah Bh + Ah Bl + Al Bh.
// CTA tile 64(m) x 128(n) x 32(k), 256 threads = 8 warps (2m x 4n), warp
// tile 32x32, mma m16n8k16. hi/lo stored as SEPARATE f16 tiles (total smem
// = raw fp32 size). Rows = 32 f16 = 64B, 16B chunks swizzled
// chunk' = c ^ ((row>>1)&3)  -> STS and ldmatrix conflict-free.
// Split done once at the LDG->STS stage (no per-fragment ALU).
// ---------------------------------------------------------------------------
#define GBM 64
#define GBN 128
#define GBK 32
// byte offsets within smem (halves layout)
#define AHI_OFF 0
#define ALO_OFF 8192          // A hi: 2 bufs x 4096B
#define BHI_OFF 16384         // B hi: 2 bufs x 8192B
#define BLO_OFF 32768
#define SMEM_GEMM 49152
#define ABUFB 4096            // per-buffer bytes (A)
#define BBUFB 8192

template <int NOUT>
__global__ __launch_bounds__(256, 2) void gemmk(
    const float* __restrict__ X,
    const float* __restrict__ W0, const float* __restrict__ bias0, float* __restrict__ Y0,
    const float* __restrict__ W1, const float* __restrict__ bias1, float* __restrict__ Y1,
    const float* __restrict__ W2, const float* __restrict__ bias2, float* __restrict__ Y2) {
    extern __shared__ char smg[];
    const unsigned sbase = s2u(smg);

    const float* W;
    const float* bias;
    float* Y;
    if (NOUT == 3) {
        int z = blockIdx.z;
        W = (z == 0) ? W0 : (z == 1) ? W1 : W2;
        bias = (z == 0) ? bias0 : (z == 1) ? bias1 : bias2;
        Y = (z == 0) ? Y0 : (z == 1) ? Y1 : Y2;
    } else {
        W = W0; bias = bias0; Y = Y0;
    }

    const int m0 = blockIdx.x * GBM;
    const int n0 = blockIdx.y * GBN;
    const int tid = threadIdx.x;
    const int wid = tid >> 5;
    const int lane = tid & 31;
    const int wm = (wid & 1) * 32;
    const int wn = (wid >> 1) * 32;

    // ---- staging mapping ----
    const int arow = tid >> 2, ac = tid & 3;          // A: 1 chunk (8 floats)
    const int brow = tid >> 1, bc2 = (tid & 1) * 2;   // B: 2 chunks (16 floats)
    const float* Agp = X + (size_t)(m0 + arow) * EE + ac * 8;
    const float* Bgp = W + (size_t)(n0 + brow) * EE + bc2 * 8;
    // STS half-offsets (bytes within tile)
    const int aStO = arow * 64 + ((ac ^ ((arow >> 1) & 3)) << 4);
    int bStO[2];
#pragma unroll
    for (int u = 0; u < 2; u++)
        bStO[u] = brow * 64 + (((bc2 + u) ^ ((brow >> 1) & 3)) << 4);

    // ---- fragment ldmatrix lane addressing ----
    const int a_m = (lane & 7) + ((lane >> 3) & 1) * 8;
    const int a_kh = lane >> 4;           // k-half within k16
    const int b_n = (lane & 7) + (lane >> 4) * 8;
    const int b_kh = (lane >> 3) & 1;
    unsigned aRow[2], bRow[2];
    int aSw[2], bSw[2];
#pragma unroll
    for (int mt = 0; mt < 2; mt++) {
        int r = wm + mt * 16 + a_m;
        aRow[mt] = sbase + AHI_OFF + (unsigned)r * 64;
        aSw[mt] = (r >> 1) & 3;
    }
#pragma unroll
    for (int p = 0; p < 2; p++) {
        int r = wn + p * 16 + b_n;
        bRow[p] = sbase + BHI_OFF + (unsigned)r * 64;
        bSw[p] = (r >> 1) & 3;
    }

    float4 ra0, ra1, rb0, rb1, rb2, rb3;
    auto ldg = [&](int t) {
        ra0 = *(const float4*)(Agp + t * GBK);
        ra1 = *(const float4*)(Agp + t * GBK + 4);
        rb0 = *(const float4*)(Bgp + t * GBK);
        rb1 = *(const float4*)(Bgp + t * GBK + 4);
        rb2 = *(const float4*)(Bgp + t * GBK + 8);
        rb3 = *(const float4*)(Bgp + t * GBK + 12);
    };
    auto sts = [&](int buf) {
        char* base = smg;
        {   // A chunk: 8 floats -> 4 half2 hi + 4 half2 lo
            uint4 h, l;
            split2(ra0.x, ra0.y, h.x, l.x);
            split2(ra0.z, ra0.w, h.y, l.y);
            split2(ra1.x, ra1.y, h.z, l.z);
            split2(ra1.z, ra1.w, h.w, l.w);
            *(uint4*)(base + AHI_OFF + buf * ABUFB + aStO) = h;
            *(uint4*)(base + ALO_OFF + buf * ABUFB + aStO) = l;
        }
        {   // B chunk 0
            uint4 h, l;
            split2(rb0.x, rb0.y, h.x, l.x);
            split2(rb0.z, rb0.w, h.y, l.y);
            split2(rb1.x, rb1.y, h.z, l.z);
            split2(rb1.z, rb1.w, h.w, l.w);
            *(uint4*)(base + BHI_OFF + buf * BBUFB + bStO[0]) = h;
            *(uint4*)(base + BLO_OFF + buf * BBUFB + bStO[0]) = l;
        }
        {   // B chunk 1
            uint4 h, l;
            split2(rb2.x, rb2.y, h.x, l.x);
            split2(rb2.z, rb2.w, h.y, l.y);
            split2(rb3.x, rb3.y, h.z, l.z);
            split2(rb3.z, rb3.w, h.w, l.w);
            *(uint4*)(base + BHI_OFF + buf * BBUFB + bStO[1]) = h;
            *(uint4*)(base + BLO_OFF + buf * BBUFB + bStO[1]) = l;
        }
    };

    float c[2][4][4];
#pragma unroll
    for (int mt = 0; mt < 2; mt++)
#pragma unroll
        for (int nt = 0; nt < 4; nt++)
#pragma unroll
            for (int r = 0; r < 4; r++) c[mt][nt][r] = 0.f;

    ldg(0);
    sts(0);
    __syncthreads();

    const int NT = EE / GBK;  // 16
    for (int t = 0; t < NT; t++) {
        if (t + 1 < NT) ldg(t + 1);
        const unsigned abo = (unsigned)(t & 1) * ABUFB;
        const unsigned bbo = (unsigned)(t & 1) * BBUFB;
#pragma unroll
        for (int ks = 0; ks < 2; ks++) {   // two k16 steps per k32 tile
            unsigned ah[2][4], al[2][4], bh[4][2], bl[4][2];
#pragma unroll
            for (int mt = 0; mt < 2; mt++) {
                unsigned ad = aRow[mt] + abo +
                              (unsigned)((((ks << 1) + a_kh) ^ aSw[mt]) << 4);
                ldsm4(ah[mt][0], ah[mt][1], ah[mt][2], ah[mt][3], ad);
                ldsm4(al[mt][0], al[mt][1], al[mt][2], al[mt][3],
                      ad + (ALO_OFF - AHI_OFF));
            }
#pragma unroll
            for (int p = 0; p < 2; p++) {
                unsigned bd = bRow[p] + bbo +
                              (unsigned)((((ks << 1) + b_kh) ^ bSw[p]) << 4);
                ldsm4(bh[2 * p][0], bh[2 * p][1], bh[2 * p + 1][0],
                      bh[2 * p + 1][1], bd);
                ldsm4(bl[2 * p][0], bl[2 * p][1], bl[2 * p + 1][0],
                      bl[2 * p + 1][1], bd + (BLO_OFF - BHI_OFF));
            }
#pragma unroll
            for (int mt = 0; mt < 2; mt++)
#pragma unroll
                for (int nt = 0; nt < 4; nt++)
                    mma_f16(c[mt][nt][0], c[mt][nt][1], c[mt][nt][2], c[mt][nt][3],
                            ah[mt][0], ah[mt][1], ah[mt][2], ah[mt][3],
                            bh[nt][0], bh[nt][1]);
#pragma unroll
            for (int mt = 0; mt < 2; mt++)
#pragma unroll
                for (int nt = 0; nt < 4; nt++)
                    mma_f16(c[mt][nt][0], c[mt][nt][1], c[mt][nt][2], c[mt][nt][3],
                            ah[mt][0], ah[mt][1], ah[mt][2], ah[mt][3],
                            bl[nt][0], bl[nt][1]);
#pragma unroll
            for (int mt = 0; mt < 2; mt++)
#pragma unroll
                for (int nt = 0; nt < 4; nt++)
                    mma_f16(c[mt][nt][0], c[mt][nt][1], c[mt][nt][2], c[mt][nt][3],
                            al[mt][0], al[mt][1], al[mt][2], al[mt][3],
                            bh[nt][0], bh[nt][1]);
        }
        __syncthreads();
        if (t + 1 < NT) {
            sts((t + 1) & 1);
            __syncthreads();
        }
    }

    // epilogue
    const int g = lane >> 2;
    const int tc = lane & 3;
#pragma unroll
    for (int mt = 0; mt < 2; mt++)
#pragma unroll
        for (int nt = 0; nt < 4; nt++) {
            int col = n0 + wn + nt * 8 + tc * 2;
            float2 bbv = *(const float2*)&bias[col];
            float2 v0 = make_float2(c[mt][nt][0] + bbv.x, c[mt][nt][1] + bbv.y);
            float2 v1 = make_float2(c[mt][nt][2] + bbv.x, c[mt][nt][3] + bbv.y);
            int row = m0 + wm + mt * 16 + g;
            if (NOUT == 3) {
                int h = col >> 6, d = col & 63;
                int bi = row >> 11, tt0 = row & 2047;
                float* base = Y + (((size_t)bi * HH + h) * TT) * DD + d;
                *(float2*)&base[(size_t)tt0 * DD] = v0;
                *(float2*)&base[(size_t)(tt0 + 8) * DD] = v1;
            } else {
                *(float2*)&Y[(size_t)row * EE + col] = v0;
                *(float2*)&Y[(size_t)(row + 8) * EE + col] = v1;
            }
        }
}

// ---------------------------------------------------------------------------
// Attention (unchanged from R9 — known passing): block per (q-tile 32, h, b),
// 512 threads, 2 CTAs/SM. Warp = 2 queries; lane owns rows qi+1+l+32t.
// ---------------------------------------------------------------------------
__device__ __forceinline__ int aswz(int r, int c) {
    return (r << 6) + ((c ^ (r & 7)) << 2);
}

__global__ __launch_bounds__(512, 2) void attn_kernel(const float* __restrict__ log_sigma) {
    extern __shared__ float sm[];
    float* sQ = sm;                 // 32  x 64 (swizzled)
    float* sK = sQ + 32 * 64;       // 160 x 64 (swizzled)
    float* sV = sK + KR * 64;       // 160 x 64 (swizzled)
    float* sP = sV + KR * 64;       // 32 x 160 ([query][row])
    float* sKsq = sP + 32 * KR;     // 160
    float* sQsq = sKsq + KR;        // 32

    const int q0 = blockIdx.x * 32;
    const int h = blockIdx.y;
    const int b = blockIdx.z;
    const int tid = threadIdx.x;

    const float* Qg = g_q + ((size_t)(b * HH + h) * TT) * DD;
    const float* Kg = g_k + ((size_t)(b * HH + h) * TT) * DD;
    const float* Vg = g_v + ((size_t)(b * HH + h) * TT) * DD;
    const float scale = -0.5f * expf(-2.f * log_sigma[h]);

    {
        int r = tid >> 4, c = tid & 15;
        *(float4*)&sQ[aswz(r, c)] =
            *(const float4*)&Qg[(size_t)(q0 + r) * DD + c * 4];
    }
    const float4 z4 = make_float4(0.f, 0.f, 0.f, 0.f);
    for (int i = tid; i < KR * 16; i += 512) {
        int r = i >> 4, c = i & 15;
        int gk = q0 - 128 + r;
        float4 kv = z4, vv = z4;
        if (gk >= 0) {
            kv = *(const float4*)&Kg[(size_t)gk * DD + c * 4];
            vv = *(const float4*)&Vg[(size_t)gk * DD + c * 4];
        }
        *(float4*)&sK[aswz(r, c)] = kv;
        *(float4*)&sV[aswz(r, c)] = vv;
    }
#pragma unroll
    for (int i = 0; i < 10; i++) sP[tid + i * 512] = 0.f;
    __syncthreads();

    if (tid < KR + 32) {
        int rr = (tid < KR) ? tid : (tid - KR);
        const float* base = (tid < KR) ? sK : sQ;
        ull acc = 0ull;
#pragma unroll
        for (int c = 0; c < 16; c++) {
            ulonglong2 v = *(const ulonglong2*)&base[aswz(rr, c)];
            acc = fma2(v.x, v.x, acc);
            acc = fma2(v.y, v.y, acc);
        }
        float s = sum2(acc);
        if (tid < KR) sKsq[tid] = s;
        else sQsq[tid - KR] = s;
    }
    __syncthreads();

    const int w = tid >> 5, l = tid & 31;
    const int qA = 2 * w, qB = 2 * w + 1;
    const int r0A = qA + 1 + l, r0B = qB + 1 + l;

    ull acc2[2][4];
#pragma unroll
    for (int q = 0; q < 2; q++)
#pragma unroll
        for (int t = 0; t < 4; t++) acc2[q][t] = 0ull;

    {
        const int rkA = r0A & 7, rkB = r0B & 7;
        const int qkA = qA & 7, qkB = qB & 7;
#pragma unroll 4
        for (int c = 0; c < 16; c++) {
            ulonglong2 qvA = *(const ulonglong2*)&sQ[(qA << 6) + ((c ^ qkA) << 2)];
            ulonglong2 qvB = *(const ulonglong2*)&sQ[(qB << 6) + ((c ^ qkB) << 2)];
            const int cA = (c ^ rkA) << 2, cB = (c ^ rkB) << 2;
#pragma unroll
            for (int t = 0; t < 4; t++) {
                ulonglong2 kvA = *(const ulonglong2*)&sK[((r0A + 32 * t) << 6) + cA];
                acc2[0][t] = fma2(qvA.x, kvA.x, acc2[0][t]);
                acc2[0][t] = fma2(qvA.y, kvA.y, acc2[0][t]);
                ulonglong2 kvB = *(const ulonglong2*)&sK[((r0B + 32 * t) << 6) + cB];
                acc2[1][t] = fma2(qvB.x, kvB.x, acc2[1][t]);
                acc2[1][t] = fma2(qvB.y, kvB.y, acc2[1][t]);
            }
        }
    }

    unsigned key[2][4];
#pragma unroll
    for (int q = 0; q < 2; q++) {
        const int qi = (q == 0) ? qA : qB;
        const int r0 = (q == 0) ? r0A : r0B;
        const float qs = sQsq[qi];
#pragma unroll
        for (int t = 0; t < 4; t++) {
            int r = r0 + 32 * t;
            float dot = sum2(acc2[q][t]);
            float dist = qs + sKsq[r] - 2.f * dot;
            float s = dist * scale;
            bool valid = (q0 - 128 + r) >= 0;
            key[q][t] = valid ? f2ord(s) : 0u;
        }
    }

    unsigned thr[2] = {0u, 0u};
#pragma unroll 1
    for (int bp = 30; bp >= 0; bp -= 2) {
        unsigned pk[2];
#pragma unroll
        for (int q = 0; q < 2; q++) {
            unsigned c1 = thr[q] | (1u << bp);
            unsigned c2 = thr[q] | (2u << bp);
            unsigned c3 = thr[q] | (3u << bp);
            unsigned p = 0;
#pragma unroll
            for (int t = 0; t < 4; t++) {
                p += (key[q][t] >= c1 ? 1u : 0u);
                p += (key[q][t] >= c2 ? 0x100u : 0u);
                p += (key[q][t] >= c3 ? 0x10000u : 0u);
            }
            pk[q] = p;
        }
        pk[0] = __reduce_add_sync(0xffffffffu, pk[0]);
        pk[1] = __reduce_add_sync(0xffffffffu, pk[1]);
#pragma unroll
        for (int q = 0; q < 2; q++) {
            if ((pk[q] >> 16) >= TOPKK) thr[q] |= (3u << bp);
            else if (((pk[q] >> 8) & 0xffu) >= TOPKK) thr[q] |= (2u << bp);
            else if ((pk[q] & 0xffu) >= TOPKK) thr[q] |= (1u << bp);
        }
    }

    unsigned km[2][4];
    unsigned mx[2] = {0u, 0u};
#pragma unroll
    for (int q = 0; q < 2; q++)
#pragma unroll
        for (int t = 0; t < 4; t++) {
            unsigned k = key[q][t];
            unsigned kk = (k >= thr[q]) ? k : 0u;
            km[q][t] = kk;
            mx[q] = max(mx[q], kk);
        }
    mx[0] = __reduce_max_sync(0xffffffffu, mx[0]);
    mx[1] = __reduce_max_sync(0xffffffffu, mx[1]);
    float mv[2] = {ord2f(mx[0]), ord2f(mx[1])};

    float e[2][4];
    float esum[2] = {0.f, 0.f};
#pragma unroll
    for (int q = 0; q < 2; q++)
#pragma unroll
        for (int t = 0; t < 4; t++) {
            float v = (km[q][t] != 0u) ? __expf(ord2f(km[q][t]) - mv[q]) : 0.f;
            e[q][t] = v;
            esum[q] += v;
        }
#pragma unroll
    for (int o = 16; o > 0; o >>= 1) {
        esum[0] += __shfl_xor_sync(0xffffffffu, esum[0], o);
        esum[1] += __shfl_xor_sync(0xffffffffu, esum[1], o);
    }
    float inv0 = 1.f / esum[0];
    float inv1 = 1.f / esum[1];
#pragma unroll
    for (int t = 0; t < 4; t++) {
        sP[qA * KR + r0A + 32 * t] = e[0][t] * inv0;
        sP[qB * KR + r0B + 32 * t] = e[1][t] * inv1;
    }
    __syncthreads();

    {
        const int qi = tid >> 4;
        const int dp = tid & 15;
        ull a0 = 0ull, a1 = 0ull;
        const float* prow = &sP[qi * KR];
#pragma unroll 4
        for (int jj = 0; jj < 128; jj++) {
            int r = qi + 1 + jj;
            ull p2 = pack2(prow[r]);
            ulonglong2 v2 = *(const ulonglong2*)&sV[(r << 6) + ((dp ^ (r & 7)) << 2)];
            a0 = fma2(p2, v2.x, a0);
            a1 = fma2(p2, v2.y, a1);
        }
        ulonglong2 outv;
        outv.x = a0;
        outv.y = a1;
        *(ulonglong2*)&g_attn[((size_t)b * TT + q0 + qi) * EE + h * DD + 4 * dp] = outv;
    }
}

// ---------------------------------------------------------------------------
extern "C" void kernel_launch(void* const* d_in, const int* in_sizes, int n_in,
                              void* d_out, int out_size) {
    const float* x  = (const float*)d_in[0];
    const float* Wq = (const float*)d_in[1];
    const float* bq = (const float*)d_in[2];
    const float* Wk = (const float*)d_in[3];
    const float* bk = (const float*)d_in[4];
    const float* Wv = (const float*)d_in[5];
    const float* bv = (const float*)d_in[6];
    const float* Wo = (const float*)d_in[7];
    const float* bo = (const float*)d_in[8];
    const float* ls = (const float*)d_in[9];

    float *qp, *kp, *vp, *ap;
    cudaGetSymbolAddress((void**)&qp, g_q);
    cudaGetSymbolAddress((void**)&kp, g_k);
    cudaGetSymbolAddress((void**)&vp, g_v);
    cudaGetSymbolAddress((void**)&ap, g_attn);

    cudaFuncSetAttribute(gemmk<3>, cudaFuncAttributeMaxDynamicSharedMemorySize, SMEM_GEMM);
    cudaFuncSetAttribute(gemmk<1>, cudaFuncAttributeMaxDynamicSharedMemorySize, SMEM_GEMM);

    dim3 gqkv(BB * TT / GBM, EE / GBN, 3);  // 128 x 4 x 3
    gemmk<3><<<gqkv, 256, SMEM_GEMM>>>(x, Wq, bq, qp, Wk, bk, kp, Wv, bv, vp);

    const size_t asmem =
        (size_t)(32 * 64 + 2 * KR * 64 + 32 * KR + KR + 32) * sizeof(float);  // ~111KB
    cudaFuncSetAttribute(attn_kernel, cudaFuncAttributeMaxDynamicSharedMemorySize,
                         (int)asmem);
    attn_kernel<<<dim3(TT / 32, HH, BB), 512, asmem>>>(ls);

    dim3 go(BB * TT / GBM, EE / GBN);  // 128 x 4
    gemmk<1><<<go, 256, SMEM_GEMM>>>(ap, Wo, bo, (float*)d_out,
                                     nullptr, nullptr, nullptr, nullptr, nullptr, nullptr);
}

// round 12
// speedup vs baseline: 2.7670x; 1.3471x over previous
#include <cuda_runtime.h>
#include <cuda_fp16.h>
#include <math.h>

#define BB 4
#define HH 8
#define TT 2048
#define DD 64
#define EE 512
#define TOPKK 96
#define KR 160   // key rows per 32-query tile (window 128 + 32)

typedef unsigned long long ull;

// Scratch (device globals; no allocation allowed)
__device__ float g_q[(size_t)BB * HH * TT * DD];
__device__ float g_k[(size_t)BB * HH * TT * DD];
__device__ float g_v[(size_t)BB * HH * TT * DD];
__device__ float g_attn[(size_t)BB * TT * EE];

__device__ __forceinline__ unsigned f2ord(float f) {
    unsigned u = __float_as_uint(f);
    return (u & 0x80000000u) ? ~u : (u | 0x80000000u);
}
__device__ __forceinline__ float ord2f(unsigned k) {
    unsigned u = (k & 0x80000000u) ? (k & 0x7fffffffu) : ~k;
    return __uint_as_float(u);
}
__device__ __forceinline__ unsigned s2u(const void* p) {
    return (unsigned)__cvta_generic_to_shared(p);
}
__device__ __forceinline__ void ldsm4(unsigned& r0, unsigned& r1, unsigned& r2,
                                      unsigned& r3, unsigned addr) {
    asm volatile("ldmatrix.sync.aligned.m8n8.x4.shared.b16 {%0,%1,%2,%3}, [%4];"
                 : "=r"(r0), "=r"(r1), "=r"(r2), "=r"(r3) : "r"(addr));
}
__device__ __forceinline__ void ldsm2t(unsigned& r0, unsigned& r1, unsigned addr) {
    asm volatile("ldmatrix.sync.aligned.m8n8.x2.trans.shared.b16 {%0,%1}, [%2];"
                 : "=r"(r0), "=r"(r1) : "r"(addr));
}
__device__ __forceinline__ void mma_f16(float& c0, float& c1, float& c2, float& c3,
                                        unsigned a0, unsigned a1, unsigned a2,
                                        unsigned a3, unsigned b0, unsigned b1) {
    asm volatile(
        "mma.sync.aligned.m16n8k16.row.col.f32.f16.f16.f32 "
        "{%0,%1,%2,%3}, {%4,%5,%6,%7}, {%8,%9}, {%0,%1,%2,%3};"
        : "+f"(c0), "+f"(c1), "+f"(c2), "+f"(c3)
        : "r"(a0), "r"(a1), "r"(a2), "r"(a3), "r"(b0), "r"(b1));
}
// split 2 floats -> hi half2 + lo half2 (x = hi + lo, 22-bit effective mantissa)
__device__ __forceinline__ void split2(float x, float y, unsigned& h, unsigned& l) {
    __half2 h2 = __float22half2_rn(make_float2(x, y));
    float2 hf = __half22float2(h2);
    __half2 l2 = __float22half2_rn(make_float2(x - hf.x, y - hf.y));
    h = *(unsigned*)&h2;
    l = *(unsigned*)&l2;
}

// ---------------------------------------------------------------------------
// 3xFP16 tensor-core GEMM (unchanged from R10 — known passing).
// ---------------------------------------------------------------------------
#define GBM 64
#define GBN 128
#define GBK 32
#define AHI_OFF 0
#define ALO_OFF 8192
#define BHI_OFF 16384
#define BLO_OFF 32768
#define SMEM_GEMM 49152
#define ABUFB 4096
#define BBUFB 8192

template <int NOUT>
__global__ __launch_bounds__(256, 2) void gemmk(
    const float* __restrict__ X,
    const float* __restrict__ W0, const float* __restrict__ bias0, float* __restrict__ Y0,
    const float* __restrict__ W1, const float* __restrict__ bias1, float* __restrict__ Y1,
    const float* __restrict__ W2, const float* __restrict__ bias2, float* __restrict__ Y2) {
    extern __shared__ char smg[];
    const unsigned sbase = s2u(smg);

    const float* W;
    const float* bias;
    float* Y;
    if (NOUT == 3) {
        int z = blockIdx.z;
        W = (z == 0) ? W0 : (z == 1) ? W1 : W2;
        bias = (z == 0) ? bias0 : (z == 1) ? bias1 : bias2;
        Y = (z == 0) ? Y0 : (z == 1) ? Y1 : Y2;
    } else {
        W = W0; bias = bias0; Y = Y0;
    }

    const int m0 = blockIdx.x * GBM;
    const int n0 = blockIdx.y * GBN;
    const int tid = threadIdx.x;
    const int wid = tid >> 5;
    const int lane = tid & 31;
    const int wm = (wid & 1) * 32;
    const int wn = (wid >> 1) * 32;

    const int arow = tid >> 2, ac = tid & 3;
    const int brow = tid >> 1, bc2 = (tid & 1) * 2;
    const float* Agp = X + (size_t)(m0 + arow) * EE + ac * 8;
    const float* Bgp = W + (size_t)(n0 + brow) * EE + bc2 * 8;
    const int aStO = arow * 64 + ((ac ^ ((arow >> 1) & 3)) << 4);
    int bStO[2];
#pragma unroll
    for (int u = 0; u < 2; u++)
        bStO[u] = brow * 64 + (((bc2 + u) ^ ((brow >> 1) & 3)) << 4);

    const int a_m = (lane & 7) + ((lane >> 3) & 1) * 8;
    const int a_kh = lane >> 4;
    const int b_n = (lane & 7) + (lane >> 4) * 8;
    const int b_kh = (lane >> 3) & 1;
    unsigned aRow[2], bRow[2];
    int aSw[2], bSw[2];
#pragma unroll
    for (int mt = 0; mt < 2; mt++) {
        int r = wm + mt * 16 + a_m;
        aRow[mt] = sbase + AHI_OFF + (unsigned)r * 64;
        aSw[mt] = (r >> 1) & 3;
    }
#pragma unroll
    for (int p = 0; p < 2; p++) {
        int r = wn + p * 16 + b_n;
        bRow[p] = sbase + BHI_OFF + (unsigned)r * 64;
        bSw[p] = (r >> 1) & 3;
    }

    float4 ra0, ra1, rb0, rb1, rb2, rb3;
    auto ldg = [&](int t) {
        ra0 = *(const float4*)(Agp + t * GBK);
        ra1 = *(const float4*)(Agp + t * GBK + 4);
        rb0 = *(const float4*)(Bgp + t * GBK);
        rb1 = *(const float4*)(Bgp + t * GBK + 4);
        rb2 = *(const float4*)(Bgp + t * GBK + 8);
        rb3 = *(const float4*)(Bgp + t * GBK + 12);
    };
    auto sts = [&](int buf) {
        char* base = smg;
        {
            uint4 h, l;
            split2(ra0.x, ra0.y, h.x, l.x);
            split2(ra0.z, ra0.w, h.y, l.y);
            split2(ra1.x, ra1.y, h.z, l.z);
            split2(ra1.z, ra1.w, h.w, l.w);
            *(uint4*)(base + AHI_OFF + buf * ABUFB + aStO) = h;
            *(uint4*)(base + ALO_OFF + buf * ABUFB + aStO) = l;
        }
        {
            uint4 h, l;
            split2(rb0.x, rb0.y, h.x, l.x);
            split2(rb0.z, rb0.w, h.y, l.y);
            split2(rb1.x, rb1.y, h.z, l.z);
            split2(rb1.z, rb1.w, h.w, l.w);
            *(uint4*)(base + BHI_OFF + buf * BBUFB + bStO[0]) = h;
            *(uint4*)(base + BLO_OFF + buf * BBUFB + bStO[0]) = l;
        }
        {
            uint4 h, l;
            split2(rb2.x, rb2.y, h.x, l.x);
            split2(rb2.z, rb2.w, h.y, l.y);
            split2(rb3.x, rb3.y, h.z, l.z);
            split2(rb3.z, rb3.w, h.w, l.w);
            *(uint4*)(base + BHI_OFF + buf * BBUFB + bStO[1]) = h;
            *(uint4*)(base + BLO_OFF + buf * BBUFB + bStO[1]) = l;
        }
    };

    float c[2][4][4];
#pragma unroll
    for (int mt = 0; mt < 2; mt++)
#pragma unroll
        for (int nt = 0; nt < 4; nt++)
#pragma unroll
            for (int r = 0; r < 4; r++) c[mt][nt][r] = 0.f;

    ldg(0);
    sts(0);
    __syncthreads();

    const int NT = EE / GBK;
    for (int t = 0; t < NT; t++) {
        if (t + 1 < NT) ldg(t + 1);
        const unsigned abo = (unsigned)(t & 1) * ABUFB;
        const unsigned bbo = (unsigned)(t & 1) * BBUFB;
#pragma unroll
        for (int ks = 0; ks < 2; ks++) {
            unsigned ah[2][4], al[2][4], bh[4][2], bl[4][2];
#pragma unroll
            for (int mt = 0; mt < 2; mt++) {
                unsigned ad = aRow[mt] + abo +
                              (unsigned)((((ks << 1) + a_kh) ^ aSw[mt]) << 4);
                ldsm4(ah[mt][0], ah[mt][1], ah[mt][2], ah[mt][3], ad);
                ldsm4(al[mt][0], al[mt][1], al[mt][2], al[mt][3],
                      ad + (ALO_OFF - AHI_OFF));
            }
#pragma unroll
            for (int p = 0; p < 2; p++) {
                unsigned bd = bRow[p] + bbo +
                              (unsigned)((((ks << 1) + b_kh) ^ bSw[p]) << 4);
                ldsm4(bh[2 * p][0], bh[2 * p][1], bh[2 * p + 1][0],
                      bh[2 * p + 1][1], bd);
                ldsm4(bl[2 * p][0], bl[2 * p][1], bl[2 * p + 1][0],
                      bl[2 * p + 1][1], bd + (BLO_OFF - BHI_OFF));
            }
#pragma unroll
            for (int mt = 0; mt < 2; mt++)
#pragma unroll
                for (int nt = 0; nt < 4; nt++)
                    mma_f16(c[mt][nt][0], c[mt][nt][1], c[mt][nt][2], c[mt][nt][3],
                            ah[mt][0], ah[mt][1], ah[mt][2], ah[mt][3],
                            bh[nt][0], bh[nt][1]);
#pragma unroll
            for (int mt = 0; mt < 2; mt++)
#pragma unroll
                for (int nt = 0; nt < 4; nt++)
                    mma_f16(c[mt][nt][0], c[mt][nt][1], c[mt][nt][2], c[mt][nt][3],
                            ah[mt][0], ah[mt][1], ah[mt][2], ah[mt][3],
                            bl[nt][0], bl[nt][1]);
#pragma unroll
            for (int mt = 0; mt < 2; mt++)
#pragma unroll
                for (int nt = 0; nt < 4; nt++)
                    mma_f16(c[mt][nt][0], c[mt][nt][1], c[mt][nt][2], c[mt][nt][3],
                            al[mt][0], al[mt][1], al[mt][2], al[mt][3],
                            bh[nt][0], bh[nt][1]);
        }
        __syncthreads();
        if (t + 1 < NT) {
            sts((t + 1) & 1);
            __syncthreads();
        }
    }

    const int g = lane >> 2;
    const int tc = lane & 3;
#pragma unroll
    for (int mt = 0; mt < 2; mt++)
#pragma unroll
        for (int nt = 0; nt < 4; nt++) {
            int col = n0 + wn + nt * 8 + tc * 2;
            float2 bbv = *(const float2*)&bias[col];
            float2 v0 = make_float2(c[mt][nt][0] + bbv.x, c[mt][nt][1] + bbv.y);
            float2 v1 = make_float2(c[mt][nt][2] + bbv.x, c[mt][nt][3] + bbv.y);
            int row = m0 + wm + mt * 16 + g;
            if (NOUT == 3) {
                int h = col >> 6, d = col & 63;
                int bi = row >> 11, tt0 = row & 2047;
                float* base = Y + (((size_t)bi * HH + h) * TT) * DD + d;
                *(float2*)&base[(size_t)tt0 * DD] = v0;
                *(float2*)&base[(size_t)(tt0 + 8) * DD] = v1;
            } else {
                *(float2*)&Y[(size_t)row * EE + col] = v0;
                *(float2*)&Y[(size_t)(row + 8) * EE + col] = v1;
            }
        }
}

// ---------------------------------------------------------------------------
// Attention v3 — tensor-core QK^T and PV (3-term fp16 split), SIMT top-k.
// Block per (q-tile 32, h, b), 512 threads = 16 warps, ~109KB smem, 2 CTA/SM.
// smem byte offsets:
//   QH 0       QL 4096    (32 x 128B rows,  chunk ^ (row&7) swizzle)
//   KH 8192    KL 28672   (160 x 128B rows, same swizzle)  [aliased: PH/PL]
//   VH 49152   VL 69632   (160 x 128B rows, same swizzle)
//   SS 90112   (f32 scores 32 x 160; later holds P f32)
//   KSQ 110592 (160 f32)   QSQ 111232 (32 f32)
//   PH 8192 / PL 28672: f16 P tiles, 32 rows x 336B (21 chunks; 21 mod 8 = 5
//   -> ldmatrix rows hit 8 distinct bank-groups, no xor swizzle needed)
// ---------------------------------------------------------------------------
#define AQH 0
#define AQL 4096
#define AKH 8192
#define AKL 28672
#define AVH 49152
#define AVL 69632
#define ASSB 90112
#define ASSF (ASSB / 4)
#define AKSQF (110592 / 4)
#define AQSQF (111232 / 4)
#define ASMEM 111360
#define APH 8192
#define APL 28672
#define PSTRIDE 336

__global__ __launch_bounds__(512, 2) void attn_kernel(const float* __restrict__ log_sigma) {
    extern __shared__ char sma[];
    float* smf = (float*)sma;
    const unsigned sb = s2u(sma);

    const int q0 = blockIdx.x * 32;
    const int h = blockIdx.y;
    const int b = blockIdx.z;
    const int tid = threadIdx.x;
    const int w = tid >> 5, l = tid & 31;

    const float* Qg = g_q + ((size_t)(b * HH + h) * TT) * DD;
    const float* Kg = g_k + ((size_t)(b * HH + h) * TT) * DD;
    const float* Vg = g_v + ((size_t)(b * HH + h) * TT) * DD;
    const float scale = -0.5f * expf(-2.f * log_sigma[h]);
    const float4 z4 = make_float4(0.f, 0.f, 0.f, 0.f);

    // ================= load + f16-split + norms =================
    // K: 160 rows x 8 chunks (8 floats each)
    for (int i = tid; i < 1280; i += 512) {
        int row = i >> 3, cc = i & 7;
        int gk = q0 - 128 + row;
        float4 f0 = z4, f1 = z4;
        if (gk >= 0) {
            f0 = *(const float4*)&Kg[(size_t)gk * DD + cc * 8];
            f1 = *(const float4*)&Kg[(size_t)gk * DD + cc * 8 + 4];
        }
        float p = f0.x * f0.x + f0.y * f0.y + f0.z * f0.z + f0.w * f0.w +
                  f1.x * f1.x + f1.y * f1.y + f1.z * f1.z + f1.w * f1.w;
        p += __shfl_xor_sync(0xffffffffu, p, 1);
        p += __shfl_xor_sync(0xffffffffu, p, 2);
        p += __shfl_xor_sync(0xffffffffu, p, 4);
        if (cc == 0) smf[AKSQF + row] = p;
        uint4 hh, ll;
        split2(f0.x, f0.y, hh.x, ll.x);
        split2(f0.z, f0.w, hh.y, ll.y);
        split2(f1.x, f1.y, hh.z, ll.z);
        split2(f1.z, f1.w, hh.w, ll.w);
        int off = row * 128 + ((cc ^ (row & 7)) << 4);
        *(uint4*)(sma + AKH + off) = hh;
        *(uint4*)(sma + AKL + off) = ll;
    }
    // V: same, no norms
    for (int i = tid; i < 1280; i += 512) {
        int row = i >> 3, cc = i & 7;
        int gk = q0 - 128 + row;
        float4 f0 = z4, f1 = z4;
        if (gk >= 0) {
            f0 = *(const float4*)&Vg[(size_t)gk * DD + cc * 8];
            f1 = *(const float4*)&Vg[(size_t)gk * DD + cc * 8 + 4];
        }
        uint4 hh, ll;
        split2(f0.x, f0.y, hh.x, ll.x);
        split2(f0.z, f0.w, hh.y, ll.y);
        split2(f1.x, f1.y, hh.z, ll.z);
        split2(f1.z, f1.w, hh.w, ll.w);
        int off = row * 128 + ((cc ^ (row & 7)) << 4);
        *(uint4*)(sma + AVH + off) = hh;
        *(uint4*)(sma + AVL + off) = ll;
    }
    // Q: 32 rows
    if (tid < 256) {
        int row = tid >> 3, cc = tid & 7;
        float4 f0 = *(const float4*)&Qg[(size_t)(q0 + row) * DD + cc * 8];
        float4 f1 = *(const float4*)&Qg[(size_t)(q0 + row) * DD + cc * 8 + 4];
        float p = f0.x * f0.x + f0.y * f0.y + f0.z * f0.z + f0.w * f0.w +
                  f1.x * f1.x + f1.y * f1.y + f1.z * f1.z + f1.w * f1.w;
        p += __shfl_xor_sync(0xffffffffu, p, 1);
        p += __shfl_xor_sync(0xffffffffu, p, 2);
        p += __shfl_xor_sync(0xffffffffu, p, 4);
        if (cc == 0) smf[AQSQF + row] = p;
        uint4 hh, ll;
        split2(f0.x, f0.y, hh.x, ll.x);
        split2(f0.z, f0.w, hh.y, ll.y);
        split2(f1.x, f1.y, hh.z, ll.z);
        split2(f1.z, f1.w, hh.w, ll.w);
        int off = row * 128 + ((cc ^ (row & 7)) << 4);
        *(uint4*)(sma + AQH + off) = hh;
        *(uint4*)(sma + AQL + off) = ll;
    }
    __syncthreads();

    // ================= QK^T MMA: scores -> SS =================
    // 20 units (2 m-tiles x 10 n16-groups); warp w does u = w, w+16.
    {
        const int a_m = (l & 7) + ((l >> 3) & 1) * 8;
        const int a_kh = l >> 4;
        const int b_nl = (l & 7) + (l >> 4) * 8;
        const int b_kh = (l >> 3) & 1;
        for (int u = w; u < 20; u += 16) {
            const int mt = u / 10, ng = u % 10;
            const int n0 = ng * 16;
            float c[2][4];
#pragma unroll
            for (int j = 0; j < 2; j++)
#pragma unroll
                for (int r = 0; r < 4; r++) c[j][r] = 0.f;
            const int arow = mt * 16 + a_m;
            const unsigned aH = sb + AQH + (unsigned)arow * 128;
            const int asw = arow & 7;
            const int brow = n0 + b_nl;
            const unsigned bH = sb + AKH + (unsigned)brow * 128;
            const int bsw = brow & 7;
#pragma unroll
            for (int ks = 0; ks < 4; ks++) {
                unsigned ah[4], al[4], bh[4], bl[4];
                unsigned aad = aH + (unsigned)(((2 * ks + a_kh) ^ asw) << 4);
                ldsm4(ah[0], ah[1], ah[2], ah[3], aad);
                ldsm4(al[0], al[1], al[2], al[3], aad + (AQL - AQH));
                unsigned bad = bH + (unsigned)(((2 * ks + b_kh) ^ bsw) << 4);
                ldsm4(bh[0], bh[1], bh[2], bh[3], bad);
                ldsm4(bl[0], bl[1], bl[2], bl[3], bad + (AKL - AKH));
                mma_f16(c[0][0], c[0][1], c[0][2], c[0][3],
                        ah[0], ah[1], ah[2], ah[3], bh[0], bh[1]);
                mma_f16(c[1][0], c[1][1], c[1][2], c[1][3],
                        ah[0], ah[1], ah[2], ah[3], bh[2], bh[3]);
                mma_f16(c[0][0], c[0][1], c[0][2], c[0][3],
                        ah[0], ah[1], ah[2], ah[3], bl[0], bl[1]);
                mma_f16(c[1][0], c[1][1], c[1][2], c[1][3],
                        ah[0], ah[1], ah[2], ah[3], bl[2], bl[3]);
                mma_f16(c[0][0], c[0][1], c[0][2], c[0][3],
                        al[0], al[1], al[2], al[3], bh[0], bh[1]);
                mma_f16(c[1][0], c[1][1], c[1][2], c[1][3],
                        al[0], al[1], al[2], al[3], bh[2], bh[3]);
            }
            // epilogue: score = (qsq + ksq - 2 dot) * scale
            const int r1 = mt * 16 + (l >> 2);
            const int r2 = r1 + 8;
            const float qs1 = smf[AQSQF + r1];
            const float qs2 = smf[AQSQF + r2];
#pragma unroll
            for (int j = 0; j < 2; j++) {
                int cb = n0 + j * 8 + 2 * (l & 3);
                float2 kq = *(const float2*)&smf[AKSQF + cb];
                float2 s1, s2;
                s1.x = (qs1 + kq.x - 2.f * c[j][0]) * scale;
                s1.y = (qs1 + kq.y - 2.f * c[j][1]) * scale;
                s2.x = (qs2 + kq.x - 2.f * c[j][2]) * scale;
                s2.y = (qs2 + kq.y - 2.f * c[j][3]) * scale;
                *(float2*)&smf[ASSF + r1 * KR + cb] = s1;
                *(float2*)&smf[ASSF + r2 * KR + cb] = s2;
            }
        }
    }
    __syncthreads();

    // ================= top-k + softmax (SIMT, warp = 2 queries) ==========
    {
        const int qA = 2 * w, qB = 2 * w + 1;
        const int r0A = qA + 1 + l, r0B = qB + 1 + l;
        unsigned key[2][4];
#pragma unroll
        for (int q = 0; q < 2; q++) {
            const int qi = (q == 0) ? qA : qB;
            const int r0 = (q == 0) ? r0A : r0B;
#pragma unroll
            for (int t = 0; t < 4; t++) {
                int r = r0 + 32 * t;
                float s = smf[ASSF + qi * KR + r];
                bool valid = (q0 - 128 + r) >= 0;
                key[q][t] = valid ? f2ord(s) : 0u;
            }
        }

        unsigned thr[2] = {0u, 0u};
#pragma unroll 1
        for (int bp = 30; bp >= 0; bp -= 2) {
            unsigned pk[2];
#pragma unroll
            for (int q = 0; q < 2; q++) {
                unsigned c1 = thr[q] | (1u << bp);
                unsigned c2 = thr[q] | (2u << bp);
                unsigned c3 = thr[q] | (3u << bp);
                unsigned p = 0;
#pragma unroll
                for (int t = 0; t < 4; t++) {
                    p += (key[q][t] >= c1 ? 1u : 0u);
                    p += (key[q][t] >= c2 ? 0x100u : 0u);
                    p += (key[q][t] >= c3 ? 0x10000u : 0u);
                }
                pk[q] = p;
            }
            pk[0] = __reduce_add_sync(0xffffffffu, pk[0]);
            pk[1] = __reduce_add_sync(0xffffffffu, pk[1]);
#pragma unroll
            for (int q = 0; q < 2; q++) {
                if ((pk[q] >> 16) >= TOPKK) thr[q] |= (3u << bp);
                else if (((pk[q] >> 8) & 0xffu) >= TOPKK) thr[q] |= (2u << bp);
                else if ((pk[q] & 0xffu) >= TOPKK) thr[q] |= (1u << bp);
            }
        }
        // top-k filter only active when > 96 valid keys
        if (q0 + qA < TOPKK) thr[0] = 0u;
        if (q0 + qB < TOPKK) thr[1] = 0u;

        unsigned km[2][4];
        unsigned mx[2] = {0u, 0u};
#pragma unroll
        for (int q = 0; q < 2; q++)
#pragma unroll
            for (int t = 0; t < 4; t++) {
                unsigned k = key[q][t];
                unsigned kk = (k != 0u && k >= thr[q]) ? k : 0u;
                km[q][t] = kk;
                mx[q] = max(mx[q], kk);
            }
        mx[0] = __reduce_max_sync(0xffffffffu, mx[0]);
        mx[1] = __reduce_max_sync(0xffffffffu, mx[1]);
        float mv[2] = {ord2f(mx[0]), ord2f(mx[1])};

        float e[2][4];
        float esum[2] = {0.f, 0.f};
#pragma unroll
        for (int q = 0; q < 2; q++)
#pragma unroll
            for (int t = 0; t < 4; t++) {
                float v = (km[q][t] != 0u) ? __expf(ord2f(km[q][t]) - mv[q]) : 0.f;
                e[q][t] = v;
                esum[q] += v;
            }
#pragma unroll
        for (int o = 16; o > 0; o >>= 1) {
            esum[0] += __shfl_xor_sync(0xffffffffu, esum[0], o);
            esum[1] += __shfl_xor_sync(0xffffffffu, esum[1], o);
        }
        float inv0 = 1.f / esum[0];
        float inv1 = 1.f / esum[1];
#pragma unroll
        for (int t = 0; t < 4; t++) {
            smf[ASSF + qA * KR + r0A + 32 * t] = e[0][t] * inv0;
            smf[ASSF + qB * KR + r0B + 32 * t] = e[1][t] * inv1;
        }
    }
    __syncthreads();

    // ================= convert P (f32 in SS) -> f16 hi/lo tiles ==========
    // mask out-of-window slots (they hold stale scores) to zero.
    for (int i = tid; i < 1280; i += 512) {
        int q = i / 40, g = i % 40;
        int c0 = g * 4;
        float4 v = *(const float4*)&smf[ASSF + q * KR + c0];
        int lo = q + 1;
        int lb = 128 - q0;
        if (lb > lo) lo = lb;
        int hi = q + 128;
        float x0 = (c0 >= lo && c0 <= hi) ? v.x : 0.f;
        float x1 = (c0 + 1 >= lo && c0 + 1 <= hi) ? v.y : 0.f;
        float x2 = (c0 + 2 >= lo && c0 + 2 <= hi) ? v.z : 0.f;
        float x3 = (c0 + 3 >= lo && c0 + 3 <= hi) ? v.w : 0.f;
        uint2 hh, ll;
        split2(x0, x1, hh.x, ll.x);
        split2(x2, x3, hh.y, ll.y);
        int off = q * PSTRIDE + g * 8;
        *(uint2*)(sma + APH + off) = hh;
        *(uint2*)(sma + APL + off) = ll;
    }
    __syncthreads();

    // ================= PV MMA: out = P[32x160] x V[160x64] ==============
    {
        const int mt = w & 1;
        const int n8 = w >> 1;
        float c0 = 0.f, c1 = 0.f, c2 = 0.f, c3 = 0.f;
        const int prow = mt * 16 + (l & 7) + ((l >> 3) & 1) * 8;
        const unsigned pBase = sb + APH + (unsigned)prow * PSTRIDE;
        const int pkh = l >> 4;
        const int vlane = l & 15;
#pragma unroll
        for (int ks = 0; ks < 10; ks++) {
            unsigned ph[4], pl[4], vh0, vh1, vl0, vl1;
            unsigned pad = pBase + (unsigned)((2 * ks + pkh) << 4);
            ldsm4(ph[0], ph[1], ph[2], ph[3], pad);
            ldsm4(pl[0], pl[1], pl[2], pl[3], pad + (APL - APH));
            int vrow = ks * 16 + vlane;
            unsigned vad = sb + AVH + (unsigned)vrow * 128 +
                           (unsigned)((n8 ^ (vrow & 7)) << 4);
            ldsm2t(vh0, vh1, vad);
            ldsm2t(vl0, vl1, vad + (AVL - AVH));
            mma_f16(c0, c1, c2, c3, ph[0], ph[1], ph[2], ph[3], vh0, vh1);
            mma_f16(c0, c1, c2, c3, pl[0], pl[1], pl[2], pl[3], vh0, vh1);
            mma_f16(c0, c1, c2, c3, ph[0], ph[1], ph[2], ph[3], vl0, vl1);
        }
        const int gq = q0 + mt * 16 + (l >> 2);
        const int colb = h * DD + n8 * 8 + 2 * (l & 3);
        *(float2*)&g_attn[((size_t)b * TT + gq) * EE + colb] =
            make_float2(c0, c1);
        *(float2*)&g_attn[((size_t)b * TT + gq + 8) * EE + colb] =
            make_float2(c2, c3);
    }
}

// ---------------------------------------------------------------------------
extern "C" void kernel_launch(void* const* d_in, const int* in_sizes, int n_in,
                              void* d_out, int out_size) {
    const float* x  = (const float*)d_in[0];
    const float* Wq = (const float*)d_in[1];
    const float* bq = (const float*)d_in[2];
    const float* Wk = (const float*)d_in[3];
    const float* bk = (const float*)d_in[4];
    const float* Wv = (const float*)d_in[5];
    const float* bv = (const float*)d_in[6];
    const float* Wo = (const float*)d_in[7];
    const float* bo = (const float*)d_in[8];
    const float* ls = (const float*)d_in[9];

    float *qp, *kp, *vp, *ap;
    cudaGetSymbolAddress((void**)&qp, g_q);
    cudaGetSymbolAddress((void**)&kp, g_k);
    cudaGetSymbolAddress((void**)&vp, g_v);
    cudaGetSymbolAddress((void**)&ap, g_attn);

    cudaFuncSetAttribute(gemmk<3>, cudaFuncAttributeMaxDynamicSharedMemorySize, SMEM_GEMM);
    cudaFuncSetAttribute(gemmk<1>, cudaFuncAttributeMaxDynamicSharedMemorySize, SMEM_GEMM);

    dim3 gqkv(BB * TT / GBM, EE / GBN, 3);  // 128 x 4 x 3
    gemmk<3><<<gqkv, 256, SMEM_GEMM>>>(x, Wq, bq, qp, Wk, bk, kp, Wv, bv, vp);

    cudaFuncSetAttribute(attn_kernel, cudaFuncAttributeMaxDynamicSharedMemorySize,
                         ASMEM);
    attn_kernel<<<dim3(TT / 32, HH, BB), 512, ASMEM>>>(ls);

    dim3 go(BB * TT / GBM, EE / GBN);  // 128 x 4
    gemmk<1><<<go, 256, SMEM_GEMM>>>(ap, Wo, bo, (float*)d_out,
                                     nullptr, nullptr, nullptr, nullptr, nullptr, nullptr);
}

// round 13
// speedup vs baseline: 2.8755x; 1.0392x over previous
#include <cuda_runtime.h>
#include <cuda_fp16.h>
#include <math.h>

#define BB 4
#define HH 8
#define TT 2048
#define DD 64
#define EE 512
#define TOPKK 96

typedef unsigned long long ull;

// Scratch (device globals; no allocation allowed)
__device__ float g_q[(size_t)BB * HH * TT * DD];
__device__ float g_k[(size_t)BB * HH * TT * DD];
__device__ float g_v[(size_t)BB * HH * TT * DD];
__device__ float g_attn[(size_t)BB * TT * EE];

__device__ __forceinline__ unsigned f2ord(float f) {
    unsigned u = __float_as_uint(f);
    return (u & 0x80000000u) ? ~u : (u | 0x80000000u);
}
__device__ __forceinline__ float ord2f(unsigned k) {
    unsigned u = (k & 0x80000000u) ? (k & 0x7fffffffu) : ~k;
    return __uint_as_float(u);
}
__device__ __forceinline__ unsigned s2u(const void* p) {
    return (unsigned)__cvta_generic_to_shared(p);
}
__device__ __forceinline__ void ldsm4(unsigned& r0, unsigned& r1, unsigned& r2,
                                      unsigned& r3, unsigned addr) {
    asm volatile("ldmatrix.sync.aligned.m8n8.x4.shared.b16 {%0,%1,%2,%3}, [%4];"
                 : "=r"(r0), "=r"(r1), "=r"(r2), "=r"(r3) : "r"(addr));
}
__device__ __forceinline__ void ldsm4t(unsigned& r0, unsigned& r1, unsigned& r2,
                                       unsigned& r3, unsigned addr) {
    asm volatile("ldmatrix.sync.aligned.m8n8.x4.trans.shared.b16 {%0,%1,%2,%3}, [%4];"
                 : "=r"(r0), "=r"(r1), "=r"(r2), "=r"(r3) : "r"(addr));
}
__device__ __forceinline__ void ldsm2t(unsigned& r0, unsigned& r1, unsigned addr) {
    asm volatile("ldmatrix.sync.aligned.m8n8.x2.trans.shared.b16 {%0,%1}, [%2];"
                 : "=r"(r0), "=r"(r1) : "r"(addr));
}
__device__ __forceinline__ void mma_f16(float& c0, float& c1, float& c2, float& c3,
                                        unsigned a0, unsigned a1, unsigned a2,
                                        unsigned a3, unsigned b0, unsigned b1) {
    asm volatile(
        "mma.sync.aligned.m16n8k16.row.col.f32.f16.f16.f32 "
        "{%0,%1,%2,%3}, {%4,%5,%6,%7}, {%8,%9}, {%0,%1,%2,%3};"
        : "+f"(c0), "+f"(c1), "+f"(c2), "+f"(c3)
        : "r"(a0), "r"(a1), "r"(a2), "r"(a3), "r"(b0), "r"(b1));
}
// split 2 floats -> hi half2 + lo half2 (x = hi + lo, 22-bit effective mantissa)
__device__ __forceinline__ void split2(float x, float y, unsigned& h, unsigned& l) {
    __half2 h2 = __float22half2_rn(make_float2(x, y));
    float2 hf = __half22float2(h2);
    __half2 l2 = __float22half2_rn(make_float2(x - hf.x, y - hf.y));
    h = *(unsigned*)&h2;
    l = *(unsigned*)&l2;
}

// ---------------------------------------------------------------------------
// 3xFP16 tensor-core GEMM (unchanged from R12 — known passing).
// ---------------------------------------------------------------------------
#define GBM 64
#define GBN 128
#define GBK 32
#define AHI_OFF 0
#define ALO_OFF 8192
#define BHI_OFF 16384
#define BLO_OFF 32768
#define SMEM_GEMM 49152
#define ABUFB 4096
#define BBUFB 8192

template <int NOUT>
__global__ __launch_bounds__(256, 2) void gemmk(
    const float* __restrict__ X,
    const float* __restrict__ W0, const float* __restrict__ bias0, float* __restrict__ Y0,
    const float* __restrict__ W1, const float* __restrict__ bias1, float* __restrict__ Y1,
    const float* __restrict__ W2, const float* __restrict__ bias2, float* __restrict__ Y2) {
    extern __shared__ char smg[];
    const unsigned sbase = s2u(smg);

    const float* W;
    const float* bias;
    float* Y;
    if (NOUT == 3) {
        int z = blockIdx.z;
        W = (z == 0) ? W0 : (z == 1) ? W1 : W2;
        bias = (z == 0) ? bias0 : (z == 1) ? bias1 : bias2;
        Y = (z == 0) ? Y0 : (z == 1) ? Y1 : Y2;
    } else {
        W = W0; bias = bias0; Y = Y0;
    }

    const int m0 = blockIdx.x * GBM;
    const int n0 = blockIdx.y * GBN;
    const int tid = threadIdx.x;
    const int wid = tid >> 5;
    const int lane = tid & 31;
    const int wm = (wid & 1) * 32;
    const int wn = (wid >> 1) * 32;

    const int arow = tid >> 2, ac = tid & 3;
    const int brow = tid >> 1, bc2 = (tid & 1) * 2;
    const float* Agp = X + (size_t)(m0 + arow) * EE + ac * 8;
    const float* Bgp = W + (size_t)(n0 + brow) * EE + bc2 * 8;
    const int aStO = arow * 64 + ((ac ^ ((arow >> 1) & 3)) << 4);
    int bStO[2];
#pragma unroll
    for (int u = 0; u < 2; u++)
        bStO[u] = brow * 64 + (((bc2 + u) ^ ((brow >> 1) & 3)) << 4);

    const int a_m = (lane & 7) + ((lane >> 3) & 1) * 8;
    const int a_kh = lane >> 4;
    const int b_n = (lane & 7) + (lane >> 4) * 8;
    const int b_kh = (lane >> 3) & 1;
    unsigned aRow[2], bRow[2];
    int aSw[2], bSw[2];
#pragma unroll
    for (int mt = 0; mt < 2; mt++) {
        int r = wm + mt * 16 + a_m;
        aRow[mt] = sbase + AHI_OFF + (unsigned)r * 64;
        aSw[mt] = (r >> 1) & 3;
    }
#pragma unroll
    for (int p = 0; p < 2; p++) {
        int r = wn + p * 16 + b_n;
        bRow[p] = sbase + BHI_OFF + (unsigned)r * 64;
        bSw[p] = (r >> 1) & 3;
    }

    float4 ra0, ra1, rb0, rb1, rb2, rb3;
    auto ldg = [&](int t) {
        ra0 = *(const float4*)(Agp + t * GBK);
        ra1 = *(const float4*)(Agp + t * GBK + 4);
        rb0 = *(const float4*)(Bgp + t * GBK);
        rb1 = *(const float4*)(Bgp + t * GBK + 4);
        rb2 = *(const float4*)(Bgp + t * GBK + 8);
        rb3 = *(const float4*)(Bgp + t * GBK + 12);
    };
    auto sts = [&](int buf) {
        char* base = smg;
        {
            uint4 h, l;
            split2(ra0.x, ra0.y, h.x, l.x);
            split2(ra0.z, ra0.w, h.y, l.y);
            split2(ra1.x, ra1.y, h.z, l.z);
            split2(ra1.z, ra1.w, h.w, l.w);
            *(uint4*)(base + AHI_OFF + buf * ABUFB + aStO) = h;
            *(uint4*)(base + ALO_OFF + buf * ABUFB + aStO) = l;
        }
        {
            uint4 h, l;
            split2(rb0.x, rb0.y, h.x, l.x);
            split2(rb0.z, rb0.w, h.y, l.y);
            split2(rb1.x, rb1.y, h.z, l.z);
            split2(rb1.z, rb1.w, h.w, l.w);
            *(uint4*)(base + BHI_OFF + buf * BBUFB + bStO[0]) = h;
            *(uint4*)(base + BLO_OFF + buf * BBUFB + bStO[0]) = l;
        }
        {
            uint4 h, l;
            split2(rb2.x, rb2.y, h.x, l.x);
            split2(rb2.z, rb2.w, h.y, l.y);
            split2(rb3.x, rb3.y, h.z, l.z);
            split2(rb3.z, rb3.w, h.w, l.w);
            *(uint4*)(base + BHI_OFF + buf * BBUFB + bStO[1]) = h;
            *(uint4*)(base + BLO_OFF + buf * BBUFB + bStO[1]) = l;
        }
    };

    float c[2][4][4];
#pragma unroll
    for (int mt = 0; mt < 2; mt++)
#pragma unroll
        for (int nt = 0; nt < 4; nt++)
#pragma unroll
            for (int r = 0; r < 4; r++) c[mt][nt][r] = 0.f;

    ldg(0);
    sts(0);
    __syncthreads();

    const int NT = EE / GBK;
    for (int t = 0; t < NT; t++) {
        if (t + 1 < NT) ldg(t + 1);
        const unsigned abo = (unsigned)(t & 1) * ABUFB;
        const unsigned bbo = (unsigned)(t & 1) * BBUFB;
#pragma unroll
        for (int ks = 0; ks < 2; ks++) {
            unsigned ah[2][4], al[2][4], bh[4][2], bl[4][2];
#pragma unroll
            for (int mt = 0; mt < 2; mt++) {
                unsigned ad = aRow[mt] + abo +
                              (unsigned)((((ks << 1) + a_kh) ^ aSw[mt]) << 4);
                ldsm4(ah[mt][0], ah[mt][1], ah[mt][2], ah[mt][3], ad);
                ldsm4(al[mt][0], al[mt][1], al[mt][2], al[mt][3],
                      ad + (ALO_OFF - AHI_OFF));
            }
#pragma unroll
            for (int p = 0; p < 2; p++) {
                unsigned bd = bRow[p] + bbo +
                              (unsigned)((((ks << 1) + b_kh) ^ bSw[p]) << 4);
                ldsm4(bh[2 * p][0], bh[2 * p][1], bh[2 * p + 1][0],
                      bh[2 * p + 1][1], bd);
                ldsm4(bl[2 * p][0], bl[2 * p][1], bl[2 * p + 1][0],
                      bl[2 * p + 1][1], bd + (BLO_OFF - BHI_OFF));
            }
#pragma unroll
            for (int mt = 0; mt < 2; mt++)
#pragma unroll
                for (int nt = 0; nt < 4; nt++)
                    mma_f16(c[mt][nt][0], c[mt][nt][1], c[mt][nt][2], c[mt][nt][3],
                            ah[mt][0], ah[mt][1], ah[mt][2], ah[mt][3],
                            bh[nt][0], bh[nt][1]);
#pragma unroll
            for (int mt = 0; mt < 2; mt++)
#pragma unroll
                for (int nt = 0; nt < 4; nt++)
                    mma_f16(c[mt][nt][0], c[mt][nt][1], c[mt][nt][2], c[mt][nt][3],
                            ah[mt][0], ah[mt][1], ah[mt][2], ah[mt][3],
                            bl[nt][0], bl[nt][1]);
#pragma unroll
            for (int mt = 0; mt < 2; mt++)
#pragma unroll
                for (int nt = 0; nt < 4; nt++)
                    mma_f16(c[mt][nt][0], c[mt][nt][1], c[mt][nt][2], c[mt][nt][3],
                            al[mt][0], al[mt][1], al[mt][2], al[mt][3],
                            bh[nt][0], bh[nt][1]);
        }
        __syncthreads();
        if (t + 1 < NT) {
            sts((t + 1) & 1);
            __syncthreads();
        }
    }

    const int g = lane >> 2;
    const int tc = lane & 3;
#pragma unroll
    for (int mt = 0; mt < 2; mt++)
#pragma unroll
        for (int nt = 0; nt < 4; nt++) {
            int col = n0 + wn + nt * 8 + tc * 2;
            float2 bbv = *(const float2*)&bias[col];
            float2 v0 = make_float2(c[mt][nt][0] + bbv.x, c[mt][nt][1] + bbv.y);
            float2 v1 = make_float2(c[mt][nt][2] + bbv.x, c[mt][nt][3] + bbv.y);
            int row = m0 + wm + mt * 16 + g;
            if (NOUT == 3) {
                int h = col >> 6, d = col & 63;
                int bi = row >> 11, tt0 = row & 2047;
                float* base = Y + (((size_t)bi * HH + h) * TT) * DD + d;
                *(float2*)&base[(size_t)tt0 * DD] = v0;
                *(float2*)&base[(size_t)(tt0 + 8) * DD] = v1;
            } else {
                *(float2*)&Y[(size_t)row * EE + col] = v0;
                *(float2*)&Y[(size_t)(row + 8) * EE + col] = v1;
            }
        }
}

// ---------------------------------------------------------------------------
// Attention v4 — q-tile 64, KR 192. 512 threads = 16 warps, 2 CTA/SM.
// QK: 48 m16n16 units = exactly 3/warp. PV: 32 m16n8 units = exactly 2/warp.
// Aliasing (bytes):
//   QH 0        QL 8192                     (64 x 128B, swz chunk^(r&7))
//   KH 16384    KL 40960   [区 16384..65536] (192 x 128B, same swz)
//     SS (f32 scores 64x192) aliases [16384..65536]   (after QK, via regs)
//     PTH 16384 PTL 40960  (P^T f16, 192 x 128B rows) (after topk, via regs)
//   VH 65536    VL 90112
//   KSQ 114688 (192 f32)   QSQ 115456 (64 f32)   total 115712
// PV: A = P^T via ldmatrix.x4.trans; B = V via ldmatrix.x2.trans (as R12).
// ---------------------------------------------------------------------------
#define AQT 64
#define AKR 192
#define AQH 0
#define AQL 8192
#define AKH 16384
#define AKL 40960
#define ASSF 4096        /* float index of byte 16384 */
#define APH 16384
#define APL 40960
#define AVH 65536
#define AVL 90112
#define AKSQF 28672      /* float index of byte 114688 */
#define AQSQF 28864      /* float index of byte 115456 */
#define ASMEM 115712

__global__ __launch_bounds__(512, 2) void attn_kernel(const float* __restrict__ log_sigma) {
    extern __shared__ char sma[];
    float* smf = (float*)sma;
    const unsigned sb = s2u(sma);

    const int q0 = blockIdx.x * AQT;
    const int h = blockIdx.y;
    const int b = blockIdx.z;
    const int tid = threadIdx.x;
    const int w = tid >> 5, l = tid & 31;

    const float* Qg = g_q + ((size_t)(b * HH + h) * TT) * DD;
    const float* Kg = g_k + ((size_t)(b * HH + h) * TT) * DD;
    const float* Vg = g_v + ((size_t)(b * HH + h) * TT) * DD;
    const float scale = -0.5f * expf(-2.f * log_sigma[h]);
    const float4 z4 = make_float4(0.f, 0.f, 0.f, 0.f);

    // ================= load + f16-split + norms =================
    for (int i = tid; i < 1536; i += 512) {   // K: 192 rows x 8 chunks
        int row = i >> 3, cc = i & 7;
        int gk = q0 - 128 + row;
        float4 f0 = z4, f1 = z4;
        if (gk >= 0) {
            f0 = *(const float4*)&Kg[(size_t)gk * DD + cc * 8];
            f1 = *(const float4*)&Kg[(size_t)gk * DD + cc * 8 + 4];
        }
        float p = f0.x * f0.x + f0.y * f0.y + f0.z * f0.z + f0.w * f0.w +
                  f1.x * f1.x + f1.y * f1.y + f1.z * f1.z + f1.w * f1.w;
        p += __shfl_xor_sync(0xffffffffu, p, 1);
        p += __shfl_xor_sync(0xffffffffu, p, 2);
        p += __shfl_xor_sync(0xffffffffu, p, 4);
        if (cc == 0) smf[AKSQF + row] = p;
        uint4 hh, ll;
        split2(f0.x, f0.y, hh.x, ll.x);
        split2(f0.z, f0.w, hh.y, ll.y);
        split2(f1.x, f1.y, hh.z, ll.z);
        split2(f1.z, f1.w, hh.w, ll.w);
        int off = row * 128 + ((cc ^ (row & 7)) << 4);
        *(uint4*)(sma + AKH + off) = hh;
        *(uint4*)(sma + AKL + off) = ll;
    }
    for (int i = tid; i < 1536; i += 512) {   // V
        int row = i >> 3, cc = i & 7;
        int gk = q0 - 128 + row;
        float4 f0 = z4, f1 = z4;
        if (gk >= 0) {
            f0 = *(const float4*)&Vg[(size_t)gk * DD + cc * 8];
            f1 = *(const float4*)&Vg[(size_t)gk * DD + cc * 8 + 4];
        }
        uint4 hh, ll;
        split2(f0.x, f0.y, hh.x, ll.x);
        split2(f0.z, f0.w, hh.y, ll.y);
        split2(f1.x, f1.y, hh.z, ll.z);
        split2(f1.z, f1.w, hh.w, ll.w);
        int off = row * 128 + ((cc ^ (row & 7)) << 4);
        *(uint4*)(sma + AVH + off) = hh;
        *(uint4*)(sma + AVL + off) = ll;
    }
    {   // Q: 64 rows x 8 chunks = 512
        int row = tid >> 3, cc = tid & 7;
        float4 f0 = *(const float4*)&Qg[(size_t)(q0 + row) * DD + cc * 8];
        float4 f1 = *(const float4*)&Qg[(size_t)(q0 + row) * DD + cc * 8 + 4];
        float p = f0.x * f0.x + f0.y * f0.y + f0.z * f0.z + f0.w * f0.w +
                  f1.x * f1.x + f1.y * f1.y + f1.z * f1.z + f1.w * f1.w;
        p += __shfl_xor_sync(0xffffffffu, p, 1);
        p += __shfl_xor_sync(0xffffffffu, p, 2);
        p += __shfl_xor_sync(0xffffffffu, p, 4);
        if (cc == 0) smf[AQSQF + row] = p;
        uint4 hh, ll;
        split2(f0.x, f0.y, hh.x, ll.x);
        split2(f0.z, f0.w, hh.y, ll.y);
        split2(f1.x, f1.y, hh.z, ll.z);
        split2(f1.z, f1.w, hh.w, ll.w);
        int off = row * 128 + ((cc ^ (row & 7)) << 4);
        *(uint4*)(sma + AQH + off) = hh;
        *(uint4*)(sma + AQL + off) = ll;
    }
    __syncthreads();

    // ================= QK^T MMA: 48 units, 3 per warp; scores to regs ======
    float sc[3][2][4];
    {
        const int a_m = (l & 7) + ((l >> 3) & 1) * 8;
        const int a_kh = l >> 4;
        const int b_nl = (l & 7) + (l >> 4) * 8;
        const int b_kh = (l >> 3) & 1;
#pragma unroll
        for (int i = 0; i < 3; i++) {
            const int u = w + 16 * i;
            const int mt = u / 12, ng = u % 12;
            float c[2][4];
#pragma unroll
            for (int j = 0; j < 2; j++)
#pragma unroll
                for (int r = 0; r < 4; r++) c[j][r] = 0.f;
            const int arow = mt * 16 + a_m;
            const unsigned aH = sb + AQH + (unsigned)arow * 128;
            const int asw = arow & 7;
            const int brow = ng * 16 + b_nl;
            const unsigned bH = sb + AKH + (unsigned)brow * 128;
            const int bsw = brow & 7;
#pragma unroll
            for (int ks = 0; ks < 4; ks++) {
                unsigned ah[4], al[4], bh[4], bl[4];
                unsigned aad = aH + (unsigned)(((2 * ks + a_kh) ^ asw) << 4);
                ldsm4(ah[0], ah[1], ah[2], ah[3], aad);
                ldsm4(al[0], al[1], al[2], al[3], aad + (AQL - AQH));
                unsigned bad = bH + (unsigned)(((2 * ks + b_kh) ^ bsw) << 4);
                ldsm4(bh[0], bh[1], bh[2], bh[3], bad);
                ldsm4(bl[0], bl[1], bl[2], bl[3], bad + (AKL - AKH));
                mma_f16(c[0][0], c[0][1], c[0][2], c[0][3],
                        ah[0], ah[1], ah[2], ah[3], bh[0], bh[1]);
                mma_f16(c[1][0], c[1][1], c[1][2], c[1][3],
                        ah[0], ah[1], ah[2], ah[3], bh[2], bh[3]);
                mma_f16(c[0][0], c[0][1], c[0][2], c[0][3],
                        ah[0], ah[1], ah[2], ah[3], bl[0], bl[1]);
                mma_f16(c[1][0], c[1][1], c[1][2], c[1][3],
                        ah[0], ah[1], ah[2], ah[3], bl[2], bl[3]);
                mma_f16(c[0][0], c[0][1], c[0][2], c[0][3],
                        al[0], al[1], al[2], al[3], bh[0], bh[1]);
                mma_f16(c[1][0], c[1][1], c[1][2], c[1][3],
                        al[0], al[1], al[2], al[3], bh[2], bh[3]);
            }
            const int r1 = mt * 16 + (l >> 2);
            const float qs1 = smf[AQSQF + r1];
            const float qs2 = smf[AQSQF + r1 + 8];
#pragma unroll
            for (int j = 0; j < 2; j++) {
                int cb = ng * 16 + j * 8 + 2 * (l & 3);
                float2 kq = *(const float2*)&smf[AKSQF + cb];
                sc[i][j][0] = (qs1 + kq.x - 2.f * c[j][0]) * scale;
                sc[i][j][1] = (qs1 + kq.y - 2.f * c[j][1]) * scale;
                sc[i][j][2] = (qs2 + kq.x - 2.f * c[j][2]) * scale;
                sc[i][j][3] = (qs2 + kq.y - 2.f * c[j][3]) * scale;
            }
        }
    }
    __syncthreads();   // all K-tile reads done; SS may overwrite K region

    // write scores (SS aliases K tiles)
#pragma unroll
    for (int i = 0; i < 3; i++) {
        const int u = w + 16 * i;
        const int mt = u / 12, ng = u % 12;
        const int r1 = mt * 16 + (l >> 2);
#pragma unroll
        for (int j = 0; j < 2; j++) {
            int cb = ng * 16 + j * 8 + 2 * (l & 3);
            *(float2*)&smf[ASSF + r1 * AKR + cb] =
                make_float2(sc[i][j][0], sc[i][j][1]);
            *(float2*)&smf[ASSF + (r1 + 8) * AKR + cb] =
                make_float2(sc[i][j][2], sc[i][j][3]);
        }
    }
    __syncthreads();

    // ================= top-k + softmax (warp = 4 queries) =================
    float ev[4][4];
    int slotr[4];
    {
        const int qbase = 4 * w;
        unsigned key[4][4];
#pragma unroll
        for (int q = 0; q < 4; q++) {
            const int qi = qbase + q;
            const int r0 = qi + 1 + l;
            slotr[q] = r0;
#pragma unroll
            for (int t = 0; t < 4; t++) {
                int r = r0 + 32 * t;
                float s = smf[ASSF + qi * AKR + r];
                bool valid = (q0 - 128 + r) >= 0;
                key[q][t] = valid ? f2ord(s) : 0u;
            }
        }
        __syncthreads();   // all SS reads done; PT may overwrite

        unsigned thr[4] = {0u, 0u, 0u, 0u};
#pragma unroll 1
        for (int bp = 31; bp >= 0; bp--) {
            unsigned pk = 0;
#pragma unroll
            for (int q = 0; q < 4; q++) {
                unsigned cand = thr[q] | (1u << bp);
                unsigned cnt = (key[q][0] >= cand ? 1u : 0u) +
                               (key[q][1] >= cand ? 1u : 0u) +
                               (key[q][2] >= cand ? 1u : 0u) +
                               (key[q][3] >= cand ? 1u : 0u);
                pk += cnt << (8 * q);
            }
            pk = __reduce_add_sync(0xffffffffu, pk);
#pragma unroll
            for (int q = 0; q < 4; q++)
                if (((pk >> (8 * q)) & 0xffu) >= TOPKK) thr[q] |= (1u << bp);
        }
#pragma unroll
        for (int q = 0; q < 4; q++)
            if (q0 + qbase + q < TOPKK) thr[q] = 0u;

        unsigned mx[4] = {0u, 0u, 0u, 0u};
        unsigned km[4][4];
#pragma unroll
        for (int q = 0; q < 4; q++)
#pragma unroll
            for (int t = 0; t < 4; t++) {
                unsigned k = key[q][t];
                unsigned kk = (k != 0u && k >= thr[q]) ? k : 0u;
                km[q][t] = kk;
                mx[q] = max(mx[q], kk);
            }
#pragma unroll
        for (int q = 0; q < 4; q++) mx[q] = __reduce_max_sync(0xffffffffu, mx[q]);

        float esum[4] = {0.f, 0.f, 0.f, 0.f};
#pragma unroll
        for (int q = 0; q < 4; q++) {
            float mv = ord2f(mx[q]);
#pragma unroll
            for (int t = 0; t < 4; t++) {
                float v = (km[q][t] != 0u) ? __expf(ord2f(km[q][t]) - mv) : 0.f;
                ev[q][t] = v;
                esum[q] += v;
            }
        }
#pragma unroll
        for (int o = 16; o > 0; o >>= 1) {
            esum[0] += __shfl_xor_sync(0xffffffffu, esum[0], o);
            esum[1] += __shfl_xor_sync(0xffffffffu, esum[1], o);
            esum[2] += __shfl_xor_sync(0xffffffffu, esum[2], o);
            esum[3] += __shfl_xor_sync(0xffffffffu, esum[3], o);
        }
#pragma unroll
        for (int q = 0; q < 4; q++) {
            float inv = 1.f / esum[q];
#pragma unroll
            for (int t = 0; t < 4; t++) ev[q][t] *= inv;
        }
    }

    // zero P^T (aliases SS), then scatter P values
    {
        int zb = APH + tid * 96;
#pragma unroll
        for (int k = 0; k < 6; k++)
            *(uint4*)(sma + zb + k * 16) = make_uint4(0u, 0u, 0u, 0u);
    }
    __syncthreads();
    {
        const int qbase = 4 * w;
#pragma unroll
        for (int q = 0; q < 4; q++) {
            const int qi = qbase + q;
            const int ccol = ((qi >> 3) << 4) + (qi & 7) * 2;  // pre-swizzle byte col
#pragma unroll
            for (int t = 0; t < 4; t++) {
                int r = slotr[q] + 32 * t;
                float v = ev[q][t];
                __half hv = __float2half_rn(v);
                __half lv = __float2half_rn(v - __half2float(hv));
                int off = r * 128 + (((qi >> 3) ^ (r & 7)) << 4) + (qi & 7) * 2;
                *(__half*)(sma + APH + off) = hv;
                *(__half*)(sma + APL + off) = lv;
            }
        }
    }
    __syncthreads();

    // ================= PV MMA: 32 units (m16 x n8), 2 per warp ============
#pragma unroll
    for (int i = 0; i < 2; i++) {
        const int u = w + 16 * i;
        const int mt = u >> 3;
        const int n8 = u & 7;
        float c0 = 0.f, c1 = 0.f, c2 = 0.f, c3 = 0.f;
        const int prow_in = (l & 7) + ((l >> 4) << 3);    // k-row within k16
        const int pchunk = 2 * mt + ((l >> 3) & 1);
        const int vlane = l & 15;
#pragma unroll
        for (int ks = 0; ks < 12; ks++) {
            unsigned ph[4], pl[4], vh0, vh1, vl0, vl1;
            int prow = ks * 16 + prow_in;
            unsigned pad = sb + APH + (unsigned)prow * 128 +
                           (unsigned)((pchunk ^ (prow & 7)) << 4);
            ldsm4t(ph[0], ph[1], ph[2], ph[3], pad);
            ldsm4t(pl[0], pl[1], pl[2], pl[3], pad + (APL - APH));
            int vrow = ks * 16 + vlane;
            unsigned vad = sb + AVH + (unsigned)vrow * 128 +
                           (unsigned)((n8 ^ (vrow & 7)) << 4);
            ldsm2t(vh0, vh1, vad);
            ldsm2t(vl0, vl1, vad + (AVL - AVH));
            mma_f16(c0, c1, c2, c3, ph[0], ph[1], ph[2], ph[3], vh0, vh1);
            mma_f16(c0, c1, c2, c3, pl[0], pl[1], pl[2], pl[3], vh0, vh1);
            mma_f16(c0, c1, c2, c3, ph[0], ph[1], ph[2], ph[3], vl0, vl1);
        }
        const int gq = q0 + mt * 16 + (l >> 2);
        const int colb = h * DD + n8 * 8 + 2 * (l & 3);
        *(float2*)&g_attn[((size_t)b * TT + gq) * EE + colb] = make_float2(c0, c1);
        *(float2*)&g_attn[((size_t)b * TT + gq + 8) * EE + colb] = make_float2(c2, c3);
    }
}

// ---------------------------------------------------------------------------
extern "C" void kernel_launch(void* const* d_in, const int* in_sizes, int n_in,
                              void* d_out, int out_size) {
    const float* x  = (const float*)d_in[0];
    const float* Wq = (const float*)d_in[1];
    const float* bq = (const float*)d_in[2];
    const float* Wk = (const float*)d_in[3];
    const float* bk = (const float*)d_in[4];
    const float* Wv = (const float*)d_in[5];
    const float* bv = (const float*)d_in[6];
    const float* Wo = (const float*)d_in[7];
    const float* bo = (const float*)d_in[8];
    const float* ls = (const float*)d_in[9];

    float *qp, *kp, *vp, *ap;
    cudaGetSymbolAddress((void**)&qp, g_q);
    cudaGetSymbolAddress((void**)&kp, g_k);
    cudaGetSymbolAddress((void**)&vp, g_v);
    cudaGetSymbolAddress((void**)&ap, g_attn);

    cudaFuncSetAttribute(gemmk<3>, cudaFuncAttributeMaxDynamicSharedMemorySize, SMEM_GEMM);
    cudaFuncSetAttribute(gemmk<1>, cudaFuncAttributeMaxDynamicSharedMemorySize, SMEM_GEMM);

    dim3 gqkv(BB * TT / GBM, EE / GBN, 3);  // 128 x 4 x 3
    gemmk<3><<<gqkv, 256, SMEM_GEMM>>>(x, Wq, bq, qp, Wk, bk, kp, Wv, bv, vp);

    cudaFuncSetAttribute(attn_kernel, cudaFuncAttributeMaxDynamicSharedMemorySize,
                         ASMEM);
    attn_kernel<<<dim3(TT / AQT, HH, BB), 512, ASMEM>>>(ls);

    dim3 go(BB * TT / GBM, EE / GBN);  // 128 x 4
    gemmk<1><<<go, 256, SMEM_GEMM>>>(ap, Wo, bo, (float*)d_out,
                                     nullptr, nullptr, nullptr, nullptr, nullptr, nullptr);
}

// round 14
// speedup vs baseline: 2.9330x; 1.0200x over previous
#include <cuda_runtime.h>
#include <cuda_fp16.h>
#include <math.h>

#define BB 4
#define HH 8
#define TT 2048
#define DD 64
#define EE 512
#define TOPKK 96

typedef unsigned long long ull;

// Scratch (device globals; no allocation allowed)
__device__ float g_q[(size_t)BB * HH * TT * DD];
__device__ float g_k[(size_t)BB * HH * TT * DD];
__device__ float g_v[(size_t)BB * HH * TT * DD];
__device__ __half g_xh[(size_t)BB * TT * EE];
__device__ __half g_xl[(size_t)BB * TT * EE];
__device__ __half g_wh[(size_t)4 * EE * EE];
__device__ __half g_wl[(size_t)4 * EE * EE];
__device__ __half g_ah[(size_t)BB * TT * EE];
__device__ __half g_al[(size_t)BB * TT * EE];

__device__ __forceinline__ unsigned f2ord(float f) {
    unsigned u = __float_as_uint(f);
    return (u & 0x80000000u) ? ~u : (u | 0x80000000u);
}
__device__ __forceinline__ float ord2f(unsigned k) {
    unsigned u = (k & 0x80000000u) ? (k & 0x7fffffffu) : ~k;
    return __uint_as_float(u);
}
__device__ __forceinline__ unsigned s2u(const void* p) {
    return (unsigned)__cvta_generic_to_shared(p);
}
__device__ __forceinline__ void ldsm4(unsigned& r0, unsigned& r1, unsigned& r2,
                                      unsigned& r3, unsigned addr) {
    asm volatile("ldmatrix.sync.aligned.m8n8.x4.shared.b16 {%0,%1,%2,%3}, [%4];"
                 : "=r"(r0), "=r"(r1), "=r"(r2), "=r"(r3) : "r"(addr));
}
__device__ __forceinline__ void ldsm4t(unsigned& r0, unsigned& r1, unsigned& r2,
                                       unsigned& r3, unsigned addr) {
    asm volatile("ldmatrix.sync.aligned.m8n8.x4.trans.shared.b16 {%0,%1,%2,%3}, [%4];"
                 : "=r"(r0), "=r"(r1), "=r"(r2), "=r"(r3) : "r"(addr));
}
__device__ __forceinline__ void ldsm2t(unsigned& r0, unsigned& r1, unsigned addr) {
    asm volatile("ldmatrix.sync.aligned.m8n8.x2.trans.shared.b16 {%0,%1}, [%2];"
                 : "=r"(r0), "=r"(r1) : "r"(addr));
}
__device__ __forceinline__ void mma_f16(float& c0, float& c1, float& c2, float& c3,
                                        unsigned a0, unsigned a1, unsigned a2,
                                        unsigned a3, unsigned b0, unsigned b1) {
    asm volatile(
        "mma.sync.aligned.m16n8k16.row.col.f32.f16.f16.f32 "
        "{%0,%1,%2,%3}, {%4,%5,%6,%7}, {%8,%9}, {%0,%1,%2,%3};"
        : "+f"(c0), "+f"(c1), "+f"(c2), "+f"(c3)
        : "r"(a0), "r"(a1), "r"(a2), "r"(a3), "r"(b0), "r"(b1));
}
__device__ __forceinline__ void split2(float x, float y, unsigned& h, unsigned& l) {
    __half2 h2 = __float22half2_rn(make_float2(x, y));
    float2 hf = __half22float2(h2);
    __half2 l2 = __float22half2_rn(make_float2(x - hf.x, y - hf.y));
    h = *(unsigned*)&h2;
    l = *(unsigned*)&l2;
}
__device__ __forceinline__ void cp16(unsigned s, const void* g) {
    asm volatile("cp.async.cg.shared.global [%0], [%1], 16;" :: "r"(s), "l"(g));
}

// ---------------------------------------------------------------------------
// Elementwise fp32 -> f16 hi/lo split (pre-pass; ~10us total for all inputs).
// ---------------------------------------------------------------------------
__global__ __launch_bounds__(256) void convk(const float* __restrict__ src,
                                             __half* __restrict__ dh,
                                             __half* __restrict__ dl, int n) {
    int i = (blockIdx.x * 256 + threadIdx.x) * 4;
    if (i < n) {
        float4 v = *(const float4*)(src + i);
        uint2 hh, ll;
        split2(v.x, v.y, hh.x, ll.x);
        split2(v.z, v.w, hh.y, ll.y);
        *(uint2*)(dh + i) = hh;
        *(uint2*)(dl + i) = ll;
    }
}

// ---------------------------------------------------------------------------
// 3xFP16 GEMM, pre-split f16 inputs, cp.async pipeline, 3 CTA/SM.
// Y = A @ W^T + bias, A = Ah+Al, W = Wh+Wl (f16 each).
// CTA 64m x 128n x 32k, 8 warps (2m x 4n), warp tile 32x32, m16n8k16.
// smem rows 64B (32 halves), chunk swizzle c ^ ((row>>1)&3) (R10-proven).
// ---------------------------------------------------------------------------
#define GBM 64
#define GBN 128
#define GBK 32
#define AHI_OFF 0
#define ALO_OFF 8192
#define BHI_OFF 16384
#define BLO_OFF 32768
#define SMEM_GEMM 49152
#define ABUFB 4096
#define BBUFB 8192

template <int NOUT>
__global__ __launch_bounds__(256, 3) void gemmk(
    const __half* __restrict__ Ah, const __half* __restrict__ Al,
    const __half* __restrict__ Wh0, const __half* __restrict__ Wl0,
    const float* __restrict__ bias0, float* __restrict__ Y0,
    const float* __restrict__ bias1, float* __restrict__ Y1,
    const float* __restrict__ bias2, float* __restrict__ Y2) {
    extern __shared__ char smg[];
    const unsigned sbase = s2u(smg);

    const __half* Wh = Wh0;
    const __half* Wl = Wl0;
    const float* bias;
    float* Y;
    if (NOUT == 3) {
        int z = blockIdx.z;
        Wh += (size_t)z * EE * EE;
        Wl += (size_t)z * EE * EE;
        bias = (z == 0) ? bias0 : (z == 1) ? bias1 : bias2;
        Y = (z == 0) ? Y0 : (z == 1) ? Y1 : Y2;
    } else {
        bias = bias0;
        Y = Y0;
    }

    const int m0 = blockIdx.x * GBM;
    const int n0 = blockIdx.y * GBN;
    const int tid = threadIdx.x;
    const int wid = tid >> 5;
    const int lane = tid & 31;
    const int wm = (wid & 1) * 32;
    const int wn = (wid >> 1) * 32;

    // cp.async staging mapping
    const int arow = tid >> 2, ac = tid & 3;          // A: 1 chunk / thread
    const int brow = tid >> 1, bc2 = (tid & 1) * 2;   // B: 2 chunks / thread
    const __half* aSrcH = Ah + (size_t)(m0 + arow) * EE + ac * 8;
    const __half* aSrcL = Al + (size_t)(m0 + arow) * EE + ac * 8;
    const __half* bSrcH = Wh + (size_t)(n0 + brow) * EE + bc2 * 8;
    const __half* bSrcL = Wl + (size_t)(n0 + brow) * EE + bc2 * 8;
    const unsigned aStO = (unsigned)(arow * 64 + ((ac ^ ((arow >> 1) & 3)) << 4));
    const unsigned bStO0 = (unsigned)(brow * 64 + ((bc2 ^ ((brow >> 1) & 3)) << 4));
    const unsigned bStO1 = (unsigned)(brow * 64 + (((bc2 + 1) ^ ((brow >> 1) & 3)) << 4));

    auto issue = [&](int t, int buf) {
        unsigned ao = (unsigned)buf * ABUFB;
        unsigned bo = (unsigned)buf * BBUFB;
        const int ko = t * GBK;
        cp16(sbase + AHI_OFF + ao + aStO, aSrcH + ko);
        cp16(sbase + ALO_OFF + ao + aStO, aSrcL + ko);
        cp16(sbase + BHI_OFF + bo + bStO0, bSrcH + ko);
        cp16(sbase + BHI_OFF + bo + bStO1, bSrcH + ko + 8);
        cp16(sbase + BLO_OFF + bo + bStO0, bSrcL + ko);
        cp16(sbase + BLO_OFF + bo + bStO1, bSrcL + ko + 8);
        asm volatile("cp.async.commit_group;");
    };

    // fragment ldmatrix lane addressing (R10-proven)
    const int a_m = (lane & 7) + ((lane >> 3) & 1) * 8;
    const int a_kh = lane >> 4;
    const int b_n = (lane & 7) + (lane >> 4) * 8;
    const int b_kh = (lane >> 3) & 1;
    unsigned aRow[2], bRow[2];
    int aSw[2], bSw[2];
#pragma unroll
    for (int mt = 0; mt < 2; mt++) {
        int r = wm + mt * 16 + a_m;
        aRow[mt] = sbase + AHI_OFF + (unsigned)r * 64;
        aSw[mt] = (r >> 1) & 3;
    }
#pragma unroll
    for (int p = 0; p < 2; p++) {
        int r = wn + p * 16 + b_n;
        bRow[p] = sbase + BHI_OFF + (unsigned)r * 64;
        bSw[p] = (r >> 1) & 3;
    }

    float c[2][4][4];
#pragma unroll
    for (int mt = 0; mt < 2; mt++)
#pragma unroll
        for (int nt = 0; nt < 4; nt++)
#pragma unroll
            for (int r = 0; r < 4; r++) c[mt][nt][r] = 0.f;

    issue(0, 0);
    const int NT = EE / GBK;  // 16
    for (int t = 0; t < NT; t++) {
        if (t + 1 < NT) {
            issue(t + 1, (t + 1) & 1);
            asm volatile("cp.async.wait_group 1;");
        } else {
            asm volatile("cp.async.wait_group 0;");
        }
        __syncthreads();
        const unsigned abo = (unsigned)(t & 1) * ABUFB;
        const unsigned bbo = (unsigned)(t & 1) * BBUFB;
#pragma unroll
        for (int ks = 0; ks < 2; ks++) {
            unsigned ah[2][4], al[2][4];
#pragma unroll
            for (int mt = 0; mt < 2; mt++) {
                unsigned ad = aRow[mt] + abo +
                              (unsigned)((((ks << 1) + a_kh) ^ aSw[mt]) << 4);
                ldsm4(ah[mt][0], ah[mt][1], ah[mt][2], ah[mt][3], ad);
                ldsm4(al[mt][0], al[mt][1], al[mt][2], al[mt][3],
                      ad + (ALO_OFF - AHI_OFF));
            }
#pragma unroll
            for (int p = 0; p < 2; p++) {
                unsigned bh0, bh1, bh2, bh3, bl0, bl1, bl2, bl3;
                unsigned bd = bRow[p] + bbo +
                              (unsigned)((((ks << 1) + b_kh) ^ bSw[p]) << 4);
                ldsm4(bh0, bh1, bh2, bh3, bd);
                ldsm4(bl0, bl1, bl2, bl3, bd + (BLO_OFF - BHI_OFF));
#pragma unroll
                for (int mt = 0; mt < 2; mt++) {
                    float* cp0 = c[mt][2 * p];
                    float* cp1 = c[mt][2 * p + 1];
                    mma_f16(cp0[0], cp0[1], cp0[2], cp0[3],
                            ah[mt][0], ah[mt][1], ah[mt][2], ah[mt][3], bh0, bh1);
                    mma_f16(cp1[0], cp1[1], cp1[2], cp1[3],
                            ah[mt][0], ah[mt][1], ah[mt][2], ah[mt][3], bh2, bh3);
                    mma_f16(cp0[0], cp0[1], cp0[2], cp0[3],
                            ah[mt][0], ah[mt][1], ah[mt][2], ah[mt][3], bl0, bl1);
                    mma_f16(cp1[0], cp1[1], cp1[2], cp1[3],
                            ah[mt][0], ah[mt][1], ah[mt][2], ah[mt][3], bl2, bl3);
                    mma_f16(cp0[0], cp0[1], cp0[2], cp0[3],
                            al[mt][0], al[mt][1], al[mt][2], al[mt][3], bh0, bh1);
                    mma_f16(cp1[0], cp1[1], cp1[2], cp1[3],
                            al[mt][0], al[mt][1], al[mt][2], al[mt][3], bh2, bh3);
                }
            }
        }
        __syncthreads();
    }

    const int g = lane >> 2;
    const int tc = lane & 3;
#pragma unroll
    for (int mt = 0; mt < 2; mt++)
#pragma unroll
        for (int nt = 0; nt < 4; nt++) {
            int col = n0 + wn + nt * 8 + tc * 2;
            float2 bbv = *(const float2*)&bias[col];
            float2 v0 = make_float2(c[mt][nt][0] + bbv.x, c[mt][nt][1] + bbv.y);
            float2 v1 = make_float2(c[mt][nt][2] + bbv.x, c[mt][nt][3] + bbv.y);
            int row = m0 + wm + mt * 16 + g;
            if (NOUT == 3) {
                int h = col >> 6, d = col & 63;
                int bi = row >> 11, tt0 = row & 2047;
                float* base = Y + (((size_t)bi * HH + h) * TT) * DD + d;
                *(float2*)&base[(size_t)tt0 * DD] = v0;
                *(float2*)&base[(size_t)(tt0 + 8) * DD] = v1;
            } else {
                *(float2*)&Y[(size_t)row * EE + col] = v0;
                *(float2*)&Y[(size_t)(row + 8) * EE + col] = v1;
            }
        }
}

// ---------------------------------------------------------------------------
// Attention v4 (R13, known passing) — only the epilogue changed: output is
// written as f16 hi/lo (g_ah/g_al) for the pre-split Wo GEMM.
// ---------------------------------------------------------------------------
#define AQT 64
#define AKR 192
#define AQH 0
#define AQL 8192
#define AKH 16384
#define AKL 40960
#define ASSF 4096
#define APH 16384
#define APL 40960
#define AVH 65536
#define AVL 90112
#define AKSQF 28672
#define AQSQF 28864
#define ASMEM 115712

__global__ __launch_bounds__(512, 2) void attn_kernel(const float* __restrict__ log_sigma) {
    extern __shared__ char sma[];
    float* smf = (float*)sma;
    const unsigned sb = s2u(sma);

    const int q0 = blockIdx.x * AQT;
    const int h = blockIdx.y;
    const int b = blockIdx.z;
    const int tid = threadIdx.x;
    const int w = tid >> 5, l = tid & 31;

    const float* Qg = g_q + ((size_t)(b * HH + h) * TT) * DD;
    const float* Kg = g_k + ((size_t)(b * HH + h) * TT) * DD;
    const float* Vg = g_v + ((size_t)(b * HH + h) * TT) * DD;
    const float scale = -0.5f * expf(-2.f * log_sigma[h]);
    const float4 z4 = make_float4(0.f, 0.f, 0.f, 0.f);

    for (int i = tid; i < 1536; i += 512) {
        int row = i >> 3, cc = i & 7;
        int gk = q0 - 128 + row;
        float4 f0 = z4, f1 = z4;
        if (gk >= 0) {
            f0 = *(const float4*)&Kg[(size_t)gk * DD + cc * 8];
            f1 = *(const float4*)&Kg[(size_t)gk * DD + cc * 8 + 4];
        }
        float p = f0.x * f0.x + f0.y * f0.y + f0.z * f0.z + f0.w * f0.w +
                  f1.x * f1.x + f1.y * f1.y + f1.z * f1.z + f1.w * f1.w;
        p += __shfl_xor_sync(0xffffffffu, p, 1);
        p += __shfl_xor_sync(0xffffffffu, p, 2);
        p += __shfl_xor_sync(0xffffffffu, p, 4);
        if (cc == 0) smf[AKSQF + row] = p;
        uint4 hh, ll;
        split2(f0.x, f0.y, hh.x, ll.x);
        split2(f0.z, f0.w, hh.y, ll.y);
        split2(f1.x, f1.y, hh.z, ll.z);
        split2(f1.z, f1.w, hh.w, ll.w);
        int off = row * 128 + ((cc ^ (row & 7)) << 4);
        *(uint4*)(sma + AKH + off) = hh;
        *(uint4*)(sma + AKL + off) = ll;
    }
    for (int i = tid; i < 1536; i += 512) {
        int row = i >> 3, cc = i & 7;
        int gk = q0 - 128 + row;
        float4 f0 = z4, f1 = z4;
        if (gk >= 0) {
            f0 = *(const float4*)&Vg[(size_t)gk * DD + cc * 8];
            f1 = *(const float4*)&Vg[(size_t)gk * DD + cc * 8 + 4];
        }
        uint4 hh, ll;
        split2(f0.x, f0.y, hh.x, ll.x);
        split2(f0.z, f0.w, hh.y, ll.y);
        split2(f1.x, f1.y, hh.z, ll.z);
        split2(f1.z, f1.w, hh.w, ll.w);
        int off = row * 128 + ((cc ^ (row & 7)) << 4);
        *(uint4*)(sma + AVH + off) = hh;
        *(uint4*)(sma + AVL + off) = ll;
    }
    {
        int row = tid >> 3, cc = tid & 7;
        float4 f0 = *(const float4*)&Qg[(size_t)(q0 + row) * DD + cc * 8];
        float4 f1 = *(const float4*)&Qg[(size_t)(q0 + row) * DD + cc * 8 + 4];
        float p = f0.x * f0.x + f0.y * f0.y + f0.z * f0.z + f0.w * f0.w +
                  f1.x * f1.x + f1.y * f1.y + f1.z * f1.z + f1.w * f1.w;
        p += __shfl_xor_sync(0xffffffffu, p, 1);
        p += __shfl_xor_sync(0xffffffffu, p, 2);
        p += __shfl_xor_sync(0xffffffffu, p, 4);
        if (cc == 0) smf[AQSQF + row] = p;
        uint4 hh, ll;
        split2(f0.x, f0.y, hh.x, ll.x);
        split2(f0.z, f0.w, hh.y, ll.y);
        split2(f1.x, f1.y, hh.z, ll.z);
        split2(f1.z, f1.w, hh.w, ll.w);
        int off = row * 128 + ((cc ^ (row & 7)) << 4);
        *(uint4*)(sma + AQH + off) = hh;
        *(uint4*)(sma + AQL + off) = ll;
    }
    __syncthreads();

    float sc[3][2][4];
    {
        const int a_m = (l & 7) + ((l >> 3) & 1) * 8;
        const int a_kh = l >> 4;
        const int b_nl = (l & 7) + (l >> 4) * 8;
        const int b_kh = (l >> 3) & 1;
#pragma unroll
        for (int i = 0; i < 3; i++) {
            const int u = w + 16 * i;
            const int mt = u / 12, ng = u % 12;
            float c[2][4];
#pragma unroll
            for (int j = 0; j < 2; j++)
#pragma unroll
                for (int r = 0; r < 4; r++) c[j][r] = 0.f;
            const int arow = mt * 16 + a_m;
            const unsigned aH = sb + AQH + (unsigned)arow * 128;
            const int asw = arow & 7;
            const int brow = ng * 16 + b_nl;
            const unsigned bH = sb + AKH + (unsigned)brow * 128;
            const int bsw = brow & 7;
#pragma unroll
            for (int ks = 0; ks < 4; ks++) {
                unsigned ah[4], al[4], bh[4], bl[4];
                unsigned aad = aH + (unsigned)(((2 * ks + a_kh) ^ asw) << 4);
                ldsm4(ah[0], ah[1], ah[2], ah[3], aad);
                ldsm4(al[0], al[1], al[2], al[3], aad + (AQL - AQH));
                unsigned bad = bH + (unsigned)(((2 * ks + b_kh) ^ bsw) << 4);
                ldsm4(bh[0], bh[1], bh[2], bh[3], bad);
                ldsm4(bl[0], bl[1], bl[2], bl[3], bad + (AKL - AKH));
                mma_f16(c[0][0], c[0][1], c[0][2], c[0][3],
                        ah[0], ah[1], ah[2], ah[3], bh[0], bh[1]);
                mma_f16(c[1][0], c[1][1], c[1][2], c[1][3],
                        ah[0], ah[1], ah[2], ah[3], bh[2], bh[3]);
                mma_f16(c[0][0], c[0][1], c[0][2], c[0][3],
                        ah[0], ah[1], ah[2], ah[3], bl[0], bl[1]);
                mma_f16(c[1][0], c[1][1], c[1][2], c[1][3],
                        ah[0], ah[1], ah[2], ah[3], bl[2], bl[3]);
                mma_f16(c[0][0], c[0][1], c[0][2], c[0][3],
                        al[0], al[1], al[2], al[3], bh[0], bh[1]);
                mma_f16(c[1][0], c[1][1], c[1][2], c[1][3],
                        al[0], al[1], al[2], al[3], bh[2], bh[3]);
            }
            const int r1 = mt * 16 + (l >> 2);
            const float qs1 = smf[AQSQF + r1];
            const float qs2 = smf[AQSQF + r1 + 8];
#pragma unroll
            for (int j = 0; j < 2; j++) {
                int cb = ng * 16 + j * 8 + 2 * (l & 3);
                float2 kq = *(const float2*)&smf[AKSQF + cb];
                sc[i][j][0] = (qs1 + kq.x - 2.f * c[j][0]) * scale;
                sc[i][j][1] = (qs1 + kq.y - 2.f * c[j][1]) * scale;
                sc[i][j][2] = (qs2 + kq.x - 2.f * c[j][2]) * scale;
                sc[i][j][3] = (qs2 + kq.y - 2.f * c[j][3]) * scale;
            }
        }
    }
    __syncthreads();

#pragma unroll
    for (int i = 0; i < 3; i++) {
        const int u = w + 16 * i;
        const int mt = u / 12, ng = u % 12;
        const int r1 = mt * 16 + (l >> 2);
#pragma unroll
        for (int j = 0; j < 2; j++) {
            int cb = ng * 16 + j * 8 + 2 * (l & 3);
            *(float2*)&smf[ASSF + r1 * AKR + cb] =
                make_float2(sc[i][j][0], sc[i][j][1]);
            *(float2*)&smf[ASSF + (r1 + 8) * AKR + cb] =
                make_float2(sc[i][j][2], sc[i][j][3]);
        }
    }
    __syncthreads();

    float ev[4][4];
    int slotr[4];
    {
        const int qbase = 4 * w;
        unsigned key[4][4];
#pragma unroll
        for (int q = 0; q < 4; q++) {
            const int qi = qbase + q;
            const int r0 = qi + 1 + l;
            slotr[q] = r0;
#pragma unroll
            for (int t = 0; t < 4; t++) {
                int r = r0 + 32 * t;
                float s = smf[ASSF + qi * AKR + r];
                bool valid = (q0 - 128 + r) >= 0;
                key[q][t] = valid ? f2ord(s) : 0u;
            }
        }
        __syncthreads();

        unsigned thr[4] = {0u, 0u, 0u, 0u};
#pragma unroll 1
        for (int bp = 31; bp >= 0; bp--) {
            unsigned pk = 0;
#pragma unroll
            for (int q = 0; q < 4; q++) {
                unsigned cand = thr[q] | (1u << bp);
                unsigned cnt = (key[q][0] >= cand ? 1u : 0u) +
                               (key[q][1] >= cand ? 1u : 0u) +
                               (key[q][2] >= cand ? 1u : 0u) +
                               (key[q][3] >= cand ? 1u : 0u);
                pk += cnt << (8 * q);
            }
            pk = __reduce_add_sync(0xffffffffu, pk);
#pragma unroll
            for (int q = 0; q < 4; q++)
                if (((pk >> (8 * q)) & 0xffu) >= TOPKK) thr[q] |= (1u << bp);
        }
#pragma unroll
        for (int q = 0; q < 4; q++)
            if (q0 + qbase + q < TOPKK) thr[q] = 0u;

        unsigned mx[4] = {0u, 0u, 0u, 0u};
        unsigned km[4][4];
#pragma unroll
        for (int q = 0; q < 4; q++)
#pragma unroll
            for (int t = 0; t < 4; t++) {
                unsigned k = key[q][t];
                unsigned kk = (k != 0u && k >= thr[q]) ? k : 0u;
                km[q][t] = kk;
                mx[q] = max(mx[q], kk);
            }
#pragma unroll
        for (int q = 0; q < 4; q++) mx[q] = __reduce_max_sync(0xffffffffu, mx[q]);

        float esum[4] = {0.f, 0.f, 0.f, 0.f};
#pragma unroll
        for (int q = 0; q < 4; q++) {
            float mv = ord2f(mx[q]);
#pragma unroll
            for (int t = 0; t < 4; t++) {
                float v = (km[q][t] != 0u) ? __expf(ord2f(km[q][t]) - mv) : 0.f;
                ev[q][t] = v;
                esum[q] += v;
            }
        }
#pragma unroll
        for (int o = 16; o > 0; o >>= 1) {
            esum[0] += __shfl_xor_sync(0xffffffffu, esum[0], o);
            esum[1] += __shfl_xor_sync(0xffffffffu, esum[1], o);
            esum[2] += __shfl_xor_sync(0xffffffffu, esum[2], o);
            esum[3] += __shfl_xor_sync(0xffffffffu, esum[3], o);
        }
#pragma unroll
        for (int q = 0; q < 4; q++) {
            float inv = 1.f / esum[q];
#pragma unroll
            for (int t = 0; t < 4; t++) ev[q][t] *= inv;
        }
    }

    {
        int zb = APH + tid * 96;
#pragma unroll
        for (int k = 0; k < 6; k++)
            *(uint4*)(sma + zb + k * 16) = make_uint4(0u, 0u, 0u, 0u);
    }
    __syncthreads();
    {
        const int qbase = 4 * w;
#pragma unroll
        for (int q = 0; q < 4; q++) {
            const int qi = qbase + q;
#pragma unroll
            for (int t = 0; t < 4; t++) {
                int r = slotr[q] + 32 * t;
                float v = ev[q][t];
                __half hv = __float2half_rn(v);
                __half lv = __float2half_rn(v - __half2float(hv));
                int off = r * 128 + (((qi >> 3) ^ (r & 7)) << 4) + (qi & 7) * 2;
                *(__half*)(sma + APH + off) = hv;
                *(__half*)(sma + APL + off) = lv;
            }
        }
    }
    __syncthreads();

#pragma unroll
    for (int i = 0; i < 2; i++) {
        const int u = w + 16 * i;
        const int mt = u >> 3;
        const int n8 = u & 7;
        float c0 = 0.f, c1 = 0.f, c2 = 0.f, c3 = 0.f;
        const int prow_in = (l & 7) + ((l >> 4) << 3);
        const int pchunk = 2 * mt + ((l >> 3) & 1);
        const int vlane = l & 15;
#pragma unroll
        for (int ks = 0; ks < 12; ks++) {
            unsigned ph[4], pl[4], vh0, vh1, vl0, vl1;
            int prow = ks * 16 + prow_in;
            unsigned pad = sb + APH + (unsigned)prow * 128 +
                           (unsigned)((pchunk ^ (prow & 7)) << 4);
            ldsm4t(ph[0], ph[1], ph[2], ph[3], pad);
            ldsm4t(pl[0], pl[1], pl[2], pl[3], pad + (APL - APH));
            int vrow = ks * 16 + vlane;
            unsigned vad = sb + AVH + (unsigned)vrow * 128 +
                           (unsigned)((n8 ^ (vrow & 7)) << 4);
            ldsm2t(vh0, vh1, vad);
            ldsm2t(vl0, vl1, vad + (AVL - AVH));
            mma_f16(c0, c1, c2, c3, ph[0], ph[1], ph[2], ph[3], vh0, vh1);
            mma_f16(c0, c1, c2, c3, pl[0], pl[1], pl[2], pl[3], vh0, vh1);
            mma_f16(c0, c1, c2, c3, ph[0], ph[1], ph[2], ph[3], vl0, vl1);
        }
        const int gq = q0 + mt * 16 + (l >> 2);
        const int colb = h * DD + n8 * 8 + 2 * (l & 3);
        // write output as f16 hi/lo (pre-split input for the Wo GEMM)
        unsigned h01, l01, h23, l23;
        split2(c0, c1, h01, l01);
        split2(c2, c3, h23, l23);
        size_t o1 = ((size_t)b * TT + gq) * EE + colb;
        size_t o2 = ((size_t)b * TT + gq + 8) * EE + colb;
        *(unsigned*)&g_ah[o1] = h01;
        *(unsigned*)&g_al[o1] = l01;
        *(unsigned*)&g_ah[o2] = h23;
        *(unsigned*)&g_al[o2] = l23;
    }
}

// ---------------------------------------------------------------------------
extern "C" void kernel_launch(void* const* d_in, const int* in_sizes, int n_in,
                              void* d_out, int out_size) {
    const float* x  = (const float*)d_in[0];
    const float* Wq = (const float*)d_in[1];
    const float* bq = (const float*)d_in[2];
    const float* Wk = (const float*)d_in[3];
    const float* bk = (const float*)d_in[4];
    const float* Wv = (const float*)d_in[5];
    const float* bv = (const float*)d_in[6];
    const float* Wo = (const float*)d_in[7];
    const float* bo = (const float*)d_in[8];
    const float* ls = (const float*)d_in[9];

    float *qp, *kp, *vp;
    __half *xh, *xl, *wh, *wl, *ah, *al;
    cudaGetSymbolAddress((void**)&qp, g_q);
    cudaGetSymbolAddress((void**)&kp, g_k);
    cudaGetSymbolAddress((void**)&vp, g_v);
    cudaGetSymbolAddress((void**)&xh, g_xh);
    cudaGetSymbolAddress((void**)&xl, g_xl);
    cudaGetSymbolAddress((void**)&wh, g_wh);
    cudaGetSymbolAddress((void**)&wl, g_wl);
    cudaGetSymbolAddress((void**)&ah, g_ah);
    cudaGetSymbolAddress((void**)&al, g_al);

    // pre-split inputs to f16 hi/lo
    const int NX = BB * TT * EE;      // 4194304
    const int NW = EE * EE;           // 262144
    convk<<<NX / 4 / 256, 256>>>(x, xh, xl, NX);
    convk<<<NW / 4 / 256, 256>>>(Wq, wh, wl, NW);
    convk<<<NW / 4 / 256, 256>>>(Wk, wh + (size_t)NW, wl + (size_t)NW, NW);
    convk<<<NW / 4 / 256, 256>>>(Wv, wh + (size_t)2 * NW, wl + (size_t)2 * NW, NW);
    convk<<<NW / 4 / 256, 256>>>(Wo, wh + (size_t)3 * NW, wl + (size_t)3 * NW, NW);

    cudaFuncSetAttribute(gemmk<3>, cudaFuncAttributeMaxDynamicSharedMemorySize, SMEM_GEMM);
    cudaFuncSetAttribute(gemmk<1>, cudaFuncAttributeMaxDynamicSharedMemorySize, SMEM_GEMM);

    dim3 gqkv(BB * TT / GBM, EE / GBN, 3);  // 128 x 4 x 3
    gemmk<3><<<gqkv, 256, SMEM_GEMM>>>(xh, xl, wh, wl, bq, qp, bk, kp, bv, vp);

    cudaFuncSetAttribute(attn_kernel, cudaFuncAttributeMaxDynamicSharedMemorySize,
                         ASMEM);
    attn_kernel<<<dim3(TT / AQT, HH, BB), 512, ASMEM>>>(ls);

    dim3 go(BB * TT / GBM, EE / GBN);  // 128 x 4
    gemmk<1><<<go, 256, SMEM_GEMM>>>(ah, al, wh + (size_t)3 * NW, wl + (size_t)3 * NW,
                                     bo, (float*)d_out, nullptr, nullptr,
                                     nullptr, nullptr);
}

// round 16
// speedup vs baseline: 3.2125x; 1.0953x over previous
#include <cuda_runtime.h>
#include <cuda_fp16.h>
#include <math.h>

#define BB 4
#define HH 8
#define TT 2048
#define DD 64
#define EE 512
#define TOPKK 96

typedef unsigned long long ull;

// Scratch (device globals; no allocation allowed)
__device__ float g_q[(size_t)BB * HH * TT * DD];
__device__ float g_k[(size_t)BB * HH * TT * DD];
__device__ float g_v[(size_t)BB * HH * TT * DD];
__device__ __half g_xh[(size_t)BB * TT * EE];
__device__ __half g_xl[(size_t)BB * TT * EE];
__device__ __half g_wh[(size_t)4 * EE * EE];
__device__ __half g_wl[(size_t)4 * EE * EE];
__device__ __half g_ah[(size_t)BB * TT * EE];
__device__ __half g_al[(size_t)BB * TT * EE];

__device__ __forceinline__ unsigned f2ord(float f) {
    unsigned u = __float_as_uint(f);
    return (u & 0x80000000u) ? ~u : (u | 0x80000000u);
}
__device__ __forceinline__ float ord2f(unsigned k) {
    unsigned u = (k & 0x80000000u) ? (k & 0x7fffffffu) : ~k;
    return __uint_as_float(u);
}
__device__ __forceinline__ unsigned s2u(const void* p) {
    return (unsigned)__cvta_generic_to_shared(p);
}
__device__ __forceinline__ void ldsm4(unsigned& r0, unsigned& r1, unsigned& r2,
                                      unsigned& r3, unsigned addr) {
    asm volatile("ldmatrix.sync.aligned.m8n8.x4.shared.b16 {%0,%1,%2,%3}, [%4];"
                 : "=r"(r0), "=r"(r1), "=r"(r2), "=r"(r3) : "r"(addr));
}
__device__ __forceinline__ void ldsm4t(unsigned& r0, unsigned& r1, unsigned& r2,
                                       unsigned& r3, unsigned addr) {
    asm volatile("ldmatrix.sync.aligned.m8n8.x4.trans.shared.b16 {%0,%1,%2,%3}, [%4];"
                 : "=r"(r0), "=r"(r1), "=r"(r2), "=r"(r3) : "r"(addr));
}
__device__ __forceinline__ void ldsm2t(unsigned& r0, unsigned& r1, unsigned addr) {
    asm volatile("ldmatrix.sync.aligned.m8n8.x2.trans.shared.b16 {%0,%1}, [%2];"
                 : "=r"(r0), "=r"(r1) : "r"(addr));
}
__device__ __forceinline__ void mma_f16(float& c0, float& c1, float& c2, float& c3,
                                        unsigned a0, unsigned a1, unsigned a2,
                                        unsigned a3, unsigned b0, unsigned b1) {
    asm volatile(
        "mma.sync.aligned.m16n8k16.row.col.f32.f16.f16.f32 "
        "{%0,%1,%2,%3}, {%4,%5,%6,%7}, {%8,%9}, {%0,%1,%2,%3};"
        : "+f"(c0), "+f"(c1), "+f"(c2), "+f"(c3)
        : "r"(a0), "r"(a1), "r"(a2), "r"(a3), "r"(b0), "r"(b1));
}
__device__ __forceinline__ void split2(float x, float y, unsigned& h, unsigned& l) {
    __half2 h2 = __float22half2_rn(make_float2(x, y));
    float2 hf = __half22float2(h2);
    __half2 l2 = __float22half2_rn(make_float2(x - hf.x, y - hf.y));
    h = *(unsigned*)&h2;
    l = *(unsigned*)&l2;
}
__device__ __forceinline__ void cp16(unsigned s, const void* g) {
    asm volatile("cp.async.cg.shared.global [%0], [%1], 16;" :: "r"(s), "l"(g));
}

// ---------------------------------------------------------------------------
// fp32 -> f16 hi/lo split pre-pass. convk: x. convw4: all 4 weights, 1 launch.
// ---------------------------------------------------------------------------
__global__ __launch_bounds__(256) void convk(const float* __restrict__ src,
                                             __half* __restrict__ dh,
                                             __half* __restrict__ dl, int n) {
    int i = (blockIdx.x * 256 + threadIdx.x) * 4;
    if (i < n) {
        float4 v = *(const float4*)(src + i);
        uint2 hh, ll;
        split2(v.x, v.y, hh.x, ll.x);
        split2(v.z, v.w, hh.y, ll.y);
        *(uint2*)(dh + i) = hh;
        *(uint2*)(dl + i) = ll;
    }
}
__global__ __launch_bounds__(256) void convw4(
    const float* __restrict__ s0, const float* __restrict__ s1,
    const float* __restrict__ s2, const float* __restrict__ s3,
    __half* __restrict__ dh, __half* __restrict__ dl, int n) {
    int z = blockIdx.y;
    const float* s = (z == 0) ? s0 : (z == 1) ? s1 : (z == 2) ? s2 : s3;
    size_t off = (size_t)z * n;
    int i = (blockIdx.x * 256 + threadIdx.x) * 4;
    if (i < n) {
        float4 v = *(const float4*)(s + i);
        uint2 hh, ll;
        split2(v.x, v.y, hh.x, ll.x);
        split2(v.z, v.w, hh.y, ll.y);
        *(uint2*)(dh + off + i) = hh;
        *(uint2*)(dl + off + i) = ll;
    }
}

// ---------------------------------------------------------------------------
// FP16-split GEMM, pre-split f16 inputs, cp.async pipeline (R14 base).
// Term policy: Q/K projections use 3 terms (AhBh+AhBl+AlBh); V projection
// (z==2) and the Wo GEMM (NOUT==1) drop AlBh — linear paths, no top-k
// amplification, error ~3e-4 random.
// ---------------------------------------------------------------------------
#define GBM 64
#define GBN 128
#define GBK 32
#define AHI_OFF 0
#define ALO_OFF 8192
#define BHI_OFF 16384
#define BLO_OFF 32768
#define SMEM_GEMM 49152
#define ABUFB 4096
#define BBUFB 8192

template <int NOUT>
__global__ __launch_bounds__(256, 3) void gemmk(
    const __half* __restrict__ Ah, const __half* __restrict__ Al,
    const __half* __restrict__ Wh0, const __half* __restrict__ Wl0,
    const float* __restrict__ bias0, float* __restrict__ Y0,
    const float* __restrict__ bias1, float* __restrict__ Y1,
    const float* __restrict__ bias2, float* __restrict__ Y2) {
    extern __shared__ char smg[];
    const unsigned sbase = s2u(smg);

    const __half* Wh = Wh0;
    const __half* Wl = Wl0;
    const float* bias;
    float* Y;
    bool t3;
    if (NOUT == 3) {
        int z = blockIdx.z;
        Wh += (size_t)z * EE * EE;
        Wl += (size_t)z * EE * EE;
        bias = (z == 0) ? bias0 : (z == 1) ? bias1 : bias2;
        Y = (z == 0) ? Y0 : (z == 1) ? Y1 : Y2;
        t3 = (z != 2);
    } else {
        bias = bias0;
        Y = Y0;
        t3 = false;
    }

    const int m0 = blockIdx.x * GBM;
    const int n0 = blockIdx.y * GBN;
    const int tid = threadIdx.x;
    const int wid = tid >> 5;
    const int lane = tid & 31;
    const int wm = (wid & 1) * 32;
    const int wn = (wid >> 1) * 32;

    const int arow = tid >> 2, ac = tid & 3;
    const int brow = tid >> 1, bc2 = (tid & 1) * 2;
    const __half* aSrcH = Ah + (size_t)(m0 + arow) * EE + ac * 8;
    const __half* aSrcL = Al + (size_t)(m0 + arow) * EE + ac * 8;
    const __half* bSrcH = Wh + (size_t)(n0 + brow) * EE + bc2 * 8;
    const __half* bSrcL = Wl + (size_t)(n0 + brow) * EE + bc2 * 8;
    const unsigned aStO = (unsigned)(arow * 64 + ((ac ^ ((arow >> 1) & 3)) << 4));
    const unsigned bStO0 = (unsigned)(brow * 64 + ((bc2 ^ ((brow >> 1) & 3)) << 4));
    const unsigned bStO1 = (unsigned)(brow * 64 + (((bc2 + 1) ^ ((brow >> 1) & 3)) << 4));

    auto issue = [&](int t, int buf) {
        unsigned ao = (unsigned)buf * ABUFB;
        unsigned bo = (unsigned)buf * BBUFB;
        const int ko = t * GBK;
        cp16(sbase + AHI_OFF + ao + aStO, aSrcH + ko);
        cp16(sbase + ALO_OFF + ao + aStO, aSrcL + ko);
        cp16(sbase + BHI_OFF + bo + bStO0, bSrcH + ko);
        cp16(sbase + BHI_OFF + bo + bStO1, bSrcH + ko + 8);
        cp16(sbase + BLO_OFF + bo + bStO0, bSrcL + ko);
        cp16(sbase + BLO_OFF + bo + bStO1, bSrcL + ko + 8);
        asm volatile("cp.async.commit_group;");
    };

    const int a_m = (lane & 7) + ((lane >> 3) & 1) * 8;
    const int a_kh = lane >> 4;
    const int b_n = (lane & 7) + (lane >> 4) * 8;
    const int b_kh = (lane >> 3) & 1;
    unsigned aRow[2], bRow[2];
    int aSw[2], bSw[2];
#pragma unroll
    for (int mt = 0; mt < 2; mt++) {
        int r = wm + mt * 16 + a_m;
        aRow[mt] = sbase + AHI_OFF + (unsigned)r * 64;
        aSw[mt] = (r >> 1) & 3;
    }
#pragma unroll
    for (int p = 0; p < 2; p++) {
        int r = wn + p * 16 + b_n;
        bRow[p] = sbase + BHI_OFF + (unsigned)r * 64;
        bSw[p] = (r >> 1) & 3;
    }

    float c[2][4][4];
#pragma unroll
    for (int mt = 0; mt < 2; mt++)
#pragma unroll
        for (int nt = 0; nt < 4; nt++)
#pragma unroll
            for (int r = 0; r < 4; r++) c[mt][nt][r] = 0.f;

    issue(0, 0);
    const int NT = EE / GBK;  // 16
    for (int t = 0; t < NT; t++) {
        if (t + 1 < NT) {
            issue(t + 1, (t + 1) & 1);
            asm volatile("cp.async.wait_group 1;");
        } else {
            asm volatile("cp.async.wait_group 0;");
        }
        __syncthreads();
        const unsigned abo = (unsigned)(t & 1) * ABUFB;
        const unsigned bbo = (unsigned)(t & 1) * BBUFB;
#pragma unroll
        for (int ks = 0; ks < 2; ks++) {
            unsigned ah[2][4], al[2][4];
#pragma unroll
            for (int mt = 0; mt < 2; mt++) {
                unsigned ad = aRow[mt] + abo +
                              (unsigned)((((ks << 1) + a_kh) ^ aSw[mt]) << 4);
                ldsm4(ah[mt][0], ah[mt][1], ah[mt][2], ah[mt][3], ad);
                ldsm4(al[mt][0], al[mt][1], al[mt][2], al[mt][3],
                      ad + (ALO_OFF - AHI_OFF));
            }
#pragma unroll
            for (int p = 0; p < 2; p++) {
                unsigned bh0, bh1, bh2, bh3, bl0, bl1, bl2, bl3;
                unsigned bd = bRow[p] + bbo +
                              (unsigned)((((ks << 1) + b_kh) ^ bSw[p]) << 4);
                ldsm4(bh0, bh1, bh2, bh3, bd);
                ldsm4(bl0, bl1, bl2, bl3, bd + (BLO_OFF - BHI_OFF));
#pragma unroll
                for (int mt = 0; mt < 2; mt++) {
                    float* cp0 = c[mt][2 * p];
                    float* cp1 = c[mt][2 * p + 1];
                    mma_f16(cp0[0], cp0[1], cp0[2], cp0[3],
                            ah[mt][0], ah[mt][1], ah[mt][2], ah[mt][3], bh0, bh1);
                    mma_f16(cp1[0], cp1[1], cp1[2], cp1[3],
                            ah[mt][0], ah[mt][1], ah[mt][2], ah[mt][3], bh2, bh3);
                    mma_f16(cp0[0], cp0[1], cp0[2], cp0[3],
                            ah[mt][0], ah[mt][1], ah[mt][2], ah[mt][3], bl0, bl1);
                    mma_f16(cp1[0], cp1[1], cp1[2], cp1[3],
                            ah[mt][0], ah[mt][1], ah[mt][2], ah[mt][3], bl2, bl3);
                }
                if (t3) {
#pragma unroll
                    for (int mt = 0; mt < 2; mt++) {
                        float* cp0 = c[mt][2 * p];
                        float* cp1 = c[mt][2 * p + 1];
                        mma_f16(cp0[0], cp0[1], cp0[2], cp0[3],
                                al[mt][0], al[mt][1], al[mt][2], al[mt][3], bh0, bh1);
                        mma_f16(cp1[0], cp1[1], cp1[2], cp1[3],
                                al[mt][0], al[mt][1], al[mt][2], al[mt][3], bh2, bh3);
                    }
                }
            }
        }
        __syncthreads();
    }

    const int g = lane >> 2;
    const int tc = lane & 3;
#pragma unroll
    for (int mt = 0; mt < 2; mt++)
#pragma unroll
        for (int nt = 0; nt < 4; nt++) {
            int col = n0 + wn + nt * 8 + tc * 2;
            float2 bbv = *(const float2*)&bias[col];
            float2 v0 = make_float2(c[mt][nt][0] + bbv.x, c[mt][nt][1] + bbv.y);
            float2 v1 = make_float2(c[mt][nt][2] + bbv.x, c[mt][nt][3] + bbv.y);
            int row = m0 + wm + mt * 16 + g;
            if (NOUT == 3) {
                int h = col >> 6, d = col & 63;
                int bi = row >> 11, tt0 = row & 2047;
                float* base = Y + (((size_t)bi * HH + h) * TT) * DD + d;
                *(float2*)&base[(size_t)tt0 * DD] = v0;
                *(float2*)&base[(size_t)(tt0 + 8) * DD] = v1;
            } else {
                *(float2*)&Y[(size_t)row * EE + col] = v0;
                *(float2*)&Y[(size_t)(row + 8) * EE + col] = v1;
            }
        }
}

// ---------------------------------------------------------------------------
// Attention v4 (R14 base). Changes: top-k starts at bit 30 (bit 31 provably 0)
// and early-exits when a query's count hits exactly 96 (provably exact).
// ---------------------------------------------------------------------------
#define AQT 64
#define AKR 192
#define AQH 0
#define AQL 8192
#define AKH 16384
#define AKL 40960
#define ASSF 4096
#define APH 16384
#define APL 40960
#define AVH 65536
#define AVL 90112
#define AKSQF 28672
#define AQSQF 28864
#define ASMEM 115712

__global__ __launch_bounds__(512, 2) void attn_kernel(const float* __restrict__ log_sigma) {
    extern __shared__ char sma[];
    float* smf = (float*)sma;
    const unsigned sb = s2u(sma);

    const int q0 = blockIdx.x * AQT;
    const int h = blockIdx.y;
    const int b = blockIdx.z;
    const int tid = threadIdx.x;
    const int w = tid >> 5, l = tid & 31;

    const float* Qg = g_q + ((size_t)(b * HH + h) * TT) * DD;
    const float* Kg = g_k + ((size_t)(b * HH + h) * TT) * DD;
    const float* Vg = g_v + ((size_t)(b * HH + h) * TT) * DD;
    const float scale = -0.5f * expf(-2.f * log_sigma[h]);
    const float4 z4 = make_float4(0.f, 0.f, 0.f, 0.f);

    for (int i = tid; i < 1536; i += 512) {
        int row = i >> 3, cc = i & 7;
        int gk = q0 - 128 + row;
        float4 f0 = z4, f1 = z4;
        if (gk >= 0) {
            f0 = *(const float4*)&Kg[(size_t)gk * DD + cc * 8];
            f1 = *(const float4*)&Kg[(size_t)gk * DD + cc * 8 + 4];
        }
        float p = f0.x * f0.x + f0.y * f0.y + f0.z * f0.z + f0.w * f0.w +
                  f1.x * f1.x + f1.y * f1.y + f1.z * f1.z + f1.w * f1.w;
        p += __shfl_xor_sync(0xffffffffu, p, 1);
        p += __shfl_xor_sync(0xffffffffu, p, 2);
        p += __shfl_xor_sync(0xffffffffu, p, 4);
        if (cc == 0) smf[AKSQF + row] = p;
        uint4 hh, ll;
        split2(f0.x, f0.y, hh.x, ll.x);
        split2(f0.z, f0.w, hh.y, ll.y);
        split2(f1.x, f1.y, hh.z, ll.z);
        split2(f1.z, f1.w, hh.w, ll.w);
        int off = row * 128 + ((cc ^ (row & 7)) << 4);
        *(uint4*)(sma + AKH + off) = hh;
        *(uint4*)(sma + AKL + off) = ll;
    }
    for (int i = tid; i < 1536; i += 512) {
        int row = i >> 3, cc = i & 7;
        int gk = q0 - 128 + row;
        float4 f0 = z4, f1 = z4;
        if (gk >= 0) {
            f0 = *(const float4*)&Vg[(size_t)gk * DD + cc * 8];
            f1 = *(const float4*)&Vg[(size_t)gk * DD + cc * 8 + 4];
        }
        uint4 hh, ll;
        split2(f0.x, f0.y, hh.x, ll.x);
        split2(f0.z, f0.w, hh.y, ll.y);
        split2(f1.x, f1.y, hh.z, ll.z);
        split2(f1.z, f1.w, hh.w, ll.w);
        int off = row * 128 + ((cc ^ (row & 7)) << 4);
        *(uint4*)(sma + AVH + off) = hh;
        *(uint4*)(sma + AVL + off) = ll;
    }
    {
        int row = tid >> 3, cc = tid & 7;
        float4 f0 = *(const float4*)&Qg[(size_t)(q0 + row) * DD + cc * 8];
        float4 f1 = *(const float4*)&Qg[(size_t)(q0 + row) * DD + cc * 8 + 4];
        float p = f0.x * f0.x + f0.y * f0.y + f0.z * f0.z + f0.w * f0.w +
                  f1.x * f1.x + f1.y * f1.y + f1.z * f1.z + f1.w * f1.w;
        p += __shfl_xor_sync(0xffffffffu, p, 1);
        p += __shfl_xor_sync(0xffffffffu, p, 2);
        p += __shfl_xor_sync(0xffffffffu, p, 4);
        if (cc == 0) smf[AQSQF + row] = p;
        uint4 hh, ll;
        split2(f0.x, f0.y, hh.x, ll.x);
        split2(f0.z, f0.w, hh.y, ll.y);
        split2(f1.x, f1.y, hh.z, ll.z);
        split2(f1.z, f1.w, hh.w, ll.w);
        int off = row * 128 + ((cc ^ (row & 7)) << 4);
        *(uint4*)(sma + AQH + off) = hh;
        *(uint4*)(sma + AQL + off) = ll;
    }
    __syncthreads();

    float sc[3][2][4];
    {
        const int a_m = (l & 7) + ((l >> 3) & 1) * 8;
        const int a_kh = l >> 4;
        const int b_nl = (l & 7) + (l >> 4) * 8;
        const int b_kh = (l >> 3) & 1;
#pragma unroll
        for (int i = 0; i < 3; i++) {
            const int u = w + 16 * i;
            const int mt = u / 12, ng = u % 12;
            float c[2][4];
#pragma unroll
            for (int j = 0; j < 2; j++)
#pragma unroll
                for (int r = 0; r < 4; r++) c[j][r] = 0.f;
            const int arow = mt * 16 + a_m;
            const unsigned aH = sb + AQH + (unsigned)arow * 128;
            const int asw = arow & 7;
            const int brow = ng * 16 + b_nl;
            const unsigned bH = sb + AKH + (unsigned)brow * 128;
            const int bsw = brow & 7;
#pragma unroll
            for (int ks = 0; ks < 4; ks++) {
                unsigned ah[4], al[4], bh[4], bl[4];
                unsigned aad = aH + (unsigned)(((2 * ks + a_kh) ^ asw) << 4);
                ldsm4(ah[0], ah[1], ah[2], ah[3], aad);
                ldsm4(al[0], al[1], al[2], al[3], aad + (AQL - AQH));
                unsigned bad = bH + (unsigned)(((2 * ks + b_kh) ^ bsw) << 4);
                ldsm4(bh[0], bh[1], bh[2], bh[3], bad);
                ldsm4(bl[0], bl[1], bl[2], bl[3], bad + (AKL - AKH));
                mma_f16(c[0][0], c[0][1], c[0][2], c[0][3],
                        ah[0], ah[1], ah[2], ah[3], bh[0], bh[1]);
                mma_f16(c[1][0], c[1][1], c[1][2], c[1][3],
                        ah[0], ah[1], ah[2], ah[3], bh[2], bh[3]);
                mma_f16(c[0][0], c[0][1], c[0][2], c[0][3],
                        ah[0], ah[1], ah[2], ah[3], bl[0], bl[1]);
                mma_f16(c[1][0], c[1][1], c[1][2], c[1][3],
                        ah[0], ah[1], ah[2], ah[3], bl[2], bl[3]);
                mma_f16(c[0][0], c[0][1], c[0][2], c[0][3],
                        al[0], al[1], al[2], al[3], bh[0], bh[1]);
                mma_f16(c[1][0], c[1][1], c[1][2], c[1][3],
                        al[0], al[1], al[2], al[3], bh[2], bh[3]);
            }
            const int r1 = mt * 16 + (l >> 2);
            const float qs1 = smf[AQSQF + r1];
            const float qs2 = smf[AQSQF + r1 + 8];
#pragma unroll
            for (int j = 0; j < 2; j++) {
                int cb = ng * 16 + j * 8 + 2 * (l & 3);
                float2 kq = *(const float2*)&smf[AKSQF + cb];
                sc[i][j][0] = (qs1 + kq.x - 2.f * c[j][0]) * scale;
                sc[i][j][1] = (qs1 + kq.y - 2.f * c[j][1]) * scale;
                sc[i][j][2] = (qs2 + kq.x - 2.f * c[j][2]) * scale;
                sc[i][j][3] = (qs2 + kq.y - 2.f * c[j][3]) * scale;
            }
        }
    }
    __syncthreads();

#pragma unroll
    for (int i = 0; i < 3; i++) {
        const int u = w + 16 * i;
        const int mt = u / 12, ng = u % 12;
        const int r1 = mt * 16 + (l >> 2);
#pragma unroll
        for (int j = 0; j < 2; j++) {
            int cb = ng * 16 + j * 8 + 2 * (l & 3);
            *(float2*)&smf[ASSF + r1 * AKR + cb] =
                make_float2(sc[i][j][0], sc[i][j][1]);
            *(float2*)&smf[ASSF + (r1 + 8) * AKR + cb] =
                make_float2(sc[i][j][2], sc[i][j][3]);
        }
    }
    __syncthreads();

    float ev[4][4];
    int slotr[4];
    {
        const int qbase = 4 * w;
        unsigned key[4][4];
#pragma unroll
        for (int q = 0; q < 4; q++) {
            const int qi = qbase + q;
            const int r0 = qi + 1 + l;
            slotr[q] = r0;
#pragma unroll
            for (int t = 0; t < 4; t++) {
                int r = r0 + 32 * t;
                float s = smf[ASSF + qi * AKR + r];
                bool valid = (q0 - 128 + r) >= 0;
                key[q][t] = valid ? f2ord(s) : 0u;
            }
        }
        __syncthreads();

        // exact top-96 thresholds; bit 31 provably 0 (scores <= ~0);
        // early-exit when count==96 (kept set provably identical).
        unsigned thr[4] = {0u, 0u, 0u, 0u};
        unsigned done = 0;
#pragma unroll 1
        for (int bp = 30; bp >= 0; bp--) {
            unsigned pk = 0;
#pragma unroll
            for (int q = 0; q < 4; q++) {
                unsigned cand = thr[q] | (1u << bp);
                unsigned cnt = (key[q][0] >= cand ? 1u : 0u) +
                               (key[q][1] >= cand ? 1u : 0u) +
                               (key[q][2] >= cand ? 1u : 0u) +
                               (key[q][3] >= cand ? 1u : 0u);
                pk += cnt << (8 * q);
            }
            pk = __reduce_add_sync(0xffffffffu, pk);
#pragma unroll
            for (int q = 0; q < 4; q++) {
                if (done & (1u << q)) continue;
                unsigned cnt = (pk >> (8 * q)) & 0xffu;
                if (cnt >= TOPKK) {
                    thr[q] |= (1u << bp);
                    if (cnt == TOPKK) done |= (1u << q);
                }
            }
            if (done == 0xfu) break;
        }
#pragma unroll
        for (int q = 0; q < 4; q++)
            if (q0 + qbase + q < TOPKK) thr[q] = 0u;

        unsigned mx[4] = {0u, 0u, 0u, 0u};
        unsigned km[4][4];
#pragma unroll
        for (int q = 0; q < 4; q++)
#pragma unroll
            for (int t = 0; t < 4; t++) {
                unsigned k = key[q][t];
                unsigned kk = (k != 0u && k >= thr[q]) ? k : 0u;
                km[q][t] = kk;
                mx[q] = max(mx[q], kk);
            }
#pragma unroll
        for (int q = 0; q < 4; q++) mx[q] = __reduce_max_sync(0xffffffffu, mx[q]);

        float esum[4] = {0.f, 0.f, 0.f, 0.f};
#pragma unroll
        for (int q = 0; q < 4; q++) {
            float mv = ord2f(mx[q]);
#pragma unroll
            for (int t = 0; t < 4; t++) {
                float v = (km[q][t] != 0u) ? __expf(ord2f(km[q][t]) - mv) : 0.f;
                ev[q][t] = v;
                esum[q] += v;
            }
        }
#pragma unroll
        for (int o = 16; o > 0; o >>= 1) {
            esum[0] += __shfl_xor_sync(0xffffffffu, esum[0], o);
            esum[1] += __shfl_xor_sync(0xffffffffu, esum[1], o);
            esum[2] += __shfl_xor_sync(0xffffffffu, esum[2], o);
            esum[3] += __shfl_xor_sync(0xffffffffu, esum[3], o);
        }
#pragma unroll
        for (int q = 0; q < 4; q++) {
            float inv = 1.f / esum[q];
#pragma unroll
            for (int t = 0; t < 4; t++) ev[q][t] *= inv;
        }
    }

    {
        int zb = APH + tid * 96;
#pragma unroll
        for (int k = 0; k < 6; k++)
            *(uint4*)(sma + zb + k * 16) = make_uint4(0u, 0u, 0u, 0u);
    }
    __syncthreads();
    {
        const int qbase = 4 * w;
#pragma unroll
        for (int q = 0; q < 4; q++) {
            const int qi = qbase + q;
#pragma unroll
            for (int t = 0; t < 4; t++) {
                int r = slotr[q] + 32 * t;
                float v = ev[q][t];
                __half hv = __float2half_rn(v);
                __half lv = __float2half_rn(v - __half2float(hv));
                int off = r * 128 + (((qi >> 3) ^ (r & 7)) << 4) + (qi & 7) * 2;
                *(__half*)(sma + APH + off) = hv;
                *(__half*)(sma + APL + off) = lv;
            }
        }
    }
    __syncthreads();

#pragma unroll
    for (int i = 0; i < 2; i++) {
        const int u = w + 16 * i;
        const int mt = u >> 3;
        const int n8 = u & 7;
        float c0 = 0.f, c1 = 0.f, c2 = 0.f, c3 = 0.f;
        const int prow_in = (l & 7) + ((l >> 4) << 3);
        const int pchunk = 2 * mt + ((l >> 3) & 1);
        const int vlane = l & 15;
#pragma unroll
        for (int ks = 0; ks < 12; ks++) {
            unsigned ph[4], pl[4], vh0, vh1, vl0, vl1;
            int prow = ks * 16 + prow_in;
            unsigned pad = sb + APH + (unsigned)prow * 128 +
                           (unsigned)((pchunk ^ (prow & 7)) << 4);
            ldsm4t(ph[0], ph[1], ph[2], ph[3], pad);
            ldsm4t(pl[0], pl[1], pl[2], pl[3], pad + (APL - APH));
            int vrow = ks * 16 + vlane;
            unsigned vad = sb + AVH + (unsigned)vrow * 128 +
                           (unsigned)((n8 ^ (vrow & 7)) << 4);
            ldsm2t(vh0, vh1, vad);
            ldsm2t(vl0, vl1, vad + (AVL - AVH));
            mma_f16(c0, c1, c2, c3, ph[0], ph[1], ph[2], ph[3], vh0, vh1);
            mma_f16(c0, c1, c2, c3, pl[0], pl[1], pl[2], pl[3], vh0, vh1);
            mma_f16(c0, c1, c2, c3, ph[0], ph[1], ph[2], ph[3], vl0, vl1);
        }
        const int gq = q0 + mt * 16 + (l >> 2);
        const int colb = h * DD + n8 * 8 + 2 * (l & 3);
        unsigned h01, l01, h23, l23;
        split2(c0, c1, h01, l01);
        split2(c2, c3, h23, l23);
        size_t o1 = ((size_t)b * TT + gq) * EE + colb;
        size_t o2 = ((size_t)b * TT + gq + 8) * EE + colb;
        *(unsigned*)&g_ah[o1] = h01;
        *(unsigned*)&g_al[o1] = l01;
        *(unsigned*)&g_ah[o2] = h23;
        *(unsigned*)&g_al[o2] = l23;
    }
}

// ---------------------------------------------------------------------------
extern "C" void kernel_launch(void* const* d_in, const int* in_sizes, int n_in,
                              void* d_out, int out_size) {
    const float* x  = (const float*)d_in[0];
    const float* Wq = (const float*)d_in[1];
    const float* bq = (const float*)d_in[2];
    const float* Wk = (const float*)d_in[3];
    const float* bk = (const float*)d_in[4];
    const float* Wv = (const float*)d_in[5];
    const float* bv = (const float*)d_in[6];
    const float* Wo = (const float*)d_in[7];
    const float* bo = (const float*)d_in[8];
    const float* ls = (const float*)d_in[9];

    float *qp, *kp, *vp;
    __half *xh, *xl, *wh, *wl, *ah, *al;
    cudaGetSymbolAddress((void**)&qp, g_q);
    cudaGetSymbolAddress((void**)&kp, g_k);
    cudaGetSymbolAddress((void**)&vp, g_v);
    cudaGetSymbolAddress((void**)&xh, g_xh);
    cudaGetSymbolAddress((void**)&xl, g_xl);
    cudaGetSymbolAddress((void**)&wh, g_wh);
    cudaGetSymbolAddress((void**)&wl, g_wl);
    cudaGetSymbolAddress((void**)&ah, g_ah);
    cudaGetSymbolAddress((void**)&al, g_al);

    const int NX = BB * TT * EE;
    const int NW = EE * EE;
    convk<<<NX / 4 / 256, 256>>>(x, xh, xl, NX);
    convw4<<<dim3(NW / 4 / 256, 4), 256>>>(Wq, Wk, Wv, Wo, wh, wl, NW);

    cudaFuncSetAttribute(gemmk<3>, cudaFuncAttributeMaxDynamicSharedMemorySize, SMEM_GEMM);
    cudaFuncSetAttribute(gemmk<1>, cudaFuncAttributeMaxDynamicSharedMemorySize, SMEM_GEMM);

    dim3 gqkv(BB * TT / GBM, EE / GBN, 3);  // 128 x 4 x 3
    gemmk<3><<<gqkv, 256, SMEM_GEMM>>>(xh, xl, wh, wl, bq, qp, bk, kp, bv, vp);

    cudaFuncSetAttribute(attn_kernel, cudaFuncAttributeMaxDynamicSharedMemorySize,
                         ASMEM);
    attn_kernel<<<dim3(TT / AQT, HH, BB), 512, ASMEM>>>(ls);

    dim3 go(BB * TT / GBM, EE / GBN);  // 128 x 4
    gemmk<1><<<go, 256, SMEM_GEMM>>>(ah, al, wh + (size_t)3 * NW, wl + (size_t)3 * NW,
                                     bo, (float*)d_out, nullptr, nullptr,
                                     nullptr, nullptr);
}

// round 17
// speedup vs baseline: 3.2777x; 1.0203x over previous
#include <cuda_runtime.h>
#include <cuda_fp16.h>
#include <math.h>

#define BB 4
#define HH 8
#define TT 2048
#define DD 64
#define EE 512
#define TOPKK 96

typedef unsigned long long ull;

// Scratch (device globals; no allocation allowed)
__device__ __half g_qh[(size_t)BB * HH * TT * DD];
__device__ __half g_ql[(size_t)BB * HH * TT * DD];
__device__ __half g_kh[(size_t)BB * HH * TT * DD];
__device__ __half g_kl[(size_t)BB * HH * TT * DD];
__device__ __half g_vh[(size_t)BB * HH * TT * DD];
__device__ __half g_vl[(size_t)BB * HH * TT * DD];
__device__ float g_nq[(size_t)BB * HH * TT];
__device__ float g_nk[(size_t)BB * HH * TT];
__device__ __half g_xh[(size_t)BB * TT * EE];
__device__ __half g_xl[(size_t)BB * TT * EE];
__device__ __half g_wh[(size_t)4 * EE * EE];
__device__ __half g_wl[(size_t)4 * EE * EE];
__device__ __half g_ah[(size_t)BB * TT * EE];
__device__ __half g_al[(size_t)BB * TT * EE];

__device__ __forceinline__ unsigned f2ord(float f) {
    unsigned u = __float_as_uint(f);
    return (u & 0x80000000u) ? ~u : (u | 0x80000000u);
}
__device__ __forceinline__ float ord2f(unsigned k) {
    unsigned u = (k & 0x80000000u) ? (k & 0x7fffffffu) : ~k;
    return __uint_as_float(u);
}
__device__ __forceinline__ unsigned s2u(const void* p) {
    return (unsigned)__cvta_generic_to_shared(p);
}
__device__ __forceinline__ void ldsm4(unsigned& r0, unsigned& r1, unsigned& r2,
                                      unsigned& r3, unsigned addr) {
    asm volatile("ldmatrix.sync.aligned.m8n8.x4.shared.b16 {%0,%1,%2,%3}, [%4];"
                 : "=r"(r0), "=r"(r1), "=r"(r2), "=r"(r3) : "r"(addr));
}
__device__ __forceinline__ void ldsm4t(unsigned& r0, unsigned& r1, unsigned& r2,
                                       unsigned& r3, unsigned addr) {
    asm volatile("ldmatrix.sync.aligned.m8n8.x4.trans.shared.b16 {%0,%1,%2,%3}, [%4];"
                 : "=r"(r0), "=r"(r1), "=r"(r2), "=r"(r3) : "r"(addr));
}
__device__ __forceinline__ void ldsm2t(unsigned& r0, unsigned& r1, unsigned addr) {
    asm volatile("ldmatrix.sync.aligned.m8n8.x2.trans.shared.b16 {%0,%1}, [%2];"
                 : "=r"(r0), "=r"(r1) : "r"(addr));
}
__device__ __forceinline__ void mma_f16(float& c0, float& c1, float& c2, float& c3,
                                        unsigned a0, unsigned a1, unsigned a2,
                                        unsigned a3, unsigned b0, unsigned b1) {
    asm volatile(
        "mma.sync.aligned.m16n8k16.row.col.f32.f16.f16.f32 "
        "{%0,%1,%2,%3}, {%4,%5,%6,%7}, {%8,%9}, {%0,%1,%2,%3};"
        : "+f"(c0), "+f"(c1), "+f"(c2), "+f"(c3)
        : "r"(a0), "r"(a1), "r"(a2), "r"(a3), "r"(b0), "r"(b1));
}
__device__ __forceinline__ void split2(float x, float y, unsigned& h, unsigned& l) {
    __half2 h2 = __float22half2_rn(make_float2(x, y));
    float2 hf = __half22float2(h2);
    __half2 l2 = __float22half2_rn(make_float2(x - hf.x, y - hf.y));
    h = *(unsigned*)&h2;
    l = *(unsigned*)&l2;
}
__device__ __forceinline__ void cp16(unsigned s, const void* g) {
    asm volatile("cp.async.cg.shared.global [%0], [%1], 16;" :: "r"(s), "l"(g));
}
__device__ __forceinline__ void cp16z(unsigned s, const void* g, unsigned sz) {
    asm volatile("cp.async.cg.shared.global [%0], [%1], 16, %2;"
                 :: "r"(s), "l"(g), "r"(sz));
}

// ---------------------------------------------------------------------------
// fp32 -> f16 hi/lo split pre-pass. convk: x. convw4: all 4 weights, 1 launch.
// ---------------------------------------------------------------------------
__global__ __launch_bounds__(256) void convk(const float* __restrict__ src,
                                             __half* __restrict__ dh,
                                             __half* __restrict__ dl, int n) {
    int i = (blockIdx.x * 256 + threadIdx.x) * 4;
    if (i < n) {
        float4 v = *(const float4*)(src + i);
        uint2 hh, ll;
        split2(v.x, v.y, hh.x, ll.x);
        split2(v.z, v.w, hh.y, ll.y);
        *(uint2*)(dh + i) = hh;
        *(uint2*)(dl + i) = ll;
    }
}
__global__ __launch_bounds__(256) void convw4(
    const float* __restrict__ s0, const float* __restrict__ s1,
    const float* __restrict__ s2, const float* __restrict__ s3,
    __half* __restrict__ dh, __half* __restrict__ dl, int n) {
    int z = blockIdx.y;
    const float* s = (z == 0) ? s0 : (z == 1) ? s1 : (z == 2) ? s2 : s3;
    size_t off = (size_t)z * n;
    int i = (blockIdx.x * 256 + threadIdx.x) * 4;
    if (i < n) {
        float4 v = *(const float4*)(s + i);
        uint2 hh, ll;
        split2(v.x, v.y, hh.x, ll.x);
        split2(v.z, v.w, hh.y, ll.y);
        *(uint2*)(dh + off + i) = hh;
        *(uint2*)(dl + off + i) = ll;
    }
}

// ---------------------------------------------------------------------------
// FP16-split GEMM (R16 mainloop). NOUT==3: QKV; writes q/k/v as f16 hi/lo in
// head-split layout AND Q/K row norms (deterministic smem reduction).
// NOUT==1: Wo; fp32 output. Terms: Q/K 3-term, V/Wo 2-term.
// ---------------------------------------------------------------------------
#define GBM 64
#define GBN 128
#define GBK 32
#define AHI_OFF 0
#define ALO_OFF 8192
#define BHI_OFF 16384
#define BLO_OFF 32768
#define SMEM_GEMM 49152
#define ABUFB 4096
#define BBUFB 8192

template <int NOUT>
__global__ __launch_bounds__(256, 3) void gemmk(
    const __half* __restrict__ Ah, const __half* __restrict__ Al,
    const __half* __restrict__ Wh0, const __half* __restrict__ Wl0,
    const float* __restrict__ bias0, const float* __restrict__ bias1,
    const float* __restrict__ bias2,
    __half* __restrict__ Yh0, __half* __restrict__ Yl0,
    __half* __restrict__ Yh1, __half* __restrict__ Yl1,
    __half* __restrict__ Yh2, __half* __restrict__ Yl2,
    float* __restrict__ Yf, float* __restrict__ nq, float* __restrict__ nk) {
    extern __shared__ char smg[];
    const unsigned sbase = s2u(smg);

    const __half* Wh = Wh0;
    const __half* Wl = Wl0;
    const float* bias;
    bool t3;
    if (NOUT == 3) {
        int z = blockIdx.z;
        Wh += (size_t)z * EE * EE;
        Wl += (size_t)z * EE * EE;
        bias = (z == 0) ? bias0 : (z == 1) ? bias1 : bias2;
        t3 = (z != 2);
    } else {
        bias = bias0;
        t3 = false;
    }

    const int m0 = blockIdx.x * GBM;
    const int n0 = blockIdx.y * GBN;
    const int tid = threadIdx.x;
    const int wid = tid >> 5;
    const int lane = tid & 31;
    const int wm = (wid & 1) * 32;
    const int wn = (wid >> 1) * 32;

    const int arow = tid >> 2, ac = tid & 3;
    const int brow = tid >> 1, bc2 = (tid & 1) * 2;
    const __half* aSrcH = Ah + (size_t)(m0 + arow) * EE + ac * 8;
    const __half* aSrcL = Al + (size_t)(m0 + arow) * EE + ac * 8;
    const __half* bSrcH = Wh + (size_t)(n0 + brow) * EE + bc2 * 8;
    const __half* bSrcL = Wl + (size_t)(n0 + brow) * EE + bc2 * 8;
    const unsigned aStO = (unsigned)(arow * 64 + ((ac ^ ((arow >> 1) & 3)) << 4));
    const unsigned bStO0 = (unsigned)(brow * 64 + ((bc2 ^ ((brow >> 1) & 3)) << 4));
    const unsigned bStO1 = (unsigned)(brow * 64 + (((bc2 + 1) ^ ((brow >> 1) & 3)) << 4));

    auto issue = [&](int t, int buf) {
        unsigned ao = (unsigned)buf * ABUFB;
        unsigned bo = (unsigned)buf * BBUFB;
        const int ko = t * GBK;
        cp16(sbase + AHI_OFF + ao + aStO, aSrcH + ko);
        cp16(sbase + ALO_OFF + ao + aStO, aSrcL + ko);
        cp16(sbase + BHI_OFF + bo + bStO0, bSrcH + ko);
        cp16(sbase + BHI_OFF + bo + bStO1, bSrcH + ko + 8);
        cp16(sbase + BLO_OFF + bo + bStO0, bSrcL + ko);
        cp16(sbase + BLO_OFF + bo + bStO1, bSrcL + ko + 8);
        asm volatile("cp.async.commit_group;");
    };

    const int a_m = (lane & 7) + ((lane >> 3) & 1) * 8;
    const int a_kh = lane >> 4;
    const int b_n = (lane & 7) + (lane >> 4) * 8;
    const int b_kh = (lane >> 3) & 1;
    unsigned aRow[2], bRow[2];
    int aSw[2], bSw[2];
#pragma unroll
    for (int mt = 0; mt < 2; mt++) {
        int r = wm + mt * 16 + a_m;
        aRow[mt] = sbase + AHI_OFF + (unsigned)r * 64;
        aSw[mt] = (r >> 1) & 3;
    }
#pragma unroll
    for (int p = 0; p < 2; p++) {
        int r = wn + p * 16 + b_n;
        bRow[p] = sbase + BHI_OFF + (unsigned)r * 64;
        bSw[p] = (r >> 1) & 3;
    }

    float c[2][4][4];
#pragma unroll
    for (int mt = 0; mt < 2; mt++)
#pragma unroll
        for (int nt = 0; nt < 4; nt++)
#pragma unroll
            for (int r = 0; r < 4; r++) c[mt][nt][r] = 0.f;

    issue(0, 0);
    const int NT = EE / GBK;  // 16
    for (int t = 0; t < NT; t++) {
        if (t + 1 < NT) {
            issue(t + 1, (t + 1) & 1);
            asm volatile("cp.async.wait_group 1;");
        } else {
            asm volatile("cp.async.wait_group 0;");
        }
        __syncthreads();
        const unsigned abo = (unsigned)(t & 1) * ABUFB;
        const unsigned bbo = (unsigned)(t & 1) * BBUFB;
#pragma unroll
        for (int ks = 0; ks < 2; ks++) {
            unsigned ah[2][4], al[2][4];
#pragma unroll
            for (int mt = 0; mt < 2; mt++) {
                unsigned ad = aRow[mt] + abo +
                              (unsigned)((((ks << 1) + a_kh) ^ aSw[mt]) << 4);
                ldsm4(ah[mt][0], ah[mt][1], ah[mt][2], ah[mt][3], ad);
                ldsm4(al[mt][0], al[mt][1], al[mt][2], al[mt][3],
                      ad + (ALO_OFF - AHI_OFF));
            }
#pragma unroll
            for (int p = 0; p < 2; p++) {
                unsigned bh0, bh1, bh2, bh3, bl0, bl1, bl2, bl3;
                unsigned bd = bRow[p] + bbo +
                              (unsigned)((((ks << 1) + b_kh) ^ bSw[p]) << 4);
                ldsm4(bh0, bh1, bh2, bh3, bd);
                ldsm4(bl0, bl1, bl2, bl3, bd + (BLO_OFF - BHI_OFF));
#pragma unroll
                for (int mt = 0; mt < 2; mt++) {
                    float* cp0 = c[mt][2 * p];
                    float* cp1 = c[mt][2 * p + 1];
                    mma_f16(cp0[0], cp0[1], cp0[2], cp0[3],
                            ah[mt][0], ah[mt][1], ah[mt][2], ah[mt][3], bh0, bh1);
                    mma_f16(cp1[0], cp1[1], cp1[2], cp1[3],
                            ah[mt][0], ah[mt][1], ah[mt][2], ah[mt][3], bh2, bh3);
                    mma_f16(cp0[0], cp0[1], cp0[2], cp0[3],
                            ah[mt][0], ah[mt][1], ah[mt][2], ah[mt][3], bl0, bl1);
                    mma_f16(cp1[0], cp1[1], cp1[2], cp1[3],
                            ah[mt][0], ah[mt][1], ah[mt][2], ah[mt][3], bl2, bl3);
                }
                if (t3) {
#pragma unroll
                    for (int mt = 0; mt < 2; mt++) {
                        float* cp0 = c[mt][2 * p];
                        float* cp1 = c[mt][2 * p + 1];
                        mma_f16(cp0[0], cp0[1], cp0[2], cp0[3],
                                al[mt][0], al[mt][1], al[mt][2], al[mt][3], bh0, bh1);
                        mma_f16(cp1[0], cp1[1], cp1[2], cp1[3],
                                al[mt][0], al[mt][1], al[mt][2], al[mt][3], bh2, bh3);
                    }
                }
            }
        }
        __syncthreads();
    }

    const int g = lane >> 2;
    const int tc = lane & 3;
    if (NOUT == 3) {
        const int z = blockIdx.z;
        __half* Yh = (z == 0) ? Yh0 : (z == 1) ? Yh1 : Yh2;
        __half* Yl = (z == 0) ? Yl0 : (z == 1) ? Yl1 : Yl2;
        float* nsm = (float*)smg;  // [64 rows][4 wn-slots]
        const int hcol = (n0 + wn) >> 6;
        const int wslot = wn >> 5;
        float np[2][2];
#pragma unroll
        for (int mt = 0; mt < 2; mt++) {
            int row = m0 + wm + mt * 16 + g;
            int bi = row >> 11, tt0 = row & 2047;
            size_t rbase = ((size_t)bi * HH + hcol) * TT + tt0;
            __half* dh = Yh + rbase * DD;
            __half* dl = Yl + rbase * DD;
            float n1 = 0.f, n2 = 0.f;
#pragma unroll
            for (int nt = 0; nt < 4; nt++) {
                int col = n0 + wn + nt * 8 + tc * 2;
                int d = col & 63;
                float2 bbv = *(const float2*)&bias[col];
                float2 v0 = make_float2(c[mt][nt][0] + bbv.x, c[mt][nt][1] + bbv.y);
                float2 v1 = make_float2(c[mt][nt][2] + bbv.x, c[mt][nt][3] + bbv.y);
                unsigned h0, l0, h1, l1;
                split2(v0.x, v0.y, h0, l0);
                split2(v1.x, v1.y, h1, l1);
                *(unsigned*)&dh[d] = h0;
                *(unsigned*)&dl[d] = l0;
                *(unsigned*)&dh[8 * DD + d] = h1;
                *(unsigned*)&dl[8 * DD + d] = l1;
                n1 += v0.x * v0.x + v0.y * v0.y;
                n2 += v1.x * v1.x + v1.y * v1.y;
            }
            np[mt][0] = n1;
            np[mt][1] = n2;
        }
        if (z < 2) {
            // reduce over tc (lanes g*4+tc consecutive) then stash per wn-slot
#pragma unroll
            for (int mt = 0; mt < 2; mt++)
#pragma unroll
                for (int v = 0; v < 2; v++) {
                    float s = np[mt][v];
                    s += __shfl_xor_sync(0xffffffffu, s, 1);
                    s += __shfl_xor_sync(0xffffffffu, s, 2);
                    np[mt][v] = s;
                }
            if (tc == 0) {
#pragma unroll
                for (int mt = 0; mt < 2; mt++) {
#pragma unroll
                    for (int v = 0; v < 2; v++) {
                        int rl = wm + mt * 16 + g + v * 8;
                        nsm[rl * 4 + wslot] = np[mt][v];
                    }
                }
            }
            __syncthreads();
            if (tid < 128) {
                int rl = tid >> 1, hd = tid & 1;
                float val = nsm[rl * 4 + hd * 2] + nsm[rl * 4 + hd * 2 + 1];
                int row = m0 + rl;
                int bi = row >> 11, tt0 = row & 2047;
                int hh = (n0 >> 6) + hd;
                float* nbuf = (z == 0) ? nq : nk;
                nbuf[((size_t)bi * HH + hh) * TT + tt0] = val;
            }
        }
    } else {
#pragma unroll
        for (int mt = 0; mt < 2; mt++)
#pragma unroll
            for (int nt = 0; nt < 4; nt++) {
                int col = n0 + wn + nt * 8 + tc * 2;
                float2 bbv = *(const float2*)&bias[col];
                float2 v0 = make_float2(c[mt][nt][0] + bbv.x, c[mt][nt][1] + bbv.y);
                float2 v1 = make_float2(c[mt][nt][2] + bbv.x, c[mt][nt][3] + bbv.y);
                int row = m0 + wm + mt * 16 + g;
                *(float2*)&Yf[(size_t)row * EE + col] = v0;
                *(float2*)&Yf[(size_t)(row + 8) * EE + col] = v1;
            }
    }
}

// ---------------------------------------------------------------------------
// Attention v5 — pre-split f16 q/k/v + precomputed norms: load phase is pure
// cp.async (zfill for out-of-window rows). Rest identical to R16.
// ---------------------------------------------------------------------------
#define AQT 64
#define AKR 192
#define AQH 0
#define AQL 8192
#define AKH 16384
#define AKL 40960
#define ASSF 4096
#define APH 16384
#define APL 40960
#define AVH 65536
#define AVL 90112
#define AKSQF 28672
#define AQSQF 28864
#define ASMEM 115712

__global__ __launch_bounds__(512, 2) void attn_kernel(const float* __restrict__ log_sigma) {
    extern __shared__ char sma[];
    float* smf = (float*)sma;
    const unsigned sb = s2u(sma);

    const int q0 = blockIdx.x * AQT;
    const int h = blockIdx.y;
    const int b = blockIdx.z;
    const int tid = threadIdx.x;
    const int w = tid >> 5, l = tid & 31;

    const size_t nbase = (size_t)(b * HH + h) * TT;
    const __half* Qh = g_qh + nbase * DD;
    const __half* Ql = g_ql + nbase * DD;
    const __half* Kh = g_kh + nbase * DD;
    const __half* Kl = g_kl + nbase * DD;
    const __half* Vh = g_vh + nbase * DD;
    const __half* Vl = g_vl + nbase * DD;
    const float scale = -0.5f * expf(-2.f * log_sigma[h]);

    // ---- K/V/Q loads: pure cp.async into swizzled smem ----
    for (int i = tid; i < 1536; i += 512) {
        int row = i >> 3, cc = i & 7;
        int gk = q0 - 128 + row;
        unsigned sz = (gk >= 0) ? 16u : 0u;
        size_t goff = (size_t)(gk < 0 ? 0 : gk) * DD + cc * 8;
        int off = row * 128 + ((cc ^ (row & 7)) << 4);
        cp16z(sb + AKH + off, Kh + goff, sz);
        cp16z(sb + AKL + off, Kl + goff, sz);
        cp16z(sb + AVH + off, Vh + goff, sz);
        cp16z(sb + AVL + off, Vl + goff, sz);
    }
    {
        int row = tid >> 3, cc = tid & 7;
        size_t goff = (size_t)(q0 + row) * DD + cc * 8;
        int off = row * 128 + ((cc ^ (row & 7)) << 4);
        cp16(sb + AQH + off, Qh + goff);
        cp16(sb + AQL + off, Ql + goff);
    }
    // ---- norms from gmem ----
    if (tid < AKR) {
        int gk = q0 - 128 + tid;
        smf[AKSQF + tid] = (gk >= 0) ? g_nk[nbase + gk] : 0.f;
    } else if (tid < AKR + 64) {
        smf[AQSQF + tid - AKR] = g_nq[nbase + q0 + tid - AKR];
    }
    asm volatile("cp.async.wait_all;" ::: "memory");
    __syncthreads();

    float sc[3][2][4];
    {
        const int a_m = (l & 7) + ((l >> 3) & 1) * 8;
        const int a_kh = l >> 4;
        const int b_nl = (l & 7) + (l >> 4) * 8;
        const int b_kh = (l >> 3) & 1;
#pragma unroll
        for (int i = 0; i < 3; i++) {
            const int u = w + 16 * i;
            const int mt = u / 12, ng = u % 12;
            float c[2][4];
#pragma unroll
            for (int j = 0; j < 2; j++)
#pragma unroll
                for (int r = 0; r < 4; r++) c[j][r] = 0.f;
            const int arow = mt * 16 + a_m;
            const unsigned aH = sb + AQH + (unsigned)arow * 128;
            const int asw = arow & 7;
            const int brow = ng * 16 + b_nl;
            const unsigned bH = sb + AKH + (unsigned)brow * 128;
            const int bsw = brow & 7;
#pragma unroll
            for (int ks = 0; ks < 4; ks++) {
                unsigned ah[4], al[4], bh[4], bl[4];
                unsigned aad = aH + (unsigned)(((2 * ks + a_kh) ^ asw) << 4);
                ldsm4(ah[0], ah[1], ah[2], ah[3], aad);
                ldsm4(al[0], al[1], al[2], al[3], aad + (AQL - AQH));
                unsigned bad = bH + (unsigned)(((2 * ks + b_kh) ^ bsw) << 4);
                ldsm4(bh[0], bh[1], bh[2], bh[3], bad);
                ldsm4(bl[0], bl[1], bl[2], bl[3], bad + (AKL - AKH));
                mma_f16(c[0][0], c[0][1], c[0][2], c[0][3],
                        ah[0], ah[1], ah[2], ah[3], bh[0], bh[1]);
                mma_f16(c[1][0], c[1][1], c[1][2], c[1][3],
                        ah[0], ah[1], ah[2], ah[3], bh[2], bh[3]);
                mma_f16(c[0][0], c[0][1], c[0][2], c[0][3],
                        ah[0], ah[1], ah[2], ah[3], bl[0], bl[1]);
                mma_f16(c[1][0], c[1][1], c[1][2], c[1][3],
                        ah[0], ah[1], ah[2], ah[3], bl[2], bl[3]);
                mma_f16(c[0][0], c[0][1], c[0][2], c[0][3],
                        al[0], al[1], al[2], al[3], bh[0], bh[1]);
                mma_f16(c[1][0], c[1][1], c[1][2], c[1][3],
                        al[0], al[1], al[2], al[3], bh[2], bh[3]);
            }
            const int r1 = mt * 16 + (l >> 2);
            const float qs1 = smf[AQSQF + r1];
            const float qs2 = smf[AQSQF + r1 + 8];
#pragma unroll
            for (int j = 0; j < 2; j++) {
                int cb = ng * 16 + j * 8 + 2 * (l & 3);
                float2 kq = *(const float2*)&smf[AKSQF + cb];
                sc[i][j][0] = (qs1 + kq.x - 2.f * c[j][0]) * scale;
                sc[i][j][1] = (qs1 + kq.y - 2.f * c[j][1]) * scale;
                sc[i][j][2] = (qs2 + kq.x - 2.f * c[j][2]) * scale;
                sc[i][j][3] = (qs2 + kq.y - 2.f * c[j][3]) * scale;
            }
        }
    }
    __syncthreads();

#pragma unroll
    for (int i = 0; i < 3; i++) {
        const int u = w + 16 * i;
        const int mt = u / 12, ng = u % 12;
        const int r1 = mt * 16 + (l >> 2);
#pragma unroll
        for (int j = 0; j < 2; j++) {
            int cb = ng * 16 + j * 8 + 2 * (l & 3);
            *(float2*)&smf[ASSF + r1 * AKR + cb] =
                make_float2(sc[i][j][0], sc[i][j][1]);
            *(float2*)&smf[ASSF + (r1 + 8) * AKR + cb] =
                make_float2(sc[i][j][2], sc[i][j][3]);
        }
    }
    __syncthreads();

    float ev[4][4];
    int slotr[4];
    {
        const int qbase = 4 * w;
        unsigned key[4][4];
#pragma unroll
        for (int q = 0; q < 4; q++) {
            const int qi = qbase + q;
            const int r0 = qi + 1 + l;
            slotr[q] = r0;
#pragma unroll
            for (int t = 0; t < 4; t++) {
                int r = r0 + 32 * t;
                float s = smf[ASSF + qi * AKR + r];
                bool valid = (q0 - 128 + r) >= 0;
                key[q][t] = valid ? f2ord(s) : 0u;
            }
        }
        __syncthreads();

        unsigned thr[4] = {0u, 0u, 0u, 0u};
        unsigned done = 0;
#pragma unroll 1
        for (int bp = 30; bp >= 0; bp--) {
            unsigned pk = 0;
#pragma unroll
            for (int q = 0; q < 4; q++) {
                unsigned cand = thr[q] | (1u << bp);
                unsigned cnt = (key[q][0] >= cand ? 1u : 0u) +
                               (key[q][1] >= cand ? 1u : 0u) +
                               (key[q][2] >= cand ? 1u : 0u) +
                               (key[q][3] >= cand ? 1u : 0u);
                pk += cnt << (8 * q);
            }
            pk = __reduce_add_sync(0xffffffffu, pk);
#pragma unroll
            for (int q = 0; q < 4; q++) {
                if (done & (1u << q)) continue;
                unsigned cnt = (pk >> (8 * q)) & 0xffu;
                if (cnt >= TOPKK) {
                    thr[q] |= (1u << bp);
                    if (cnt == TOPKK) done |= (1u << q);
                }
            }
            if (done == 0xfu) break;
        }
#pragma unroll
        for (int q = 0; q < 4; q++)
            if (q0 + qbase + q < TOPKK) thr[q] = 0u;

        unsigned mx[4] = {0u, 0u, 0u, 0u};
        unsigned km[4][4];
#pragma unroll
        for (int q = 0; q < 4; q++)
#pragma unroll
            for (int t = 0; t < 4; t++) {
                unsigned k = key[q][t];
                unsigned kk = (k != 0u && k >= thr[q]) ? k : 0u;
                km[q][t] = kk;
                mx[q] = max(mx[q], kk);
            }
#pragma unroll
        for (int q = 0; q < 4; q++) mx[q] = __reduce_max_sync(0xffffffffu, mx[q]);

        float esum[4] = {0.f, 0.f, 0.f, 0.f};
#pragma unroll
        for (int q = 0; q < 4; q++) {
            float mv = ord2f(mx[q]);
#pragma unroll
            for (int t = 0; t < 4; t++) {
                float v = (km[q][t] != 0u) ? __expf(ord2f(km[q][t]) - mv) : 0.f;
                ev[q][t] = v;
                esum[q] += v;
            }
        }
#pragma unroll
        for (int o = 16; o > 0; o >>= 1) {
            esum[0] += __shfl_xor_sync(0xffffffffu, esum[0], o);
            esum[1] += __shfl_xor_sync(0xffffffffu, esum[1], o);
            esum[2] += __shfl_xor_sync(0xffffffffu, esum[2], o);
            esum[3] += __shfl_xor_sync(0xffffffffu, esum[3], o);
        }
#pragma unroll
        for (int q = 0; q < 4; q++) {
            float inv = 1.f / esum[q];
#pragma unroll
            for (int t = 0; t < 4; t++) ev[q][t] *= inv;
        }
    }

    {
        int zb = APH + tid * 96;
#pragma unroll
        for (int k = 0; k < 6; k++)
            *(uint4*)(sma + zb + k * 16) = make_uint4(0u, 0u, 0u, 0u);
    }
    __syncthreads();
    {
        const int qbase = 4 * w;
#pragma unroll
        for (int q = 0; q < 4; q++) {
            const int qi = qbase + q;
#pragma unroll
            for (int t = 0; t < 4; t++) {
                int r = slotr[q] + 32 * t;
                float v = ev[q][t];
                __half hv = __float2half_rn(v);
                __half lv = __float2half_rn(v - __half2float(hv));
                int off = r * 128 + (((qi >> 3) ^ (r & 7)) << 4) + (qi & 7) * 2;
                *(__half*)(sma + APH + off) = hv;
                *(__half*)(sma + APL + off) = lv;
            }
        }
    }
    __syncthreads();

#pragma unroll
    for (int i = 0; i < 2; i++) {
        const int u = w + 16 * i;
        const int mt = u >> 3;
        const int n8 = u & 7;
        float c0 = 0.f, c1 = 0.f, c2 = 0.f, c3 = 0.f;
        const int prow_in = (l & 7) + ((l >> 4) << 3);
        const int pchunk = 2 * mt + ((l >> 3) & 1);
        const int vlane = l & 15;
#pragma unroll
        for (int ks = 0; ks < 12; ks++) {
            unsigned ph[4], pl[4], vh0, vh1, vl0, vl1;
            int prow = ks * 16 + prow_in;
            unsigned pad = sb + APH + (unsigned)prow * 128 +
                           (unsigned)((pchunk ^ (prow & 7)) << 4);
            ldsm4t(ph[0], ph[1], ph[2], ph[3], pad);
            ldsm4t(pl[0], pl[1], pl[2], pl[3], pad + (APL - APH));
            int vrow = ks * 16 + vlane;
            unsigned vad = sb + AVH + (unsigned)vrow * 128 +
                           (unsigned)((n8 ^ (vrow & 7)) << 4);
            ldsm2t(vh0, vh1, vad);
            ldsm2t(vl0, vl1, vad + (AVL - AVH));
            mma_f16(c0, c1, c2, c3, ph[0], ph[1], ph[2], ph[3], vh0, vh1);
            mma_f16(c0, c1, c2, c3, pl[0], pl[1], pl[2], pl[3], vh0, vh1);
            mma_f16(c0, c1, c2, c3, ph[0], ph[1], ph[2], ph[3], vl0, vl1);
        }
        const int gq = q0 + mt * 16 + (l >> 2);
        const int colb = h * DD + n8 * 8 + 2 * (l & 3);
        unsigned h01, l01, h23, l23;
        split2(c0, c1, h01, l01);
        split2(c2, c3, h23, l23);
        size_t o1 = ((size_t)b * TT + gq) * EE + colb;
        size_t o2 = ((size_t)b * TT + gq + 8) * EE + colb;
        *(unsigned*)&g_ah[o1] = h01;
        *(unsigned*)&g_al[o1] = l01;
        *(unsigned*)&g_ah[o2] = h23;
        *(unsigned*)&g_al[o2] = l23;
    }
}

// ---------------------------------------------------------------------------
extern "C" void kernel_launch(void* const* d_in, const int* in_sizes, int n_in,
                              void* d_out, int out_size) {
    const float* x  = (const float*)d_in[0];
    const float* Wq = (const float*)d_in[1];
    const float* bq = (const float*)d_in[2];
    const float* Wk = (const float*)d_in[3];
    const float* bk = (const float*)d_in[4];
    const float* Wv = (const float*)d_in[5];
    const float* bv = (const float*)d_in[6];
    const float* Wo = (const float*)d_in[7];
    const float* bo = (const float*)d_in[8];
    const float* ls = (const float*)d_in[9];

    __half *xh, *xl, *wh, *wl, *ah, *al;
    __half *qh, *ql, *kh, *kl, *vh, *vl;
    float *nq, *nk;
    cudaGetSymbolAddress((void**)&xh, g_xh);
    cudaGetSymbolAddress((void**)&xl, g_xl);
    cudaGetSymbolAddress((void**)&wh, g_wh);
    cudaGetSymbolAddress((void**)&wl, g_wl);
    cudaGetSymbolAddress((void**)&ah, g_ah);
    cudaGetSymbolAddress((void**)&al, g_al);
    cudaGetSymbolAddress((void**)&qh, g_qh);
    cudaGetSymbolAddress((void**)&ql, g_ql);
    cudaGetSymbolAddress((void**)&kh, g_kh);
    cudaGetSymbolAddress((void**)&kl, g_kl);
    cudaGetSymbolAddress((void**)&vh, g_vh);
    cudaGetSymbolAddress((void**)&vl, g_vl);
    cudaGetSymbolAddress((void**)&nq, g_nq);
    cudaGetSymbolAddress((void**)&nk, g_nk);

    const int NX = BB * TT * EE;
    const int NW = EE * EE;
    convk<<<NX / 4 / 256, 256>>>(x, xh, xl, NX);
    convw4<<<dim3(NW / 4 / 256, 4), 256>>>(Wq, Wk, Wv, Wo, wh, wl, NW);

    cudaFuncSetAttribute(gemmk<3>, cudaFuncAttributeMaxDynamicSharedMemorySize, SMEM_GEMM);
    cudaFuncSetAttribute(gemmk<1>, cudaFuncAttributeMaxDynamicSharedMemorySize, SMEM_GEMM);

    dim3 gqkv(BB * TT / GBM, EE / GBN, 3);  // 128 x 4 x 3
    gemmk<3><<<gqkv, 256, SMEM_GEMM>>>(xh, xl, wh, wl, bq, bk, bv,
                                       qh, ql, kh, kl, vh, vl,
                                       nullptr, nq, nk);

    cudaFuncSetAttribute(attn_kernel, cudaFuncAttributeMaxDynamicSharedMemorySize,
                         ASMEM);
    attn_kernel<<<dim3(TT / AQT, HH, BB), 512, ASMEM>>>(ls);

    dim3 go(BB * TT / GBM, EE / GBN);  // 128 x 4
    gemmk<1><<<go, 256, SMEM_GEMM>>>(ah, al, wh + (size_t)3 * NW, wl + (size_t)3 * NW,
                                     bo, nullptr, nullptr,
                                     nullptr, nullptr, nullptr, nullptr, nullptr,
                                     nullptr, (float*)d_out, nullptr, nullptr);
}